// round 9
// baseline (speedup 1.0000x reference)
#include <cuda_runtime.h>
#include <cstdint>
#include <math.h>

// B=4, C=256, Fq=64, T=256, HEADS=8, Dh=32, GROUPS=32, WIN=16
#define NTOK   65536
#define ELEMS  16777216

// ---------------- scratch ----------------
__device__ float g_x[ELEMS];
__device__ float g_h[ELEMS];
__device__ float g_h2[ELEMS];       // tf32 shadow of g_x
__device__ float g_y[ELEMS];
__device__ float g_qkv[3*ELEMS];
__device__ float g_a3[65536];
__device__ float g_a3b[65536];
__device__ float g_wt[589824];      // conv weights, packed
__device__ float g_wq2[196608];
__device__ float g_wo2[65536];
__device__ float g_wq3[196608];
__device__ float g_wo3[65536];
__device__ float g_wq4[196608];
__device__ float g_wo4[65536];

// ---------------- tf32 helpers ----------------
__device__ __forceinline__ uint32_t f2tf(float x) {
    uint32_t r; asm("cvt.rna.tf32.f32 %0, %1;" : "=r"(r) : "f"(x)); return r;
}
__device__ __forceinline__ float tf32r(float x) { return __uint_as_float(f2tf(x)); }
__device__ __forceinline__ void mma8(float* d, const uint32_t* a, const uint32_t* b) {
    asm volatile("mma.sync.aligned.m16n8k8.row.col.f32.tf32.tf32.f32 "
        "{%0,%1,%2,%3}, {%4,%5,%6,%7}, {%8,%9}, {%0,%1,%2,%3};"
        : "+f"(d[0]), "+f"(d[1]), "+f"(d[2]), "+f"(d[3])
        : "r"(a[0]), "r"(a[1]), "r"(a[2]), "r"(a[3]), "r"(b[0]), "r"(b[1]));
}
__device__ __forceinline__ void cpa16(uint32_t dst, const void* src, int sz) {
    asm volatile("cp.async.cg.shared.global [%0], [%1], 16, %2;" :: "r"(dst), "l"(src), "r"(sz));
}
__device__ __forceinline__ void cpa_commit() { asm volatile("cp.async.commit_group;"); }
__device__ __forceinline__ void cpa_wait0()  { asm volatile("cp.async.wait_group 0;"); }

// packed-pos -> local k within a 32-k tile: pos = 8*ks + 2*tig + b -> k = 8*ks + tig + 4*b
__device__ __forceinline__ int kOfPos(int pos) {
    int ks = pos >> 3, rem = pos & 7;
    return ks*8 + (rem >> 1) + 4*(rem & 1);
}

// smem layout (words): stage = [A0 8192][A1 8192][B0 4096][B1 4096] = 24576 w
#define A_SUB   8192
#define B_OFF0  16384
#define B_SUB   4096
#define STAGE_W 24576
#define SMEM_MM (2*STAGE_W*4)   // 196608 B

// ============ mma.sync tf32 GEMM/conv: CTA tile 256x128, 8 warps (64x64), K/barrier=64 ====
// MODE: 0 gemm, 1 gemm+bias, 2 conv, 3 conv+bias+temb+silu
// A: [M][K] tf32-valued fp32 (or conv NHWC gather); Bp prepacked P[(kt*N+n)*32+pos].
template<int MODE>
__global__ __launch_bounds__(256) void k_mm(
    const float* __restrict__ A, const float* __restrict__ Bp,
    const float* __restrict__ bias, const float* __restrict__ temb,
    const float* __restrict__ gate, float* __restrict__ Out,
    int K, int NS) {
    extern __shared__ uint32_t sm[];
    uint32_t sbase = (uint32_t)__cvta_generic_to_shared(sm);
    int tid = threadIdx.x, lane = tid & 31, wid = tid >> 5;
    int g = lane >> 2, tig = lane & 3;
    int wm = wid >> 1, wn = wid & 1;           // 4 (m) x 2 (n) warps
    int bm = blockIdx.y * 256, bn = blockIdx.x * 128;
    float acc[4][8][4] = {};
    int PKT = K >> 6;                           // 64-k stages

    auto copyStage = [&](int p, int buf) {
        #pragma unroll
        for (int sub = 0; sub < 2; sub++) {
            int kt = 2*p + sub;
            uint32_t aBase = sbase + (buf*STAGE_W + sub*A_SUB)*4;
            uint32_t bBase = sbase + (buf*STAGE_W + B_OFF0 + sub*B_SUB)*4;
            if (MODE < 2) {
                #pragma unroll
                for (int i = 0; i < 8; i++) {
                    int idx = tid + i*256, row = idx >> 3, c4 = idx & 7;
                    cpa16(aBase + ((row*32 + ((c4*4) ^ ((row & 7)*4))))*4,
                          A + (size_t)(bm + row)*K + kt*32 + c4*4, 16);
                }
            } else {
                int k0 = kt << 5, kyx = k0 >> 8, ci0 = k0 & 255;
                int ky = kyx/3, kx = kyx - 3*ky;
                #pragma unroll
                for (int i = 0; i < 8; i++) {
                    int idx = tid + i*256, row = idx >> 3, c4 = idx & 7;
                    int pp = bm + row, bb = pp >> 14, fy = (pp >> 8) & 63, fx = pp & 255;
                    int fy2 = fy + ky - 1, fx2 = fx + kx - 1;
                    bool v = ((unsigned)fy2 < 64u) && ((unsigned)fx2 < 256u);
                    cpa16(aBase + ((row*32 + ((c4*4) ^ ((row & 7)*4))))*4,
                          A + (((size_t)(bb*64 + (v?fy2:0)))*256 + (v?fx2:0))*256 + ci0 + c4*4,
                          v ? 16 : 0);
                }
            }
            #pragma unroll
            for (int i = 0; i < 4; i++) {
                int idx = tid + i*256, n = idx >> 3, c4 = idx & 7;
                cpa16(bBase + ((n*32 + ((c4*4) ^ ((n & 3)*8))))*4,
                      Bp + ((size_t)kt*NS + bn + n)*32 + c4*4, 16);
            }
        }
        cpa_commit();
    };

    copyStage(0, 0);
    for (int p = 0; p < PKT; p++) {
        cpa_wait0();
        __syncthreads();
        if (p + 1 < PKT) copyStage(p + 1, (p + 1) & 1);
        const uint32_t* stg = sm + (p & 1)*STAGE_W;
        #pragma unroll
        for (int sub = 0; sub < 2; sub++) {
            const uint32_t* As = stg + sub*A_SUB;
            const uint32_t* Bt = stg + B_OFF0 + sub*B_SUB;
            #pragma unroll
            for (int ks = 0; ks < 4; ks++) {
                int k = ks*8;
                uint32_t af[4][4], bf[8][2];
                #pragma unroll
                for (int mt = 0; mt < 4; mt++) {
                    int r1 = wm*64 + mt*16 + g, r2 = r1 + 8;
                    int sw = (g)*4;
                    af[mt][0] = As[r1*32 + ((k + tig) ^ sw)];
                    af[mt][1] = As[r2*32 + ((k + tig) ^ sw)];
                    af[mt][2] = As[r1*32 + ((k + tig + 4) ^ sw)];
                    af[mt][3] = As[r2*32 + ((k + tig + 4) ^ sw)];
                }
                #pragma unroll
                for (int nt = 0; nt < 8; nt++) {
                    int c0 = wn*64 + nt*8 + g;
                    uint2 bv = *(const uint2*)&Bt[c0*32 + ((k + tig*2) ^ ((c0 & 3)*8))];
                    bf[nt][0] = bv.x; bf[nt][1] = bv.y;
                }
                #pragma unroll
                for (int mt = 0; mt < 4; mt++)
                    #pragma unroll
                    for (int nt = 0; nt < 8; nt++)
                        mma8(acc[mt][nt], af[mt], bf[nt]);
            }
        }
    }
    float gd = (MODE == 3) ? gate[0] : 0.f;
    int bidx = bm >> 14;
    #pragma unroll
    for (int mt = 0; mt < 4; mt++) {
        int row = bm + wm*64 + mt*16 + g;
        #pragma unroll
        for (int nt = 0; nt < 8; nt++) {
            int col = bn + wn*64 + nt*8 + tig*2;
            float v[4] = {acc[mt][nt][0], acc[mt][nt][1], acc[mt][nt][2], acc[mt][nt][3]};
            if (MODE == 1) {
                float b0 = bias[col], b1v = bias[col+1];
                v[0] += b0; v[1] += b1v; v[2] += b0; v[3] += b1v;
            }
            if (MODE == 3) {
                float a0 = bias[col]   + gd * temb[bidx*256 + col];
                float a1 = bias[col+1] + gd * temb[bidx*256 + col + 1];
                v[0] += a0; v[1] += a1; v[2] += a0; v[3] += a1;
                #pragma unroll
                for (int j = 0; j < 4; j++) v[j] = v[j] / (1.f + __expf(-v[j]));
            }
            *(float2*)(Out + (size_t)row*NS + col)       = make_float2(v[0], v[1]);
            *(float2*)(Out + (size_t)(row + 8)*NS + col) = make_float2(v[2], v[3]);
        }
    }
}

// ---------------- weight prepacks (identical math to R7) ----------------
// P[(kt*N + n)*32 + pos] = tf32(W[(kt*32 + kOfPos(pos))*N + n])
__global__ void k_prepb(const float* __restrict__ W, float* __restrict__ P, int K, int N) {
    int idx = blockIdx.x * 256 + threadIdx.x;
    if (idx >= K * N) return;
    int pos = idx & 31;
    int rest = idx >> 5;
    int n = rest % N;
    int kt = rest / N;
    int k = kt*32 + kOfPos(pos);
    P[idx] = tf32r(W[(size_t)k * N + n]);
}
// conv: P[(kt*256 + co)*32 + pos] = tf32(w[co*2304 + ci*9 + kyx]), k = kt*32+kOfPos(pos)
__global__ void k_prepconv(const float* __restrict__ w, float* __restrict__ P) {
    int idx = blockIdx.x * 256 + threadIdx.x;
    int pos = idx & 31;
    int rest = idx >> 5;
    int co = rest & 255;
    int kt = rest >> 8;
    int k = kt*32 + kOfPos(pos);
    int kyx = k >> 8, ci = k & 255;
    P[idx] = tf32r(w[(size_t)co * 2304 + ci * 9 + kyx]);
}

// ---------------- transposes ----------------
__global__ void k_nchw_to_nhwc(const float* __restrict__ in, float* __restrict__ out) {
    __shared__ float tile[32][33];
    int bfq = blockIdx.z, b = bfq >> 6, fq = bfq & 63;
    int t0 = blockIdx.x * 32, c0 = blockIdx.y * 32;
    for (int r = threadIdx.y; r < 32; r += 8)
        tile[r][threadIdx.x] = in[(((size_t)b*256 + c0 + r)*64 + fq)*256 + t0 + threadIdx.x];
    __syncthreads();
    for (int r = threadIdx.y; r < 32; r += 8)
        out[((size_t)bfq*256 + t0 + r)*256 + c0 + threadIdx.x] = tile[threadIdx.x][r];
}

__global__ void k_nhwc_to_nchw_add(const float* __restrict__ xa, const float* __restrict__ xb,
                                   float* __restrict__ out) {
    __shared__ float tile[32][33];
    int bfq = blockIdx.z, b = bfq >> 6, fq = bfq & 63;
    int t0 = blockIdx.x * 32, c0 = blockIdx.y * 32;
    for (int r = threadIdx.y; r < 32; r += 8) {
        size_t p = ((size_t)bfq*256 + t0 + r)*256 + c0 + threadIdx.x;
        tile[r][threadIdx.x] = xa[p] + xb[p];
    }
    __syncthreads();
    for (int r = threadIdx.y; r < 32; r += 8)
        out[(((size_t)b*256 + c0 + r)*64 + fq)*256 + t0 + threadIdx.x] = tile[threadIdx.x][r];
}

// ---------------- GroupNorm per (b, g); ROUND -> tf32-rounded out ----------------
template<bool ROUND>
__global__ void k_gn_bg(const float* __restrict__ in, float* __restrict__ out, float eps) {
    __shared__ float rs[64];
    int b = blockIdx.x >> 5, g = blockIdx.x & 31;
    const float* base = in  + (size_t)b*16384*256 + g*8;
    float*       ob   = out + (size_t)b*16384*256 + g*8;
    float s = 0.f, s2 = 0.f;
    for (int i = threadIdx.x; i < 16384; i += 256) {
        const float4* r = (const float4*)(base + (size_t)i*256);
        float4 a = r[0], c = r[1];
        s  += a.x+a.y+a.z+a.w + c.x+c.y+c.z+c.w;
        s2 += a.x*a.x+a.y*a.y+a.z*a.z+a.w*a.w + c.x*c.x+c.y*c.y+c.z*c.z+c.w*c.w;
    }
    int lane = threadIdx.x & 31, w = threadIdx.x >> 5;
    #pragma unroll
    for (int o = 16; o; o >>= 1) {
        s  += __shfl_down_sync(0xffffffffu, s,  o);
        s2 += __shfl_down_sync(0xffffffffu, s2, o);
    }
    if (lane == 0) { rs[w] = s; rs[32 + w] = s2; }
    __syncthreads();
    if (threadIdx.x == 0) {
        float S = 0.f, S2 = 0.f;
        for (int i = 0; i < 8; i++) { S += rs[i]; S2 += rs[32 + i]; }
        rs[0] = S; rs[32] = S2;
    }
    __syncthreads();
    float mean = rs[0] * (1.f/131072.f);
    float var  = rs[32] * (1.f/131072.f) - mean*mean;
    float inv  = rsqrtf(var + eps);
    for (int i = threadIdx.x; i < 16384; i += 256) {
        const float4* r = (const float4*)(base + (size_t)i*256);
        float4 a = r[0], c = r[1];
        a.x = (a.x-mean)*inv; a.y = (a.y-mean)*inv; a.z = (a.z-mean)*inv; a.w = (a.w-mean)*inv;
        c.x = (c.x-mean)*inv; c.y = (c.y-mean)*inv; c.z = (c.z-mean)*inv; c.w = (c.w-mean)*inv;
        if (ROUND) {
            a.x = tf32r(a.x); a.y = tf32r(a.y); a.z = tf32r(a.z); a.w = tf32r(a.w);
            c.x = tf32r(c.x); c.y = tf32r(c.y); c.z = tf32r(c.z); c.w = tf32r(c.w);
        }
        float4* o4 = (float4*)(ob + (size_t)i*256);
        o4[0] = a; o4[1] = c;
    }
}

// ---------------- fused GN(h2) + x += gres*hn; h2 <- tf32 shadow of new x ----------------
__global__ void k_gn_axpy(float* __restrict__ h2, float* __restrict__ x,
                          const float* __restrict__ gate, float eps) {
    __shared__ float rs[64];
    int b = blockIdx.x >> 5, g = blockIdx.x & 31;
    float* hb = h2 + (size_t)b*16384*256 + g*8;
    float* xb = x  + (size_t)b*16384*256 + g*8;
    float s = 0.f, s2 = 0.f;
    for (int i = threadIdx.x; i < 16384; i += 256) {
        const float4* r = (const float4*)(hb + (size_t)i*256);
        float4 a = r[0], c = r[1];
        s  += a.x+a.y+a.z+a.w + c.x+c.y+c.z+c.w;
        s2 += a.x*a.x+a.y*a.y+a.z*a.z+a.w*a.w + c.x*c.x+c.y*c.y+c.z*c.z+c.w*c.w;
    }
    int lane = threadIdx.x & 31, w = threadIdx.x >> 5;
    #pragma unroll
    for (int o = 16; o; o >>= 1) {
        s  += __shfl_down_sync(0xffffffffu, s,  o);
        s2 += __shfl_down_sync(0xffffffffu, s2, o);
    }
    if (lane == 0) { rs[w] = s; rs[32 + w] = s2; }
    __syncthreads();
    if (threadIdx.x == 0) {
        float S = 0.f, S2 = 0.f;
        for (int i = 0; i < 8; i++) { S += rs[i]; S2 += rs[32 + i]; }
        rs[0] = S; rs[32] = S2;
    }
    __syncthreads();
    float mean = rs[0] * (1.f/131072.f);
    float var  = rs[32] * (1.f/131072.f) - mean*mean;
    float inv  = rsqrtf(var + eps);
    float gg = gate[0];
    for (int i = threadIdx.x; i < 16384; i += 256) {
        float4* hr = (float4*)(hb + (size_t)i*256);
        float4* xr = (float4*)(xb + (size_t)i*256);
        float4 a = hr[0], c = hr[1];
        float4 xa = xr[0], xc = xr[1];
        xa.x += gg*(a.x-mean)*inv; xa.y += gg*(a.y-mean)*inv;
        xa.z += gg*(a.z-mean)*inv; xa.w += gg*(a.w-mean)*inv;
        xc.x += gg*(c.x-mean)*inv; xc.y += gg*(c.y-mean)*inv;
        xc.z += gg*(c.z-mean)*inv; xc.w += gg*(c.w-mean)*inv;
        xr[0] = xa; xr[1] = xc;
        hr[0] = make_float4(tf32r(xa.x), tf32r(xa.y), tf32r(xa.z), tf32r(xa.w));
        hr[1] = make_float4(tf32r(xc.x), tf32r(xc.y), tf32r(xc.z), tf32r(xc.w));
    }
}

// ---------------- layer2 attention over Fq per (b,t,h); tf32-rounded out ----------
__global__ void k_attn_freq(const float* __restrict__ qkv, float* __restrict__ y) {
    __shared__ float q[64][33], kk[64][33], v[64][33];
    __shared__ float S[64][65];
    int bt = blockIdx.x, h = blockIdx.y;
    int b = bt >> 8, t = bt & 255;
    int tid = threadIdx.x;
    for (int i = tid; i < 2048; i += 128) {
        int fq = i >> 5, d = i & 31;
        size_t base = ((size_t)((b*64 + fq)*256 + t))*768 + h*32 + d;
        q[fq][d]  = qkv[base];
        kk[fq][d] = qkv[base + 256];
        v[fq][d]  = qkv[base + 512];
    }
    __syncthreads();
    const float scale = 0.17677669529663687f;
    for (int i = tid; i < 4096; i += 128) {
        int L = i >> 6, l = i & 63;
        float s = 0.f;
        #pragma unroll
        for (int d = 0; d < 32; d++) s += q[L][d] * kk[l][d];
        S[L][l] = s * scale;
    }
    __syncthreads();
    if (tid < 64) {
        float m = -1e30f;
        for (int l = 0; l < 64; l++) m = fmaxf(m, S[tid][l]);
        float su = 0.f;
        for (int l = 0; l < 64; l++) { float e = __expf(S[tid][l] - m); S[tid][l] = e; su += e; }
        float r = 1.f / su;
        for (int l = 0; l < 64; l++) S[tid][l] *= r;
    }
    __syncthreads();
    for (int i = tid; i < 2048; i += 128) {
        int L = i >> 5, d = i & 31;
        float s = 0.f;
        #pragma unroll
        for (int l = 0; l < 64; l++) s += S[L][l] * v[l][d];
        y[((size_t)((b*64 + L)*256 + t))*256 + h*32 + d] = tf32r(s);
    }
}

// ---------------- per-token GN then x += g2*y; tf32 shadow ----------
__global__ void k_gnrow_add(const float* __restrict__ yv, float* __restrict__ x,
                            const float* __restrict__ gate, float* __restrict__ xs) {
    int idx = blockIdx.x * 256 + threadIdx.x;
    int p = idx >> 5, g = idx & 31;
    size_t off = (size_t)p * 256 + g * 8;
    float4 a = *(const float4*)(yv + off), c = *(const float4*)(yv + off + 4);
    float vals[8] = {a.x, a.y, a.z, a.w, c.x, c.y, c.z, c.w};
    float m = 0.f;
    #pragma unroll
    for (int j = 0; j < 8; j++) m += vals[j];
    m *= 0.125f;
    float var = 0.f;
    #pragma unroll
    for (int j = 0; j < 8; j++) { float dd = vals[j] - m; var += dd * dd; }
    var *= 0.125f;
    float inv = rsqrtf(var + 1e-5f);
    float gg = gate[0];
    float xo[8];
    float4 xa = *(float4*)(x + off), xb = *(float4*)(x + off + 4);
    xo[0]=xa.x; xo[1]=xa.y; xo[2]=xa.z; xo[3]=xa.w;
    xo[4]=xb.x; xo[5]=xb.y; xo[6]=xb.z; xo[7]=xb.w;
    #pragma unroll
    for (int j = 0; j < 8; j++) xo[j] += gg * (vals[j] - m) * inv;
    *(float4*)(x + off)     = make_float4(xo[0], xo[1], xo[2], xo[3]);
    *(float4*)(x + off + 4) = make_float4(xo[4], xo[5], xo[6], xo[7]);
    *(float4*)(xs + off)     = make_float4(tf32r(xo[0]), tf32r(xo[1]), tf32r(xo[2]), tf32r(xo[3]));
    *(float4*)(xs + off + 4) = make_float4(tf32r(xo[4]), tf32r(xo[5]), tf32r(xo[6]), tf32r(xo[7]));
}

// ---------------- layer3 global attention per (bfq, h); tf32-rounded out --------
__global__ void k_attn_time(const float* __restrict__ qkv, float* __restrict__ yout) {
    __shared__ float part[8][32];
    __shared__ float qm[32];
    __shared__ float prob[256];
    __shared__ float redm[8], reds[8];
    int bfq = blockIdx.x, h = blockIdx.y;
    int tid = threadIdx.x;
    size_t tokbase = (size_t)bfq * 256;
    int d = tid & 31, grp = tid >> 5;
    float s = 0.f;
    for (int t = grp; t < 256; t += 8)
        s += qkv[(tokbase + t)*768 + h*32 + d];
    part[grp][d] = s;
    __syncthreads();
    if (tid < 32) {
        float ss = 0.f;
        #pragma unroll
        for (int g = 0; g < 8; g++) ss += part[g][tid];
        qm[tid] = ss * (1.f/256.f);
    }
    __syncthreads();
    const float* kr = qkv + (tokbase + tid)*768 + 256 + h*32;
    float sc = 0.f;
    #pragma unroll
    for (int dd = 0; dd < 32; dd++) sc += qm[dd] * kr[dd];
    sc *= 0.17677669529663687f;
    float m = sc;
    #pragma unroll
    for (int o = 16; o; o >>= 1) m = fmaxf(m, __shfl_xor_sync(0xffffffffu, m, o));
    if ((tid & 31) == 0) redm[grp] = m;
    __syncthreads();
    float M = redm[0];
    #pragma unroll
    for (int g = 1; g < 8; g++) M = fmaxf(M, redm[g]);
    float e = __expf(sc - M);
    float su = e;
    #pragma unroll
    for (int o = 16; o; o >>= 1) su += __shfl_xor_sync(0xffffffffu, su, o);
    if ((tid & 31) == 0) reds[grp] = su;
    __syncthreads();
    float Ssum = 0.f;
    #pragma unroll
    for (int g = 0; g < 8; g++) Ssum += reds[g];
    prob[tid] = e / Ssum;
    __syncthreads();
    float acc = 0.f;
    for (int t = grp; t < 256; t += 8)
        acc += prob[t] * qkv[(tokbase + t)*768 + 512 + h*32 + d];
    part[grp][d] = acc;
    __syncthreads();
    if (tid < 32) {
        float ss = 0.f;
        #pragma unroll
        for (int g = 0; g < 8; g++) ss += part[g][tid];
        yout[(size_t)bfq*256 + h*32 + tid] = tf32r(ss);
    }
}

// ---------------- layer3 epilogue ----------------
__global__ void k_gn_bcast_add(const float* __restrict__ yv, float* __restrict__ x,
                               const float* __restrict__ gate) {
    __shared__ float yn[256];
    int bfq = blockIdx.x, tid = threadIdx.x;
    if (tid < 32) {
        const float* r = yv + bfq*256 + tid*8;
        float vals[8];
        #pragma unroll
        for (int j = 0; j < 8; j++) vals[j] = r[j];
        float m = 0.f;
        #pragma unroll
        for (int j = 0; j < 8; j++) m += vals[j];
        m *= 0.125f;
        float var = 0.f;
        #pragma unroll
        for (int j = 0; j < 8; j++) { float dd = vals[j] - m; var += dd * dd; }
        var *= 0.125f;
        float inv = rsqrtf(var + 1e-5f);
        #pragma unroll
        for (int j = 0; j < 8; j++) yn[tid*8 + j] = (vals[j] - m) * inv;
    }
    __syncthreads();
    float add = gate[0] * yn[tid];
    float* xp = x + (size_t)bfq * 65536 + tid;
    for (int t = 0; t < 256; t++) xp[(size_t)t * 256] += add;
}

// ---------------- layer4 LSA; tf32-rounded out ----------------
__global__ void k_attn_lsa(const float* __restrict__ qkv, float* __restrict__ y) {
    __shared__ float q[16][33], kk[16][33], v[16][33];
    __shared__ float S[16][17];
    int blk = blockIdx.x;
    size_t p0 = (size_t)(blk >> 4) * 256 + (blk & 15) * 16;
    int tid = threadIdx.x;
    int qi = tid >> 4, kj = tid & 15;
    const float scale = 0.17677669529663687f;
    for (int h = 0; h < 8; h++) {
        for (int i = tid; i < 512; i += 256) {
            int r = i >> 5, d = i & 31;
            size_t a = (p0 + r)*768 + h*32 + d;
            q[r][d] = qkv[a]; kk[r][d] = qkv[a + 256]; v[r][d] = qkv[a + 512];
        }
        __syncthreads();
        float s = 0.f;
        #pragma unroll
        for (int d = 0; d < 32; d++) s += q[qi][d] * kk[kj][d];
        S[qi][kj] = s * scale;
        __syncthreads();
        if (tid < 16) {
            float m = -1e30f;
            for (int j = 0; j < 16; j++) m = fmaxf(m, S[tid][j]);
            float su = 0.f;
            for (int j = 0; j < 16; j++) { float e = __expf(S[tid][j] - m); S[tid][j] = e; su += e; }
            float r = 1.f / su;
            for (int j = 0; j < 16; j++) S[tid][j] *= r;
        }
        __syncthreads();
        for (int i = tid; i < 512; i += 256) {
            int r = i >> 5, d = i & 31;
            float s2 = 0.f;
            #pragma unroll
            for (int j = 0; j < 16; j++) s2 += S[r][j] * v[j][d];
            y[(p0 + r)*256 + h*32 + d] = tf32r(s2);
        }
        __syncthreads();
    }
}

// =====================================================================================
extern "C" void kernel_launch(void* const* d_in, const int* in_sizes, int n_in,
                              void* d_out, int out_size) {
    const float* x     = (const float*)d_in[0];
    const float* temb  = (const float*)d_in[1];
    const float* w1    = (const float*)d_in[2];
    const float* b1    = (const float*)d_in[3];
    const float* w2    = (const float*)d_in[4];
    const float* gdiff = (const float*)d_in[5];
    const float* gres  = (const float*)d_in[6];
    const float* g2    = (const float*)d_in[7];
    const float* g3    = (const float*)d_in[8];
    const float* qkv2w = (const float*)d_in[9];
    const float* qkv2b = (const float*)d_in[10];
    const float* out2w = (const float*)d_in[11];
    const float* qkv3w = (const float*)d_in[12];
    const float* qkv3b = (const float*)d_in[13];
    const float* out3w = (const float*)d_in[14];
    const float* lsaqw = (const float*)d_in[15];
    const float* lsaow = (const float*)d_in[16];
    float* out = (float*)d_out;

    float *px, *ph, *ph2, *py, *pqkv, *pa3, *pa3b, *pwt;
    float *pwq2, *pwo2, *pwq3, *pwo3, *pwq4, *pwo4;
    cudaGetSymbolAddress((void**)&px,   g_x);
    cudaGetSymbolAddress((void**)&ph,   g_h);
    cudaGetSymbolAddress((void**)&ph2,  g_h2);
    cudaGetSymbolAddress((void**)&py,   g_y);
    cudaGetSymbolAddress((void**)&pqkv, g_qkv);
    cudaGetSymbolAddress((void**)&pa3,  g_a3);
    cudaGetSymbolAddress((void**)&pa3b, g_a3b);
    cudaGetSymbolAddress((void**)&pwt,  g_wt);
    cudaGetSymbolAddress((void**)&pwq2, g_wq2);
    cudaGetSymbolAddress((void**)&pwo2, g_wo2);
    cudaGetSymbolAddress((void**)&pwq3, g_wq3);
    cudaGetSymbolAddress((void**)&pwo3, g_wo3);
    cudaGetSymbolAddress((void**)&pwq4, g_wq4);
    cudaGetSymbolAddress((void**)&pwo4, g_wo4);

    cudaFuncSetAttribute(k_mm<0>, cudaFuncAttributeMaxDynamicSharedMemorySize, SMEM_MM);
    cudaFuncSetAttribute(k_mm<1>, cudaFuncAttributeMaxDynamicSharedMemorySize, SMEM_MM);
    cudaFuncSetAttribute(k_mm<2>, cudaFuncAttributeMaxDynamicSharedMemorySize, SMEM_MM);
    cudaFuncSetAttribute(k_mm<3>, cudaFuncAttributeMaxDynamicSharedMemorySize, SMEM_MM);

    dim3 tb32(32, 8);

    k_nchw_to_nhwc<<<dim3(8, 8, 256), tb32>>>(x, px);

    // weight prepack (tf32, tile-packed)
    k_prepb<<<768, 256>>>(qkv2w, pwq2, 256, 768);
    k_prepb<<<256, 256>>>(out2w, pwo2, 256, 256);
    k_prepb<<<768, 256>>>(qkv3w, pwq3, 256, 768);
    k_prepb<<<256, 256>>>(out3w, pwo3, 256, 256);
    k_prepb<<<768, 256>>>(lsaqw, pwq4, 256, 768);
    k_prepb<<<256, 256>>>(lsaow, pwo4, 256, 256);

    // ---- Residual block ----
    k_gn_bg<true><<<128, 256>>>(px, ph, 1e-6f);
    k_prepconv<<<2304, 256>>>(w1, pwt);
    k_mm<3><<<dim3(2, 256), 256, SMEM_MM>>>(ph, pwt, b1, temb, gdiff, ph2, 2304, 256);
    k_gn_bg<true><<<128, 256>>>(ph2, ph, 1e-6f);
    k_prepconv<<<2304, 256>>>(w2, pwt);
    k_mm<2><<<dim3(2, 256), 256, SMEM_MM>>>(ph, pwt, nullptr, nullptr, nullptr, ph2, 2304, 256);
    k_gn_axpy<<<128, 256>>>(ph2, px, gres, 1e-6f);    // ph2 = tf32 shadow of updated px

    // ---- layer2 ----
    k_mm<1><<<dim3(6, 256), 256, SMEM_MM>>>(ph2, pwq2, qkv2b, nullptr, nullptr, pqkv, 256, 768);
    k_attn_freq<<<dim3(1024, 8), 128>>>(pqkv, py);
    k_mm<0><<<dim3(2, 256), 256, SMEM_MM>>>(py, pwo2, nullptr, nullptr, nullptr, ph, 256, 256);
    k_gnrow_add<<<8192, 256>>>(ph, px, g2, ph2);

    // ---- layer3 ----
    k_mm<1><<<dim3(6, 256), 256, SMEM_MM>>>(ph2, pwq3, qkv3b, nullptr, nullptr, pqkv, 256, 768);
    k_attn_time<<<dim3(256, 8), 256>>>(pqkv, pa3);
    k_mm<0><<<dim3(2, 1), 256, SMEM_MM>>>(pa3, pwo3, nullptr, nullptr, nullptr, pa3b, 256, 256);
    k_gn_bcast_add<<<256, 256>>>(pa3b, px, g3);

    // ---- layer4 ----
    k_gn_bg<true><<<128, 256>>>(px, ph, 1e-5f);
    k_mm<0><<<dim3(6, 256), 256, SMEM_MM>>>(ph, pwq4, nullptr, nullptr, nullptr, pqkv, 256, 768);
    k_attn_lsa<<<4096, 256>>>(pqkv, py);
    k_mm<0><<<dim3(2, 256), 256, SMEM_MM>>>(py, pwo4, nullptr, nullptr, nullptr, ph, 256, 256);

    k_nhwc_to_nchw_add<<<dim3(8, 8, 256), tb32>>>(px, ph, out);
}

// round 10
// speedup vs baseline: 1.0249x; 1.0249x over previous
#include <cuda_runtime.h>
#include <cstdint>
#include <math.h>

// B=4, C=256, Fq=64, T=256, HEADS=8, Dh=32, GROUPS=32, WIN=16
#define NTOK   65536
#define ELEMS  16777216

// ---------------- scratch ----------------
__device__ float g_x[ELEMS];
__device__ float g_h[ELEMS];
__device__ float g_h2[ELEMS];       // tf32 shadow of g_x
__device__ float g_y[ELEMS];
__device__ float g_qkv[3*ELEMS];
__device__ float g_a3[65536];
__device__ float g_a3b[65536];
__device__ float g_wt[589824];      // conv weights, packed
__device__ float g_wq2[196608];
__device__ float g_wo2[65536];
__device__ float g_wq3[196608];
__device__ float g_wo3[65536];
__device__ float g_wq4[196608];
__device__ float g_wo4[65536];

// ---------------- tf32 helpers ----------------
__device__ __forceinline__ uint32_t f2tf(float x) {
    uint32_t r; asm("cvt.rna.tf32.f32 %0, %1;" : "=r"(r) : "f"(x)); return r;
}
__device__ __forceinline__ float tf32r(float x) { return __uint_as_float(f2tf(x)); }
__device__ __forceinline__ void mma8(float* d, const uint32_t* a, const uint32_t* b) {
    asm volatile("mma.sync.aligned.m16n8k8.row.col.f32.tf32.tf32.f32 "
        "{%0,%1,%2,%3}, {%4,%5,%6,%7}, {%8,%9}, {%0,%1,%2,%3};"
        : "+f"(d[0]), "+f"(d[1]), "+f"(d[2]), "+f"(d[3])
        : "r"(a[0]), "r"(a[1]), "r"(a[2]), "r"(a[3]), "r"(b[0]), "r"(b[1]));
}
__device__ __forceinline__ void cpa16(uint32_t dst, const void* src, int sz) {
    asm volatile("cp.async.cg.shared.global [%0], [%1], 16, %2;" :: "r"(dst), "l"(src), "r"(sz));
}
__device__ __forceinline__ void cpa_commit() { asm volatile("cp.async.commit_group;"); }
__device__ __forceinline__ void cpa_wait0()  { asm volatile("cp.async.wait_group 0;"); }

// packed-pos -> local k within a 32-k tile: pos = 8*ks + 2*tig + b -> k = 8*ks + tig + 4*b
__device__ __forceinline__ int kOfPos(int pos) {
    int ks = pos >> 3, rem = pos & 7;
    return ks*8 + (rem >> 1) + 4*(rem & 1);
}

// smem stage (words): A[128][36] at 0, B packed rows [128][40] at 4608; stage = 9728 words
#define STAGE_W 9728
#define BS_OFF  4608
#define SMEM_MM (2*STAGE_W*4)   // 77824 B -> 2 CTA/SM

// ============ pipelined tf32 GEMM: 128x128 tile, Kt=32, cp.async 2-stage ============
// MODE: 0 plain, 1 +bias, 4 fused per-token GroupNorm(8ch) + x += gate*yn + tf32 shadow
template<int MODE>
__global__ __launch_bounds__(256, 2) void k_pgemm(
    const float* __restrict__ A, const float* __restrict__ Bp,
    const float* __restrict__ bias, const float* __restrict__ gate,
    float* __restrict__ C, float* __restrict__ xg, float* __restrict__ xs,
    int M, int N, int K) {
    extern __shared__ uint32_t dynsm[];
    uint32_t sbase = (uint32_t)__cvta_generic_to_shared(dynsm);
    int tid = threadIdx.x, lane = tid & 31, wid = tid >> 5;
    int g = lane >> 2, tig = lane & 3;
    int wm = wid >> 1, wn = wid & 1;
    int bn = blockIdx.x * 128, bm = blockIdx.y * 128;
    float acc[2][8][4] = {};
    int KT = K >> 5;

    auto copy = [&](int kt, int s) {
        int k0 = kt << 5;
        #pragma unroll
        for (int i = 0; i < 4; i++) {
            int idx = tid + i*256;
            int row = idx >> 3, c4 = idx & 7;
            cpa16(sbase + (s*STAGE_W + row*36 + c4*4)*4,
                  A + (size_t)(bm + row)*K + k0 + c4*4, 16);
            cpa16(sbase + (s*STAGE_W + BS_OFF + row*40 + c4*4)*4,
                  Bp + ((size_t)kt*N + bn + row)*32 + c4*4, 16);
        }
        cpa_commit();
    };

    copy(0, 0);
    for (int kt = 0; kt < KT; kt++) {
        cpa_wait0();
        __syncthreads();
        if (kt + 1 < KT) copy(kt + 1, (kt + 1) & 1);
        const uint32_t* As = dynsm + (kt & 1)*STAGE_W;
        const uint32_t* Bt = As + BS_OFF;
        #pragma unroll
        for (int ks = 0; ks < 4; ks++) {
            int k = ks * 8;
            uint32_t af[2][4], bf[8][2];
            #pragma unroll
            for (int mt = 0; mt < 2; mt++) {
                int r0 = wm*32 + mt*16;
                af[mt][0] = As[(r0 + g)*36 + k + tig];
                af[mt][1] = As[(r0 + g + 8)*36 + k + tig];
                af[mt][2] = As[(r0 + g)*36 + k + tig + 4];
                af[mt][3] = As[(r0 + g + 8)*36 + k + tig + 4];
            }
            #pragma unroll
            for (int nt = 0; nt < 8; nt++) {
                int c0 = wn*64 + nt*8 + g;
                uint2 bv = *(const uint2*)&Bt[c0*40 + k + tig*2];
                bf[nt][0] = bv.x; bf[nt][1] = bv.y;
            }
            #pragma unroll
            for (int mt = 0; mt < 2; mt++)
                #pragma unroll
                for (int nt = 0; nt < 8; nt++)
                    mma8(acc[mt][nt], af[mt], bf[nt]);
        }
    }

    if (MODE != 4) {
        #pragma unroll
        for (int mt = 0; mt < 2; mt++) {
            int row = bm + wm*32 + mt*16 + g;
            #pragma unroll
            for (int nt = 0; nt < 8; nt++) {
                int col = bn + wn*64 + nt*8 + tig*2;
                float2 v0 = make_float2(acc[mt][nt][0], acc[mt][nt][1]);
                float2 v1 = make_float2(acc[mt][nt][2], acc[mt][nt][3]);
                if (MODE == 1) {
                    float b0 = bias[col], b1v = bias[col + 1];
                    v0.x += b0; v0.y += b1v; v1.x += b0; v1.y += b1v;
                }
                *(float2*)(C + (size_t)row*N + col) = v0;
                *(float2*)(C + (size_t)(row + 8)*N + col) = v1;
            }
        }
    } else {
        // fused: per-(row, group nt) GN over 8 cols (quad = lanes 4g..4g+3),
        // then x += gate*yn; write x and tf32 shadow xs.
        float gg = gate[0];
        #pragma unroll
        for (int mt = 0; mt < 2; mt++) {
            int row = bm + wm*32 + mt*16 + g;
            #pragma unroll
            for (int nt = 0; nt < 8; nt++) {
                int col = bn + wn*64 + nt*8 + tig*2;
                float a0 = acc[mt][nt][0], a1 = acc[mt][nt][1];   // row
                float b0 = acc[mt][nt][2], b1 = acc[mt][nt][3];   // row+8
                // mean (two independent groups: row, row+8)
                float s0 = a0 + a1, s1 = b0 + b1;
                s0 += __shfl_xor_sync(0xffffffffu, s0, 1);
                s0 += __shfl_xor_sync(0xffffffffu, s0, 2);
                s1 += __shfl_xor_sync(0xffffffffu, s1, 1);
                s1 += __shfl_xor_sync(0xffffffffu, s1, 2);
                float m0 = s0 * 0.125f, m1 = s1 * 0.125f;
                // var (two-pass, matches previous k_gnrow_add numerics)
                float d00 = a0 - m0, d01 = a1 - m0, d10 = b0 - m1, d11 = b1 - m1;
                float q0 = d00*d00 + d01*d01, q1 = d10*d10 + d11*d11;
                q0 += __shfl_xor_sync(0xffffffffu, q0, 1);
                q0 += __shfl_xor_sync(0xffffffffu, q0, 2);
                q1 += __shfl_xor_sync(0xffffffffu, q1, 1);
                q1 += __shfl_xor_sync(0xffffffffu, q1, 2);
                float i0 = rsqrtf(q0*0.125f + 1e-5f), i1 = rsqrtf(q1*0.125f + 1e-5f);
                size_t o0 = (size_t)row*N + col, o1 = (size_t)(row + 8)*N + col;
                float2 x0 = *(float2*)(xg + o0), x1 = *(float2*)(xg + o1);
                x0.x += gg * d00 * i0; x0.y += gg * d01 * i0;
                x1.x += gg * d10 * i1; x1.y += gg * d11 * i1;
                *(float2*)(xg + o0) = x0;
                *(float2*)(xg + o1) = x1;
                *(float2*)(xs + o0) = make_float2(tf32r(x0.x), tf32r(x0.y));
                *(float2*)(xs + o1) = make_float2(tf32r(x1.x), tf32r(x1.y));
            }
        }
    }
}

// ============ pipelined conv3x3 implicit GEMM, prepacked weights ============
template<int MODE>   // 0 plain, 1 bias+temb+silu
__global__ __launch_bounds__(256, 2) void k_pconv(
    const float* __restrict__ In, const float* __restrict__ Wp,
    const float* __restrict__ bias, const float* __restrict__ temb,
    const float* __restrict__ gate, float* __restrict__ Out) {
    extern __shared__ uint32_t dynsm[];
    uint32_t sbase = (uint32_t)__cvta_generic_to_shared(dynsm);
    int tid = threadIdx.x, lane = tid & 31, wid = tid >> 5;
    int g = lane >> 2, tig = lane & 3;
    int wm = wid >> 1, wn = wid & 1;
    int bn = blockIdx.x * 128, bm = blockIdx.y * 128;
    float acc[2][8][4] = {};

    int pb[4], pfy[4], pfx[4];
    #pragma unroll
    for (int i = 0; i < 4; i++) {
        int p = bm + ((tid + i*256) >> 3);
        pb[i] = p >> 14; pfy[i] = (p >> 8) & 63; pfx[i] = p & 255;
    }

    auto copy = [&](int kt, int s) {
        int k0 = kt << 5;
        int kyx = k0 >> 8, ci0 = k0 & 255;
        int ky = kyx / 3, kx = kyx - ky*3;
        #pragma unroll
        for (int i = 0; i < 4; i++) {
            int idx = tid + i*256;
            int row = idx >> 3, c4 = idx & 7;
            int fy2 = pfy[i] + ky - 1, fx2 = pfx[i] + kx - 1;
            bool v = ((unsigned)fy2 < 64u) && ((unsigned)fx2 < 256u);
            cpa16(sbase + (s*STAGE_W + row*36 + c4*4)*4,
                  In + (((size_t)(pb[i]*64 + (v?fy2:0)))*256 + (v?fx2:0))*256 + ci0 + c4*4,
                  v ? 16 : 0);
            cpa16(sbase + (s*STAGE_W + BS_OFF + row*40 + c4*4)*4,
                  Wp + ((size_t)kt*256 + bn + row)*32 + c4*4, 16);
        }
        cpa_commit();
    };

    copy(0, 0);
    for (int kt = 0; kt < 72; kt++) {
        cpa_wait0();
        __syncthreads();
        if (kt + 1 < 72) copy(kt + 1, (kt + 1) & 1);
        const uint32_t* As = dynsm + (kt & 1)*STAGE_W;
        const uint32_t* Bt = As + BS_OFF;
        #pragma unroll
        for (int ks = 0; ks < 4; ks++) {
            int k = ks * 8;
            uint32_t af[2][4], bf[8][2];
            #pragma unroll
            for (int mt = 0; mt < 2; mt++) {
                int r0 = wm*32 + mt*16;
                af[mt][0] = As[(r0 + g)*36 + k + tig];
                af[mt][1] = As[(r0 + g + 8)*36 + k + tig];
                af[mt][2] = As[(r0 + g)*36 + k + tig + 4];
                af[mt][3] = As[(r0 + g + 8)*36 + k + tig + 4];
            }
            #pragma unroll
            for (int nt = 0; nt < 8; nt++) {
                int c0 = wn*64 + nt*8 + g;
                uint2 bv = *(const uint2*)&Bt[c0*40 + k + tig*2];
                bf[nt][0] = bv.x; bf[nt][1] = bv.y;
            }
            #pragma unroll
            for (int mt = 0; mt < 2; mt++)
                #pragma unroll
                for (int nt = 0; nt < 8; nt++)
                    mma8(acc[mt][nt], af[mt], bf[nt]);
        }
    }
    float gd = (MODE == 1) ? gate[0] : 0.f;
    #pragma unroll
    for (int mt = 0; mt < 2; mt++) {
        int row = bm + wm*32 + mt*16 + g;
        int bidx = row >> 14;
        #pragma unroll
        for (int nt = 0; nt < 8; nt++) {
            int col = bn + wn*64 + nt*8 + tig*2;
            float v[4] = {acc[mt][nt][0], acc[mt][nt][1], acc[mt][nt][2], acc[mt][nt][3]};
            if (MODE == 1) {
                float a0 = bias[col]     + gd * temb[bidx*256 + col];
                float a1 = bias[col + 1] + gd * temb[bidx*256 + col + 1];
                v[0] += a0; v[1] += a1; v[2] += a0; v[3] += a1;
                #pragma unroll
                for (int j = 0; j < 4; j++) v[j] = v[j] / (1.f + __expf(-v[j]));
            }
            *(float2*)(Out + (size_t)row*256 + col) = make_float2(v[0], v[1]);
            *(float2*)(Out + (size_t)(row + 8)*256 + col) = make_float2(v[2], v[3]);
        }
    }
}

// ---------------- weight prepacks ----------------
// P[(kt*N + n)*32 + pos] = tf32(W[(kt*32 + kOfPos(pos))*N + n])
__global__ void k_prepb(const float* __restrict__ W, float* __restrict__ P, int K, int N) {
    int idx = blockIdx.x * 256 + threadIdx.x;
    if (idx >= K * N) return;
    int pos = idx & 31;
    int rest = idx >> 5;
    int n = rest % N;
    int kt = rest / N;
    int k = kt*32 + kOfPos(pos);
    P[idx] = tf32r(W[(size_t)k * N + n]);
}
__global__ void k_prepconv(const float* __restrict__ w, float* __restrict__ P) {
    int idx = blockIdx.x * 256 + threadIdx.x;
    int pos = idx & 31;
    int rest = idx >> 5;
    int co = rest & 255;
    int kt = rest >> 8;
    int k = kt*32 + kOfPos(pos);
    int kyx = k >> 8, ci = k & 255;
    P[idx] = tf32r(w[(size_t)co * 2304 + ci * 9 + kyx]);
}

// ---------------- transposes ----------------
__global__ void k_nchw_to_nhwc(const float* __restrict__ in, float* __restrict__ out) {
    __shared__ float tile[32][33];
    int bfq = blockIdx.z, b = bfq >> 6, fq = bfq & 63;
    int t0 = blockIdx.x * 32, c0 = blockIdx.y * 32;
    for (int r = threadIdx.y; r < 32; r += 8)
        tile[r][threadIdx.x] = in[(((size_t)b*256 + c0 + r)*64 + fq)*256 + t0 + threadIdx.x];
    __syncthreads();
    for (int r = threadIdx.y; r < 32; r += 8)
        out[((size_t)bfq*256 + t0 + r)*256 + c0 + threadIdx.x] = tile[threadIdx.x][r];
}

__global__ void k_nhwc_to_nchw_add(const float* __restrict__ xa, const float* __restrict__ xb,
                                   float* __restrict__ out) {
    __shared__ float tile[32][33];
    int bfq = blockIdx.z, b = bfq >> 6, fq = bfq & 63;
    int t0 = blockIdx.x * 32, c0 = blockIdx.y * 32;
    for (int r = threadIdx.y; r < 32; r += 8) {
        size_t p = ((size_t)bfq*256 + t0 + r)*256 + c0 + threadIdx.x;
        tile[r][threadIdx.x] = xa[p] + xb[p];
    }
    __syncthreads();
    for (int r = threadIdx.y; r < 32; r += 8)
        out[(((size_t)b*256 + c0 + r)*64 + fq)*256 + t0 + threadIdx.x] = tile[threadIdx.x][r];
}

// ---------------- GroupNorm per (b, g); ROUND -> tf32-rounded out ----------------
template<bool ROUND>
__global__ void k_gn_bg(const float* __restrict__ in, float* __restrict__ out, float eps) {
    __shared__ float rs[64];
    int b = blockIdx.x >> 5, g = blockIdx.x & 31;
    const float* base = in  + (size_t)b*16384*256 + g*8;
    float*       ob   = out + (size_t)b*16384*256 + g*8;
    float s = 0.f, s2 = 0.f;
    for (int i = threadIdx.x; i < 16384; i += 256) {
        const float4* r = (const float4*)(base + (size_t)i*256);
        float4 a = r[0], c = r[1];
        s  += a.x+a.y+a.z+a.w + c.x+c.y+c.z+c.w;
        s2 += a.x*a.x+a.y*a.y+a.z*a.z+a.w*a.w + c.x*c.x+c.y*c.y+c.z*c.z+c.w*c.w;
    }
    int lane = threadIdx.x & 31, w = threadIdx.x >> 5;
    #pragma unroll
    for (int o = 16; o; o >>= 1) {
        s  += __shfl_down_sync(0xffffffffu, s,  o);
        s2 += __shfl_down_sync(0xffffffffu, s2, o);
    }
    if (lane == 0) { rs[w] = s; rs[32 + w] = s2; }
    __syncthreads();
    if (threadIdx.x == 0) {
        float S = 0.f, S2 = 0.f;
        for (int i = 0; i < 8; i++) { S += rs[i]; S2 += rs[32 + i]; }
        rs[0] = S; rs[32] = S2;
    }
    __syncthreads();
    float mean = rs[0] * (1.f/131072.f);
    float var  = rs[32] * (1.f/131072.f) - mean*mean;
    float inv  = rsqrtf(var + eps);
    for (int i = threadIdx.x; i < 16384; i += 256) {
        const float4* r = (const float4*)(base + (size_t)i*256);
        float4 a = r[0], c = r[1];
        a.x = (a.x-mean)*inv; a.y = (a.y-mean)*inv; a.z = (a.z-mean)*inv; a.w = (a.w-mean)*inv;
        c.x = (c.x-mean)*inv; c.y = (c.y-mean)*inv; c.z = (c.z-mean)*inv; c.w = (c.w-mean)*inv;
        if (ROUND) {
            a.x = tf32r(a.x); a.y = tf32r(a.y); a.z = tf32r(a.z); a.w = tf32r(a.w);
            c.x = tf32r(c.x); c.y = tf32r(c.y); c.z = tf32r(c.z); c.w = tf32r(c.w);
        }
        float4* o4 = (float4*)(ob + (size_t)i*256);
        o4[0] = a; o4[1] = c;
    }
}

// ---------------- fused GN(h2) + x += gres*hn; h2 <- tf32 shadow of new x ----------------
__global__ void k_gn_axpy(float* __restrict__ h2, float* __restrict__ x,
                          const float* __restrict__ gate, float eps) {
    __shared__ float rs[64];
    int b = blockIdx.x >> 5, g = blockIdx.x & 31;
    float* hb = h2 + (size_t)b*16384*256 + g*8;
    float* xb = x  + (size_t)b*16384*256 + g*8;
    float s = 0.f, s2 = 0.f;
    for (int i = threadIdx.x; i < 16384; i += 256) {
        const float4* r = (const float4*)(hb + (size_t)i*256);
        float4 a = r[0], c = r[1];
        s  += a.x+a.y+a.z+a.w + c.x+c.y+c.z+c.w;
        s2 += a.x*a.x+a.y*a.y+a.z*a.z+a.w*a.w + c.x*c.x+c.y*c.y+c.z*c.z+c.w*c.w;
    }
    int lane = threadIdx.x & 31, w = threadIdx.x >> 5;
    #pragma unroll
    for (int o = 16; o; o >>= 1) {
        s  += __shfl_down_sync(0xffffffffu, s,  o);
        s2 += __shfl_down_sync(0xffffffffu, s2, o);
    }
    if (lane == 0) { rs[w] = s; rs[32 + w] = s2; }
    __syncthreads();
    if (threadIdx.x == 0) {
        float S = 0.f, S2 = 0.f;
        for (int i = 0; i < 8; i++) { S += rs[i]; S2 += rs[32 + i]; }
        rs[0] = S; rs[32] = S2;
    }
    __syncthreads();
    float mean = rs[0] * (1.f/131072.f);
    float var  = rs[32] * (1.f/131072.f) - mean*mean;
    float inv  = rsqrtf(var + eps);
    float gg = gate[0];
    for (int i = threadIdx.x; i < 16384; i += 256) {
        float4* hr = (float4*)(hb + (size_t)i*256);
        float4* xr = (float4*)(xb + (size_t)i*256);
        float4 a = hr[0], c = hr[1];
        float4 xa = xr[0], xc = xr[1];
        xa.x += gg*(a.x-mean)*inv; xa.y += gg*(a.y-mean)*inv;
        xa.z += gg*(a.z-mean)*inv; xa.w += gg*(a.w-mean)*inv;
        xc.x += gg*(c.x-mean)*inv; xc.y += gg*(c.y-mean)*inv;
        xc.z += gg*(c.z-mean)*inv; xc.w += gg*(c.w-mean)*inv;
        xr[0] = xa; xr[1] = xc;
        hr[0] = make_float4(tf32r(xa.x), tf32r(xa.y), tf32r(xa.z), tf32r(xa.w));
        hr[1] = make_float4(tf32r(xc.x), tf32r(xc.y), tf32r(xc.z), tf32r(xc.w));
    }
}

// ---------------- layer2 attention over Fq per (b,t,h); tf32-rounded out ----------
__global__ void k_attn_freq(const float* __restrict__ qkv, float* __restrict__ y) {
    __shared__ float q[64][33], kk[64][33], v[64][33];
    __shared__ float S[64][65];
    int bt = blockIdx.x, h = blockIdx.y;
    int b = bt >> 8, t = bt & 255;
    int tid = threadIdx.x;
    for (int i = tid; i < 2048; i += 128) {
        int fq = i >> 5, d = i & 31;
        size_t base = ((size_t)((b*64 + fq)*256 + t))*768 + h*32 + d;
        q[fq][d]  = qkv[base];
        kk[fq][d] = qkv[base + 256];
        v[fq][d]  = qkv[base + 512];
    }
    __syncthreads();
    const float scale = 0.17677669529663687f;
    for (int i = tid; i < 4096; i += 128) {
        int L = i >> 6, l = i & 63;
        float s = 0.f;
        #pragma unroll
        for (int d = 0; d < 32; d++) s += q[L][d] * kk[l][d];
        S[L][l] = s * scale;
    }
    __syncthreads();
    if (tid < 64) {
        float m = -1e30f;
        for (int l = 0; l < 64; l++) m = fmaxf(m, S[tid][l]);
        float su = 0.f;
        for (int l = 0; l < 64; l++) { float e = __expf(S[tid][l] - m); S[tid][l] = e; su += e; }
        float r = 1.f / su;
        for (int l = 0; l < 64; l++) S[tid][l] *= r;
    }
    __syncthreads();
    for (int i = tid; i < 2048; i += 128) {
        int L = i >> 5, d = i & 31;
        float s = 0.f;
        #pragma unroll
        for (int l = 0; l < 64; l++) s += S[L][l] * v[l][d];
        y[((size_t)((b*64 + L)*256 + t))*256 + h*32 + d] = tf32r(s);
    }
}

// ---------------- layer3 global attention per (bfq, h); tf32-rounded out --------
__global__ void k_attn_time(const float* __restrict__ qkv, float* __restrict__ yout) {
    __shared__ float part[8][32];
    __shared__ float qm[32];
    __shared__ float prob[256];
    __shared__ float redm[8], reds[8];
    int bfq = blockIdx.x, h = blockIdx.y;
    int tid = threadIdx.x;
    size_t tokbase = (size_t)bfq * 256;
    int d = tid & 31, grp = tid >> 5;
    float s = 0.f;
    for (int t = grp; t < 256; t += 8)
        s += qkv[(tokbase + t)*768 + h*32 + d];
    part[grp][d] = s;
    __syncthreads();
    if (tid < 32) {
        float ss = 0.f;
        #pragma unroll
        for (int g = 0; g < 8; g++) ss += part[g][tid];
        qm[tid] = ss * (1.f/256.f);
    }
    __syncthreads();
    const float* kr = qkv + (tokbase + tid)*768 + 256 + h*32;
    float sc = 0.f;
    #pragma unroll
    for (int dd = 0; dd < 32; dd++) sc += qm[dd] * kr[dd];
    sc *= 0.17677669529663687f;
    float m = sc;
    #pragma unroll
    for (int o = 16; o; o >>= 1) m = fmaxf(m, __shfl_xor_sync(0xffffffffu, m, o));
    if ((tid & 31) == 0) redm[grp] = m;
    __syncthreads();
    float M = redm[0];
    #pragma unroll
    for (int g = 1; g < 8; g++) M = fmaxf(M, redm[g]);
    float e = __expf(sc - M);
    float su = e;
    #pragma unroll
    for (int o = 16; o; o >>= 1) su += __shfl_xor_sync(0xffffffffu, su, o);
    if ((tid & 31) == 0) reds[grp] = su;
    __syncthreads();
    float Ssum = 0.f;
    #pragma unroll
    for (int g = 0; g < 8; g++) Ssum += reds[g];
    prob[tid] = e / Ssum;
    __syncthreads();
    float acc = 0.f;
    for (int t = grp; t < 256; t += 8)
        acc += prob[t] * qkv[(tokbase + t)*768 + 512 + h*32 + d];
    part[grp][d] = acc;
    __syncthreads();
    if (tid < 32) {
        float ss = 0.f;
        #pragma unroll
        for (int g = 0; g < 8; g++) ss += part[g][tid];
        yout[(size_t)bfq*256 + h*32 + tid] = tf32r(ss);
    }
}

// ---------------- layer3 epilogue ----------------
__global__ void k_gn_bcast_add(const float* __restrict__ yv, float* __restrict__ x,
                               const float* __restrict__ gate) {
    __shared__ float yn[256];
    int bfq = blockIdx.x, tid = threadIdx.x;
    if (tid < 32) {
        const float* r = yv + bfq*256 + tid*8;
        float vals[8];
        #pragma unroll
        for (int j = 0; j < 8; j++) vals[j] = r[j];
        float m = 0.f;
        #pragma unroll
        for (int j = 0; j < 8; j++) m += vals[j];
        m *= 0.125f;
        float var = 0.f;
        #pragma unroll
        for (int j = 0; j < 8; j++) { float dd = vals[j] - m; var += dd * dd; }
        var *= 0.125f;
        float inv = rsqrtf(var + 1e-5f);
        #pragma unroll
        for (int j = 0; j < 8; j++) yn[tid*8 + j] = (vals[j] - m) * inv;
    }
    __syncthreads();
    float add = gate[0] * yn[tid];
    float* xp = x + (size_t)bfq * 65536 + tid;
    for (int t = 0; t < 256; t++) xp[(size_t)t * 256] += add;
}

// ---------------- layer4 LSA; tf32-rounded out ----------------
__global__ void k_attn_lsa(const float* __restrict__ qkv, float* __restrict__ y) {
    __shared__ float q[16][33], kk[16][33], v[16][33];
    __shared__ float S[16][17];
    int blk = blockIdx.x;
    size_t p0 = (size_t)(blk >> 4) * 256 + (blk & 15) * 16;
    int tid = threadIdx.x;
    int qi = tid >> 4, kj = tid & 15;
    const float scale = 0.17677669529663687f;
    for (int h = 0; h < 8; h++) {
        for (int i = tid; i < 512; i += 256) {
            int r = i >> 5, d = i & 31;
            size_t a = (p0 + r)*768 + h*32 + d;
            q[r][d] = qkv[a]; kk[r][d] = qkv[a + 256]; v[r][d] = qkv[a + 512];
        }
        __syncthreads();
        float s = 0.f;
        #pragma unroll
        for (int d = 0; d < 32; d++) s += q[qi][d] * kk[kj][d];
        S[qi][kj] = s * scale;
        __syncthreads();
        if (tid < 16) {
            float m = -1e30f;
            for (int j = 0; j < 16; j++) m = fmaxf(m, S[tid][j]);
            float su = 0.f;
            for (int j = 0; j < 16; j++) { float e = __expf(S[tid][j] - m); S[tid][j] = e; su += e; }
            float r = 1.f / su;
            for (int j = 0; j < 16; j++) S[tid][j] *= r;
        }
        __syncthreads();
        for (int i = tid; i < 512; i += 256) {
            int r = i >> 5, d = i & 31;
            float s2 = 0.f;
            #pragma unroll
            for (int j = 0; j < 16; j++) s2 += S[r][j] * v[j][d];
            y[(p0 + r)*256 + h*32 + d] = tf32r(s2);
        }
        __syncthreads();
    }
}

// =====================================================================================
extern "C" void kernel_launch(void* const* d_in, const int* in_sizes, int n_in,
                              void* d_out, int out_size) {
    const float* x     = (const float*)d_in[0];
    const float* temb  = (const float*)d_in[1];
    const float* w1    = (const float*)d_in[2];
    const float* b1    = (const float*)d_in[3];
    const float* w2    = (const float*)d_in[4];
    const float* gdiff = (const float*)d_in[5];
    const float* gres  = (const float*)d_in[6];
    const float* g2    = (const float*)d_in[7];
    const float* g3    = (const float*)d_in[8];
    const float* qkv2w = (const float*)d_in[9];
    const float* qkv2b = (const float*)d_in[10];
    const float* out2w = (const float*)d_in[11];
    const float* qkv3w = (const float*)d_in[12];
    const float* qkv3b = (const float*)d_in[13];
    const float* out3w = (const float*)d_in[14];
    const float* lsaqw = (const float*)d_in[15];
    const float* lsaow = (const float*)d_in[16];
    float* out = (float*)d_out;

    float *px, *ph, *ph2, *py, *pqkv, *pa3, *pa3b, *pwt;
    float *pwq2, *pwo2, *pwq3, *pwo3, *pwq4, *pwo4;
    cudaGetSymbolAddress((void**)&px,   g_x);
    cudaGetSymbolAddress((void**)&ph,   g_h);
    cudaGetSymbolAddress((void**)&ph2,  g_h2);
    cudaGetSymbolAddress((void**)&py,   g_y);
    cudaGetSymbolAddress((void**)&pqkv, g_qkv);
    cudaGetSymbolAddress((void**)&pa3,  g_a3);
    cudaGetSymbolAddress((void**)&pa3b, g_a3b);
    cudaGetSymbolAddress((void**)&pwt,  g_wt);
    cudaGetSymbolAddress((void**)&pwq2, g_wq2);
    cudaGetSymbolAddress((void**)&pwo2, g_wo2);
    cudaGetSymbolAddress((void**)&pwq3, g_wq3);
    cudaGetSymbolAddress((void**)&pwo3, g_wo3);
    cudaGetSymbolAddress((void**)&pwq4, g_wq4);
    cudaGetSymbolAddress((void**)&pwo4, g_wo4);

    cudaFuncSetAttribute(k_pgemm<0>, cudaFuncAttributeMaxDynamicSharedMemorySize, SMEM_MM);
    cudaFuncSetAttribute(k_pgemm<1>, cudaFuncAttributeMaxDynamicSharedMemorySize, SMEM_MM);
    cudaFuncSetAttribute(k_pgemm<4>, cudaFuncAttributeMaxDynamicSharedMemorySize, SMEM_MM);
    cudaFuncSetAttribute(k_pconv<0>, cudaFuncAttributeMaxDynamicSharedMemorySize, SMEM_MM);
    cudaFuncSetAttribute(k_pconv<1>, cudaFuncAttributeMaxDynamicSharedMemorySize, SMEM_MM);

    dim3 tb32(32, 8);

    k_nchw_to_nhwc<<<dim3(8, 8, 256), tb32>>>(x, px);

    // weight prepack (tf32, tile-packed)
    k_prepb<<<768, 256>>>(qkv2w, pwq2, 256, 768);
    k_prepb<<<256, 256>>>(out2w, pwo2, 256, 256);
    k_prepb<<<768, 256>>>(qkv3w, pwq3, 256, 768);
    k_prepb<<<256, 256>>>(out3w, pwo3, 256, 256);
    k_prepb<<<768, 256>>>(lsaqw, pwq4, 256, 768);
    k_prepb<<<256, 256>>>(lsaow, pwo4, 256, 256);

    // ---- Residual block ----
    k_gn_bg<true><<<128, 256>>>(px, ph, 1e-6f);
    k_prepconv<<<2304, 256>>>(w1, pwt);
    k_pconv<1><<<dim3(2, 512), 256, SMEM_MM>>>(ph, pwt, b1, temb, gdiff, ph2);
    k_gn_bg<true><<<128, 256>>>(ph2, ph, 1e-6f);
    k_prepconv<<<2304, 256>>>(w2, pwt);
    k_pconv<0><<<dim3(2, 512), 256, SMEM_MM>>>(ph, pwt, nullptr, nullptr, nullptr, ph2);
    k_gn_axpy<<<128, 256>>>(ph2, px, gres, 1e-6f);    // px updated, ph2 = tf32 shadow

    // ---- layer2 ----
    k_pgemm<1><<<dim3(6, 512), 256, SMEM_MM>>>(ph2, pwq2, qkv2b, nullptr, pqkv,
                                               nullptr, nullptr, NTOK, 768, 256);
    k_attn_freq<<<dim3(1024, 8), 128>>>(pqkv, py);
    // fused out-proj + per-token GN + x += g2*yn + shadow refresh
    k_pgemm<4><<<dim3(2, 512), 256, SMEM_MM>>>(py, pwo2, nullptr, g2, ph,
                                               px, ph2, NTOK, 256, 256);

    // ---- layer3 ----
    k_pgemm<1><<<dim3(6, 512), 256, SMEM_MM>>>(ph2, pwq3, qkv3b, nullptr, pqkv,
                                               nullptr, nullptr, NTOK, 768, 256);
    k_attn_time<<<dim3(256, 8), 256>>>(pqkv, pa3);
    k_pgemm<0><<<dim3(2, 2), 256, SMEM_MM>>>(pa3, pwo3, nullptr, nullptr, pa3b,
                                             nullptr, nullptr, 256, 256, 256);
    k_gn_bcast_add<<<256, 256>>>(pa3b, px, g3);

    // ---- layer4 ----
    k_gn_bg<true><<<128, 256>>>(px, ph, 1e-5f);
    k_pgemm<0><<<dim3(6, 512), 256, SMEM_MM>>>(ph, pwq4, nullptr, nullptr, pqkv,
                                               nullptr, nullptr, NTOK, 768, 256);
    k_attn_lsa<<<4096, 256>>>(pqkv, py);
    k_pgemm<0><<<dim3(2, 512), 256, SMEM_MM>>>(py, pwo4, nullptr, nullptr, ph,
                                               nullptr, nullptr, NTOK, 256, 256);

    k_nhwc_to_nchw_add<<<dim3(8, 8, 256), tb32>>>(px, ph, out);
}

// round 11
// speedup vs baseline: 1.0520x; 1.0264x over previous
#include <cuda_runtime.h>
#include <cstdint>
#include <math.h>

// B=4, C=256, Fq=64, T=256, HEADS=8, Dh=32, GROUPS=32, WIN=16
#define NTOK   65536
#define ELEMS  16777216

// ---------------- scratch ----------------
__device__ float g_x[ELEMS];
__device__ float g_h[ELEMS];
__device__ float g_h2[ELEMS];       // tf32 shadow of g_x
__device__ float g_y[ELEMS];
__device__ float g_qkv[3*ELEMS];
__device__ float g_a3[65536];
__device__ float g_a3b[65536];
__device__ float g_qm[65536];       // mean_t(x) per (bfq, c), tf32
__device__ float g_q3[65536];       // layer3 mean-q projected
__device__ float g_wt[589824];      // conv1 weights packed
__device__ float g_wt2[589824];     // conv2 weights packed
__device__ float g_wq2[196608];
__device__ float g_wo2[65536];
__device__ float g_wq3[131072];     // KV-only (N=512)
__device__ float g_wq3q[65536];     // q-only (N=256)
__device__ float g_wo3[65536];
__device__ float g_wq4[196608];
__device__ float g_wo4[65536];

// ---------------- tf32 helpers ----------------
__device__ __forceinline__ uint32_t f2tf(float x) {
    uint32_t r; asm("cvt.rna.tf32.f32 %0, %1;" : "=r"(r) : "f"(x)); return r;
}
__device__ __forceinline__ float tf32r(float x) { return __uint_as_float(f2tf(x)); }
__device__ __forceinline__ void mma8(float* d, const uint32_t* a, const uint32_t* b) {
    asm volatile("mma.sync.aligned.m16n8k8.row.col.f32.tf32.tf32.f32 "
        "{%0,%1,%2,%3}, {%4,%5,%6,%7}, {%8,%9}, {%0,%1,%2,%3};"
        : "+f"(d[0]), "+f"(d[1]), "+f"(d[2]), "+f"(d[3])
        : "r"(a[0]), "r"(a[1]), "r"(a[2]), "r"(a[3]), "r"(b[0]), "r"(b[1]));
}
__device__ __forceinline__ void cpa16(uint32_t dst, const void* src, int sz) {
    asm volatile("cp.async.cg.shared.global [%0], [%1], 16, %2;" :: "r"(dst), "l"(src), "r"(sz));
}
__device__ __forceinline__ void cpa_commit() { asm volatile("cp.async.commit_group;"); }
__device__ __forceinline__ void cpa_wait0()  { asm volatile("cp.async.wait_group 0;"); }

// packed-pos -> local k within a 32-k tile
__device__ __forceinline__ int kOfPos(int pos) {
    int ks = pos >> 3, rem = pos & 7;
    return ks*8 + (rem >> 1) + 4*(rem & 1);
}

// smem stage (words): A[128][36] at 0, B packed rows [128][40] at 4608; stage = 9728 words
#define STAGE_W 9728
#define BS_OFF  4608
#define SMEM_MM (2*STAGE_W*4)   // 77824 B -> 2 CTA/SM

// ============ pipelined tf32 GEMM: 128x128 tile, Kt=32, cp.async 2-stage ============
// MODE: 0 plain, 1 +bias, 4 fused per-token GN(8ch) + x += gate*yn + tf32 shadow
template<int MODE>
__global__ __launch_bounds__(256, 2) void k_pgemm(
    const float* __restrict__ A, const float* __restrict__ Bp,
    const float* __restrict__ bias, const float* __restrict__ gate,
    float* __restrict__ C, float* __restrict__ xg, float* __restrict__ xs,
    int M, int N, int K) {
    extern __shared__ uint32_t dynsm[];
    uint32_t sbase = (uint32_t)__cvta_generic_to_shared(dynsm);
    int tid = threadIdx.x, lane = tid & 31, wid = tid >> 5;
    int g = lane >> 2, tig = lane & 3;
    int wm = wid >> 1, wn = wid & 1;
    int bn = blockIdx.x * 128, bm = blockIdx.y * 128;
    float acc[2][8][4] = {};
    int KT = K >> 5;

    auto copy = [&](int kt, int s) {
        int k0 = kt << 5;
        #pragma unroll
        for (int i = 0; i < 4; i++) {
            int idx = tid + i*256;
            int row = idx >> 3, c4 = idx & 7;
            cpa16(sbase + (s*STAGE_W + row*36 + c4*4)*4,
                  A + (size_t)(bm + row)*K + k0 + c4*4, 16);
            cpa16(sbase + (s*STAGE_W + BS_OFF + row*40 + c4*4)*4,
                  Bp + ((size_t)kt*N + bn + row)*32 + c4*4, 16);
        }
        cpa_commit();
    };

    copy(0, 0);
    for (int kt = 0; kt < KT; kt++) {
        cpa_wait0();
        __syncthreads();
        if (kt + 1 < KT) copy(kt + 1, (kt + 1) & 1);
        const uint32_t* As = dynsm + (kt & 1)*STAGE_W;
        const uint32_t* Bt = As + BS_OFF;
        #pragma unroll
        for (int ks = 0; ks < 4; ks++) {
            int k = ks * 8;
            uint32_t af[2][4], bf[8][2];
            #pragma unroll
            for (int mt = 0; mt < 2; mt++) {
                int r0 = wm*32 + mt*16;
                af[mt][0] = As[(r0 + g)*36 + k + tig];
                af[mt][1] = As[(r0 + g + 8)*36 + k + tig];
                af[mt][2] = As[(r0 + g)*36 + k + tig + 4];
                af[mt][3] = As[(r0 + g + 8)*36 + k + tig + 4];
            }
            #pragma unroll
            for (int nt = 0; nt < 8; nt++) {
                int c0 = wn*64 + nt*8 + g;
                uint2 bv = *(const uint2*)&Bt[c0*40 + k + tig*2];
                bf[nt][0] = bv.x; bf[nt][1] = bv.y;
            }
            #pragma unroll
            for (int mt = 0; mt < 2; mt++)
                #pragma unroll
                for (int nt = 0; nt < 8; nt++)
                    mma8(acc[mt][nt], af[mt], bf[nt]);
        }
    }

    if (MODE != 4) {
        #pragma unroll
        for (int mt = 0; mt < 2; mt++) {
            int row = bm + wm*32 + mt*16 + g;
            #pragma unroll
            for (int nt = 0; nt < 8; nt++) {
                int col = bn + wn*64 + nt*8 + tig*2;
                float2 v0 = make_float2(acc[mt][nt][0], acc[mt][nt][1]);
                float2 v1 = make_float2(acc[mt][nt][2], acc[mt][nt][3]);
                if (MODE == 1) {
                    float b0 = bias[col], b1v = bias[col + 1];
                    v0.x += b0; v0.y += b1v; v1.x += b0; v1.y += b1v;
                }
                *(float2*)(C + (size_t)row*N + col) = v0;
                *(float2*)(C + (size_t)(row + 8)*N + col) = v1;
            }
        }
    } else {
        float gg = gate[0];
        #pragma unroll
        for (int mt = 0; mt < 2; mt++) {
            int row = bm + wm*32 + mt*16 + g;
            #pragma unroll
            for (int nt = 0; nt < 8; nt++) {
                int col = bn + wn*64 + nt*8 + tig*2;
                float a0 = acc[mt][nt][0], a1 = acc[mt][nt][1];
                float b0 = acc[mt][nt][2], b1 = acc[mt][nt][3];
                float s0 = a0 + a1, s1 = b0 + b1;
                s0 += __shfl_xor_sync(0xffffffffu, s0, 1);
                s0 += __shfl_xor_sync(0xffffffffu, s0, 2);
                s1 += __shfl_xor_sync(0xffffffffu, s1, 1);
                s1 += __shfl_xor_sync(0xffffffffu, s1, 2);
                float m0 = s0 * 0.125f, m1 = s1 * 0.125f;
                float d00 = a0 - m0, d01 = a1 - m0, d10 = b0 - m1, d11 = b1 - m1;
                float q0 = d00*d00 + d01*d01, q1 = d10*d10 + d11*d11;
                q0 += __shfl_xor_sync(0xffffffffu, q0, 1);
                q0 += __shfl_xor_sync(0xffffffffu, q0, 2);
                q1 += __shfl_xor_sync(0xffffffffu, q1, 1);
                q1 += __shfl_xor_sync(0xffffffffu, q1, 2);
                float i0 = rsqrtf(q0*0.125f + 1e-5f), i1 = rsqrtf(q1*0.125f + 1e-5f);
                size_t o0 = (size_t)row*N + col, o1 = (size_t)(row + 8)*N + col;
                float2 x0 = *(float2*)(xg + o0), x1 = *(float2*)(xg + o1);
                x0.x += gg * d00 * i0; x0.y += gg * d01 * i0;
                x1.x += gg * d10 * i1; x1.y += gg * d11 * i1;
                *(float2*)(xg + o0) = x0;
                *(float2*)(xg + o1) = x1;
                *(float2*)(xs + o0) = make_float2(tf32r(x0.x), tf32r(x0.y));
                *(float2*)(xs + o1) = make_float2(tf32r(x1.x), tf32r(x1.y));
            }
        }
    }
}

// ============ pipelined conv3x3 implicit GEMM ============
template<int MODE>   // 0 plain, 1 bias+temb+silu
__global__ __launch_bounds__(256, 2) void k_pconv(
    const float* __restrict__ In, const float* __restrict__ Wp,
    const float* __restrict__ bias, const float* __restrict__ temb,
    const float* __restrict__ gate, float* __restrict__ Out) {
    extern __shared__ uint32_t dynsm[];
    uint32_t sbase = (uint32_t)__cvta_generic_to_shared(dynsm);
    int tid = threadIdx.x, lane = tid & 31, wid = tid >> 5;
    int g = lane >> 2, tig = lane & 3;
    int wm = wid >> 1, wn = wid & 1;
    int bn = blockIdx.x * 128, bm = blockIdx.y * 128;
    float acc[2][8][4] = {};

    int pb[4], pfy[4], pfx[4];
    #pragma unroll
    for (int i = 0; i < 4; i++) {
        int p = bm + ((tid + i*256) >> 3);
        pb[i] = p >> 14; pfy[i] = (p >> 8) & 63; pfx[i] = p & 255;
    }

    auto copy = [&](int kt, int s) {
        int k0 = kt << 5;
        int kyx = k0 >> 8, ci0 = k0 & 255;
        int ky = kyx / 3, kx = kyx - ky*3;
        #pragma unroll
        for (int i = 0; i < 4; i++) {
            int idx = tid + i*256;
            int row = idx >> 3, c4 = idx & 7;
            int fy2 = pfy[i] + ky - 1, fx2 = pfx[i] + kx - 1;
            bool v = ((unsigned)fy2 < 64u) && ((unsigned)fx2 < 256u);
            cpa16(sbase + (s*STAGE_W + row*36 + c4*4)*4,
                  In + (((size_t)(pb[i]*64 + (v?fy2:0)))*256 + (v?fx2:0))*256 + ci0 + c4*4,
                  v ? 16 : 0);
            cpa16(sbase + (s*STAGE_W + BS_OFF + row*40 + c4*4)*4,
                  Wp + ((size_t)kt*256 + bn + row)*32 + c4*4, 16);
        }
        cpa_commit();
    };

    copy(0, 0);
    for (int kt = 0; kt < 72; kt++) {
        cpa_wait0();
        __syncthreads();
        if (kt + 1 < 72) copy(kt + 1, (kt + 1) & 1);
        const uint32_t* As = dynsm + (kt & 1)*STAGE_W;
        const uint32_t* Bt = As + BS_OFF;
        #pragma unroll
        for (int ks = 0; ks < 4; ks++) {
            int k = ks * 8;
            uint32_t af[2][4], bf[8][2];
            #pragma unroll
            for (int mt = 0; mt < 2; mt++) {
                int r0 = wm*32 + mt*16;
                af[mt][0] = As[(r0 + g)*36 + k + tig];
                af[mt][1] = As[(r0 + g + 8)*36 + k + tig];
                af[mt][2] = As[(r0 + g)*36 + k + tig + 4];
                af[mt][3] = As[(r0 + g + 8)*36 + k + tig + 4];
            }
            #pragma unroll
            for (int nt = 0; nt < 8; nt++) {
                int c0 = wn*64 + nt*8 + g;
                uint2 bv = *(const uint2*)&Bt[c0*40 + k + tig*2];
                bf[nt][0] = bv.x; bf[nt][1] = bv.y;
            }
            #pragma unroll
            for (int mt = 0; mt < 2; mt++)
                #pragma unroll
                for (int nt = 0; nt < 8; nt++)
                    mma8(acc[mt][nt], af[mt], bf[nt]);
        }
    }
    float gd = (MODE == 1) ? gate[0] : 0.f;
    #pragma unroll
    for (int mt = 0; mt < 2; mt++) {
        int row = bm + wm*32 + mt*16 + g;
        int bidx = row >> 14;
        #pragma unroll
        for (int nt = 0; nt < 8; nt++) {
            int col = bn + wn*64 + nt*8 + tig*2;
            float v[4] = {acc[mt][nt][0], acc[mt][nt][1], acc[mt][nt][2], acc[mt][nt][3]};
            if (MODE == 1) {
                float a0 = bias[col]     + gd * temb[bidx*256 + col];
                float a1 = bias[col + 1] + gd * temb[bidx*256 + col + 1];
                v[0] += a0; v[1] += a1; v[2] += a0; v[3] += a1;
                #pragma unroll
                for (int j = 0; j < 4; j++) v[j] = v[j] / (1.f + __expf(-v[j]));
            }
            *(float2*)(Out + (size_t)row*256 + col) = make_float2(v[0], v[1]);
            *(float2*)(Out + (size_t)(row + 8)*256 + col) = make_float2(v[2], v[3]);
        }
    }
}

// ---------------- merged weight prepack (single launch) ----------------
__device__ __forceinline__ void prep_gemm(const float* __restrict__ W, float* __restrict__ P,
                                          int NP, int coff, int srcN, int li) {
    int pos = li & 31;
    int rest = li >> 5;
    int n = rest % NP;
    int kt = rest / NP;
    int k = kt*32 + kOfPos(pos);
    P[li] = tf32r(W[(size_t)k * srcN + coff + n]);
}
__device__ __forceinline__ void prep_conv(const float* __restrict__ w, float* __restrict__ P, int li) {
    int pos = li & 31;
    int rest = li >> 5;
    int co = rest & 255;
    int kt = rest >> 8;
    int k = kt*32 + kOfPos(pos);
    int kyx = k >> 8, ci = k & 255;
    P[li] = tf32r(w[(size_t)co * 2304 + ci * 9 + kyx]);
}
__global__ void k_prep_all(
    const float* __restrict__ w1, const float* __restrict__ w2,
    const float* __restrict__ qkv2w, const float* __restrict__ out2w,
    const float* __restrict__ qkv3w, const float* __restrict__ out3w,
    const float* __restrict__ lsaqw, const float* __restrict__ lsaow,
    float* wt1, float* wt2, float* wq2, float* wo2, float* wq3kv, float* wq3q,
    float* wo3, float* wq4, float* wo4) {
    int idx = blockIdx.x * 256 + threadIdx.x;
    if      (idx < 589824)  prep_conv(w1, wt1, idx);
    else if (idx < 1179648) prep_conv(w2, wt2, idx - 589824);
    else if (idx < 1376256) prep_gemm(qkv2w, wq2, 768, 0, 768, idx - 1179648);
    else if (idx < 1441792) prep_gemm(out2w, wo2, 256, 0, 256, idx - 1376256);
    else if (idx < 1572864) prep_gemm(qkv3w, wq3kv, 512, 256, 768, idx - 1441792);
    else if (idx < 1638400) prep_gemm(qkv3w, wq3q, 256, 0, 768, idx - 1572864);
    else if (idx < 1703936) prep_gemm(out3w, wo3, 256, 0, 256, idx - 1638400);
    else if (idx < 1900544) prep_gemm(lsaqw, wq4, 768, 0, 768, idx - 1703936);
    else if (idx < 1966080) prep_gemm(lsaow, wo4, 256, 0, 256, idx - 1900544);
}

// ---------------- transposes ----------------
__global__ void k_nchw_to_nhwc(const float* __restrict__ in, float* __restrict__ out) {
    __shared__ float tile[32][33];
    int bfq = blockIdx.z, b = bfq >> 6, fq = bfq & 63;
    int t0 = blockIdx.x * 32, c0 = blockIdx.y * 32;
    for (int r = threadIdx.y; r < 32; r += 8)
        tile[r][threadIdx.x] = in[(((size_t)b*256 + c0 + r)*64 + fq)*256 + t0 + threadIdx.x];
    __syncthreads();
    for (int r = threadIdx.y; r < 32; r += 8)
        out[((size_t)bfq*256 + t0 + r)*256 + c0 + threadIdx.x] = tile[threadIdx.x][r];
}

__global__ void k_nhwc_to_nchw_add(const float* __restrict__ xa, const float* __restrict__ xb,
                                   float* __restrict__ out) {
    __shared__ float tile[32][33];
    int bfq = blockIdx.z, b = bfq >> 6, fq = bfq & 63;
    int t0 = blockIdx.x * 32, c0 = blockIdx.y * 32;
    for (int r = threadIdx.y; r < 32; r += 8) {
        size_t p = ((size_t)bfq*256 + t0 + r)*256 + c0 + threadIdx.x;
        tile[r][threadIdx.x] = xa[p] + xb[p];
    }
    __syncthreads();
    for (int r = threadIdx.y; r < 32; r += 8)
        out[(((size_t)b*256 + c0 + r)*64 + fq)*256 + t0 + threadIdx.x] = tile[threadIdx.x][r];
}

// ---------------- GroupNorm per (b, g) ----------------
template<bool ROUND>
__global__ void k_gn_bg(const float* __restrict__ in, float* __restrict__ out, float eps) {
    __shared__ float rs[64];
    int b = blockIdx.x >> 5, g = blockIdx.x & 31;
    const float* base = in  + (size_t)b*16384*256 + g*8;
    float*       ob   = out + (size_t)b*16384*256 + g*8;
    float s = 0.f, s2 = 0.f;
    for (int i = threadIdx.x; i < 16384; i += 256) {
        const float4* r = (const float4*)(base + (size_t)i*256);
        float4 a = r[0], c = r[1];
        s  += a.x+a.y+a.z+a.w + c.x+c.y+c.z+c.w;
        s2 += a.x*a.x+a.y*a.y+a.z*a.z+a.w*a.w + c.x*c.x+c.y*c.y+c.z*c.z+c.w*c.w;
    }
    int lane = threadIdx.x & 31, w = threadIdx.x >> 5;
    #pragma unroll
    for (int o = 16; o; o >>= 1) {
        s  += __shfl_down_sync(0xffffffffu, s,  o);
        s2 += __shfl_down_sync(0xffffffffu, s2, o);
    }
    if (lane == 0) { rs[w] = s; rs[32 + w] = s2; }
    __syncthreads();
    if (threadIdx.x == 0) {
        float S = 0.f, S2 = 0.f;
        for (int i = 0; i < 8; i++) { S += rs[i]; S2 += rs[32 + i]; }
        rs[0] = S; rs[32] = S2;
    }
    __syncthreads();
    float mean = rs[0] * (1.f/131072.f);
    float var  = rs[32] * (1.f/131072.f) - mean*mean;
    float inv  = rsqrtf(var + eps);
    for (int i = threadIdx.x; i < 16384; i += 256) {
        const float4* r = (const float4*)(base + (size_t)i*256);
        float4 a = r[0], c = r[1];
        a.x = (a.x-mean)*inv; a.y = (a.y-mean)*inv; a.z = (a.z-mean)*inv; a.w = (a.w-mean)*inv;
        c.x = (c.x-mean)*inv; c.y = (c.y-mean)*inv; c.z = (c.z-mean)*inv; c.w = (c.w-mean)*inv;
        if (ROUND) {
            a.x = tf32r(a.x); a.y = tf32r(a.y); a.z = tf32r(a.z); a.w = tf32r(a.w);
            c.x = tf32r(c.x); c.y = tf32r(c.y); c.z = tf32r(c.z); c.w = tf32r(c.w);
        }
        float4* o4 = (float4*)(ob + (size_t)i*256);
        o4[0] = a; o4[1] = c;
    }
}

// ---------------- fused GN(h2) + x += gres*hn; h2 <- tf32 shadow of new x --------
__global__ void k_gn_axpy(float* __restrict__ h2, float* __restrict__ x,
                          const float* __restrict__ gate, float eps) {
    __shared__ float rs[64];
    int b = blockIdx.x >> 5, g = blockIdx.x & 31;
    float* hb = h2 + (size_t)b*16384*256 + g*8;
    float* xb = x  + (size_t)b*16384*256 + g*8;
    float s = 0.f, s2 = 0.f;
    for (int i = threadIdx.x; i < 16384; i += 256) {
        const float4* r = (const float4*)(hb + (size_t)i*256);
        float4 a = r[0], c = r[1];
        s  += a.x+a.y+a.z+a.w + c.x+c.y+c.z+c.w;
        s2 += a.x*a.x+a.y*a.y+a.z*a.z+a.w*a.w + c.x*c.x+c.y*c.y+c.z*c.z+c.w*c.w;
    }
    int lane = threadIdx.x & 31, w = threadIdx.x >> 5;
    #pragma unroll
    for (int o = 16; o; o >>= 1) {
        s  += __shfl_down_sync(0xffffffffu, s,  o);
        s2 += __shfl_down_sync(0xffffffffu, s2, o);
    }
    if (lane == 0) { rs[w] = s; rs[32 + w] = s2; }
    __syncthreads();
    if (threadIdx.x == 0) {
        float S = 0.f, S2 = 0.f;
        for (int i = 0; i < 8; i++) { S += rs[i]; S2 += rs[32 + i]; }
        rs[0] = S; rs[32] = S2;
    }
    __syncthreads();
    float mean = rs[0] * (1.f/131072.f);
    float var  = rs[32] * (1.f/131072.f) - mean*mean;
    float inv  = rsqrtf(var + eps);
    float gg = gate[0];
    for (int i = threadIdx.x; i < 16384; i += 256) {
        float4* hr = (float4*)(hb + (size_t)i*256);
        float4* xr = (float4*)(xb + (size_t)i*256);
        float4 a = hr[0], c = hr[1];
        float4 xa = xr[0], xc = xr[1];
        xa.x += gg*(a.x-mean)*inv; xa.y += gg*(a.y-mean)*inv;
        xa.z += gg*(a.z-mean)*inv; xa.w += gg*(a.w-mean)*inv;
        xc.x += gg*(c.x-mean)*inv; xc.y += gg*(c.y-mean)*inv;
        xc.z += gg*(c.z-mean)*inv; xc.w += gg*(c.w-mean)*inv;
        xr[0] = xa; xr[1] = xc;
        hr[0] = make_float4(tf32r(xa.x), tf32r(xa.y), tf32r(xa.z), tf32r(xa.w));
        hr[1] = make_float4(tf32r(xc.x), tf32r(xc.y), tf32r(xc.z), tf32r(xc.w));
    }
}

// ---------------- layer2 attention over Fq per (b,t,h); tf32-rounded out ----------
__global__ void k_attn_freq(const float* __restrict__ qkv, float* __restrict__ y) {
    __shared__ float q[64][33], kk[64][33], v[64][33];
    __shared__ float S[64][65];
    int bt = blockIdx.x, h = blockIdx.y;
    int b = bt >> 8, t = bt & 255;
    int tid = threadIdx.x;
    for (int i = tid; i < 2048; i += 128) {
        int fq = i >> 5, d = i & 31;
        size_t base = ((size_t)((b*64 + fq)*256 + t))*768 + h*32 + d;
        q[fq][d]  = qkv[base];
        kk[fq][d] = qkv[base + 256];
        v[fq][d]  = qkv[base + 512];
    }
    __syncthreads();
    const float scale = 0.17677669529663687f;
    for (int i = tid; i < 4096; i += 128) {
        int L = i >> 6, l = i & 63;
        float s = 0.f;
        #pragma unroll
        for (int d = 0; d < 32; d++) s += q[L][d] * kk[l][d];
        S[L][l] = s * scale;
    }
    __syncthreads();
    if (tid < 64) {
        float m = -1e30f;
        for (int l = 0; l < 64; l++) m = fmaxf(m, S[tid][l]);
        float su = 0.f;
        for (int l = 0; l < 64; l++) { float e = __expf(S[tid][l] - m); S[tid][l] = e; su += e; }
        float r = 1.f / su;
        for (int l = 0; l < 64; l++) S[tid][l] *= r;
    }
    __syncthreads();
    for (int i = tid; i < 2048; i += 128) {
        int L = i >> 5, d = i & 31;
        float s = 0.f;
        #pragma unroll
        for (int l = 0; l < 64; l++) s += S[L][l] * v[l][d];
        y[((size_t)((b*64 + L)*256 + t))*256 + h*32 + d] = tf32r(s);
    }
}

// ---------------- layer3 attention: precomputed q, KV-only buffer [NTOK,512] ----------
__global__ void k_attn_time2(const float* __restrict__ kv, const float* __restrict__ q3,
                             float* __restrict__ yout) {
    __shared__ float qs[32];
    __shared__ float part[8][32];
    __shared__ float prob[256];
    __shared__ float redm[8], reds[8];
    int bfq = blockIdx.x, h = blockIdx.y;
    int tid = threadIdx.x;
    size_t tokbase = (size_t)bfq * 256;
    int d = tid & 31, grp = tid >> 5;
    if (tid < 32) qs[tid] = q3[bfq*256 + h*32 + tid];
    __syncthreads();
    const float* kr = kv + (tokbase + tid)*512 + h*32;
    float sc = 0.f;
    #pragma unroll
    for (int dd = 0; dd < 32; dd++) sc += qs[dd] * kr[dd];
    sc *= 0.17677669529663687f;
    float m = sc;
    #pragma unroll
    for (int o = 16; o; o >>= 1) m = fmaxf(m, __shfl_xor_sync(0xffffffffu, m, o));
    if ((tid & 31) == 0) redm[grp] = m;
    __syncthreads();
    float M = redm[0];
    #pragma unroll
    for (int g = 1; g < 8; g++) M = fmaxf(M, redm[g]);
    float e = __expf(sc - M);
    float su = e;
    #pragma unroll
    for (int o = 16; o; o >>= 1) su += __shfl_xor_sync(0xffffffffu, su, o);
    if ((tid & 31) == 0) reds[grp] = su;
    __syncthreads();
    float Ssum = 0.f;
    #pragma unroll
    for (int g = 0; g < 8; g++) Ssum += reds[g];
    prob[tid] = e / Ssum;
    __syncthreads();
    float acc = 0.f;
    for (int t = grp; t < 256; t += 8)
        acc += prob[t] * kv[(tokbase + t)*512 + 256 + h*32 + d];
    part[grp][d] = acc;
    __syncthreads();
    if (tid < 32) {
        float ss = 0.f;
        #pragma unroll
        for (int g = 0; g < 8; g++) ss += part[g][tid];
        yout[(size_t)bfq*256 + h*32 + tid] = tf32r(ss);
    }
}

// ---------------- mean over T of tf32 shadow: qm[bfq, c] ----------------
__global__ void k_meanx(const float* __restrict__ xs, float* __restrict__ qm) {
    int bfq = blockIdx.x, c = threadIdx.x;
    const float* p = xs + (size_t)bfq * 65536 + c;
    float s = 0.f;
    for (int t = 0; t < 256; t++) s += p[(size_t)t * 256];
    qm[bfq*256 + c] = tf32r(s * (1.f/256.f));
}

// ---------------- layer3 epilogue ----------------
__global__ void k_gn_bcast_add(const float* __restrict__ yv, float* __restrict__ x,
                               const float* __restrict__ gate) {
    __shared__ float yn[256];
    int bfq = blockIdx.x, tid = threadIdx.x;
    if (tid < 32) {
        const float* r = yv + bfq*256 + tid*8;
        float vals[8];
        #pragma unroll
        for (int j = 0; j < 8; j++) vals[j] = r[j];
        float m = 0.f;
        #pragma unroll
        for (int j = 0; j < 8; j++) m += vals[j];
        m *= 0.125f;
        float var = 0.f;
        #pragma unroll
        for (int j = 0; j < 8; j++) { float dd = vals[j] - m; var += dd * dd; }
        var *= 0.125f;
        float inv = rsqrtf(var + 1e-5f);
        #pragma unroll
        for (int j = 0; j < 8; j++) yn[tid*8 + j] = (vals[j] - m) * inv;
    }
    __syncthreads();
    float add = gate[0] * yn[tid];
    float* xp = x + (size_t)bfq * 65536 + tid;
    for (int t = 0; t < 256; t++) xp[(size_t)t * 256] += add;
}

// ---------------- layer4 LSA; tf32-rounded out ----------------
__global__ void k_attn_lsa(const float* __restrict__ qkv, float* __restrict__ y) {
    __shared__ float q[16][33], kk[16][33], v[16][33];
    __shared__ float S[16][17];
    int blk = blockIdx.x;
    size_t p0 = (size_t)(blk >> 4) * 256 + (blk & 15) * 16;
    int tid = threadIdx.x;
    int qi = tid >> 4, kj = tid & 15;
    const float scale = 0.17677669529663687f;
    for (int h = 0; h < 8; h++) {
        for (int i = tid; i < 512; i += 256) {
            int r = i >> 5, d = i & 31;
            size_t a = (p0 + r)*768 + h*32 + d;
            q[r][d] = qkv[a]; kk[r][d] = qkv[a + 256]; v[r][d] = qkv[a + 512];
        }
        __syncthreads();
        float s = 0.f;
        #pragma unroll
        for (int d = 0; d < 32; d++) s += q[qi][d] * kk[kj][d];
        S[qi][kj] = s * scale;
        __syncthreads();
        if (tid < 16) {
            float m = -1e30f;
            for (int j = 0; j < 16; j++) m = fmaxf(m, S[tid][j]);
            float su = 0.f;
            for (int j = 0; j < 16; j++) { float e = __expf(S[tid][j] - m); S[tid][j] = e; su += e; }
            float r = 1.f / su;
            for (int j = 0; j < 16; j++) S[tid][j] *= r;
        }
        __syncthreads();
        for (int i = tid; i < 512; i += 256) {
            int r = i >> 5, d = i & 31;
            float s2 = 0.f;
            #pragma unroll
            for (int j = 0; j < 16; j++) s2 += S[r][j] * v[j][d];
            y[(p0 + r)*256 + h*32 + d] = tf32r(s2);
        }
        __syncthreads();
    }
}

// =====================================================================================
extern "C" void kernel_launch(void* const* d_in, const int* in_sizes, int n_in,
                              void* d_out, int out_size) {
    const float* x     = (const float*)d_in[0];
    const float* temb  = (const float*)d_in[1];
    const float* w1    = (const float*)d_in[2];
    const float* b1    = (const float*)d_in[3];
    const float* w2    = (const float*)d_in[4];
    const float* gdiff = (const float*)d_in[5];
    const float* gres  = (const float*)d_in[6];
    const float* g2    = (const float*)d_in[7];
    const float* g3    = (const float*)d_in[8];
    const float* qkv2w = (const float*)d_in[9];
    const float* qkv2b = (const float*)d_in[10];
    const float* out2w = (const float*)d_in[11];
    const float* qkv3w = (const float*)d_in[12];
    const float* qkv3b = (const float*)d_in[13];
    const float* out3w = (const float*)d_in[14];
    const float* lsaqw = (const float*)d_in[15];
    const float* lsaow = (const float*)d_in[16];
    float* out = (float*)d_out;

    float *px, *ph, *ph2, *py, *pqkv, *pa3, *pa3b, *pqm, *pq3;
    float *pwt, *pwt2, *pwq2, *pwo2, *pwq3, *pwq3q, *pwo3, *pwq4, *pwo4;
    cudaGetSymbolAddress((void**)&px,    g_x);
    cudaGetSymbolAddress((void**)&ph,    g_h);
    cudaGetSymbolAddress((void**)&ph2,   g_h2);
    cudaGetSymbolAddress((void**)&py,    g_y);
    cudaGetSymbolAddress((void**)&pqkv,  g_qkv);
    cudaGetSymbolAddress((void**)&pa3,   g_a3);
    cudaGetSymbolAddress((void**)&pa3b,  g_a3b);
    cudaGetSymbolAddress((void**)&pqm,   g_qm);
    cudaGetSymbolAddress((void**)&pq3,   g_q3);
    cudaGetSymbolAddress((void**)&pwt,   g_wt);
    cudaGetSymbolAddress((void**)&pwt2,  g_wt2);
    cudaGetSymbolAddress((void**)&pwq2,  g_wq2);
    cudaGetSymbolAddress((void**)&pwo2,  g_wo2);
    cudaGetSymbolAddress((void**)&pwq3,  g_wq3);
    cudaGetSymbolAddress((void**)&pwq3q, g_wq3q);
    cudaGetSymbolAddress((void**)&pwo3,  g_wo3);
    cudaGetSymbolAddress((void**)&pwq4,  g_wq4);
    cudaGetSymbolAddress((void**)&pwo4,  g_wo4);

    cudaFuncSetAttribute(k_pgemm<0>, cudaFuncAttributeMaxDynamicSharedMemorySize, SMEM_MM);
    cudaFuncSetAttribute(k_pgemm<1>, cudaFuncAttributeMaxDynamicSharedMemorySize, SMEM_MM);
    cudaFuncSetAttribute(k_pgemm<4>, cudaFuncAttributeMaxDynamicSharedMemorySize, SMEM_MM);
    cudaFuncSetAttribute(k_pconv<0>, cudaFuncAttributeMaxDynamicSharedMemorySize, SMEM_MM);
    cudaFuncSetAttribute(k_pconv<1>, cudaFuncAttributeMaxDynamicSharedMemorySize, SMEM_MM);

    dim3 tb32(32, 8);

    // [0] single merged prepack
    k_prep_all<<<7680, 256>>>(w1, w2, qkv2w, out2w, qkv3w, out3w, lsaqw, lsaow,
                              pwt, pwt2, pwq2, pwo2, pwq3, pwq3q, pwo3, pwq4, pwo4);
    // [1]
    k_nchw_to_nhwc<<<dim3(8, 8, 256), tb32>>>(x, px);

    // ---- Residual block ----  [2..6]
    k_gn_bg<true><<<128, 256>>>(px, ph, 1e-6f);
    k_pconv<1><<<dim3(2, 512), 256, SMEM_MM>>>(ph, pwt, b1, temb, gdiff, ph2);
    k_gn_bg<true><<<128, 256>>>(ph2, ph, 1e-6f);
    k_pconv<0><<<dim3(2, 512), 256, SMEM_MM>>>(ph, pwt2, nullptr, nullptr, nullptr, ph2);  // launch #5: profiled
    k_gn_axpy<<<128, 256>>>(ph2, px, gres, 1e-6f);    // px updated, ph2 = tf32 shadow

    // ---- layer2 ----
    k_pgemm<1><<<dim3(6, 512), 256, SMEM_MM>>>(ph2, pwq2, qkv2b, nullptr, pqkv,
                                               nullptr, nullptr, NTOK, 768, 256);
    k_attn_freq<<<dim3(1024, 8), 128>>>(pqkv, py);
    k_pgemm<4><<<dim3(2, 512), 256, SMEM_MM>>>(py, pwo2, nullptr, g2, ph,
                                               px, ph2, NTOK, 256, 256);

    // ---- layer3 (q via mean-then-project) ----
    k_pgemm<1><<<dim3(4, 512), 256, SMEM_MM>>>(ph2, pwq3, qkv3b + 256, nullptr, pqkv,
                                               nullptr, nullptr, NTOK, 512, 256);
    k_meanx<<<256, 256>>>(ph2, pqm);
    k_pgemm<1><<<dim3(2, 2), 256, SMEM_MM>>>(pqm, pwq3q, qkv3b, nullptr, pq3,
                                             nullptr, nullptr, 256, 256, 256);
    k_attn_time2<<<dim3(256, 8), 256>>>(pqkv, pq3, pa3);
    k_pgemm<0><<<dim3(2, 2), 256, SMEM_MM>>>(pa3, pwo3, nullptr, nullptr, pa3b,
                                             nullptr, nullptr, 256, 256, 256);
    k_gn_bcast_add<<<256, 256>>>(pa3b, px, g3);

    // ---- layer4 ----
    k_gn_bg<true><<<128, 256>>>(px, ph, 1e-5f);
    k_pgemm<0><<<dim3(6, 512), 256, SMEM_MM>>>(ph, pwq4, nullptr, nullptr, pqkv,
                                               nullptr, nullptr, NTOK, 768, 256);
    k_attn_lsa<<<4096, 256>>>(pqkv, py);
    k_pgemm<0><<<dim3(2, 512), 256, SMEM_MM>>>(py, pwo4, nullptr, nullptr, ph,
                                               nullptr, nullptr, NTOK, 256, 256);

    k_nhwc_to_nchw_add<<<dim3(8, 8, 256), tb32>>>(px, ph, out);
}

// round 12
// speedup vs baseline: 1.1114x; 1.0564x over previous
#include <cuda_runtime.h>
#include <cstdint>
#include <math.h>

// B=4, C=256, Fq=64, T=256, HEADS=8, Dh=32, GROUPS=32, WIN=16
#define NTOK   65536
#define ELEMS  16777216

// ---------------- scratch ----------------
__device__ float g_x[ELEMS];
__device__ float g_h[ELEMS];
__device__ float g_h2[ELEMS];       // tf32 shadow of g_x
__device__ float g_y[ELEMS];
__device__ float g_qkv[3*ELEMS];
__device__ float g_a3[65536];
__device__ float g_a3b[65536];
__device__ float g_qm[65536];
__device__ float g_q3[65536];
__device__ float g_wt[589824];
__device__ float g_wt2[589824];
__device__ float g_wq2[196608];
__device__ float g_wo2[65536];
__device__ float g_wq3[131072];     // KV-only (N=512)
__device__ float g_wq3q[65536];     // q-only (N=256)
__device__ float g_wo3[65536];
__device__ float g_wq4[196608];
__device__ float g_wo4[65536];

// ---------------- tf32 helpers ----------------
__device__ __forceinline__ uint32_t f2tf(float x) {
    uint32_t r; asm("cvt.rna.tf32.f32 %0, %1;" : "=r"(r) : "f"(x)); return r;
}
__device__ __forceinline__ float tf32r(float x) { return __uint_as_float(f2tf(x)); }
__device__ __forceinline__ void mma8(float* d, const uint32_t* a, const uint32_t* b) {
    asm volatile("mma.sync.aligned.m16n8k8.row.col.f32.tf32.tf32.f32 "
        "{%0,%1,%2,%3}, {%4,%5,%6,%7}, {%8,%9}, {%0,%1,%2,%3};"
        : "+f"(d[0]), "+f"(d[1]), "+f"(d[2]), "+f"(d[3])
        : "r"(a[0]), "r"(a[1]), "r"(a[2]), "r"(a[3]), "r"(b[0]), "r"(b[1]));
}
__device__ __forceinline__ void cpa16(uint32_t dst, const void* src, int sz) {
    asm volatile("cp.async.cg.shared.global [%0], [%1], 16, %2;" :: "r"(dst), "l"(src), "r"(sz));
}
__device__ __forceinline__ void cpa_commit() { asm volatile("cp.async.commit_group;"); }
__device__ __forceinline__ void cpa_wait0()  { asm volatile("cp.async.wait_group 0;"); }
__device__ __forceinline__ void cpa_wait1()  { asm volatile("cp.async.wait_group 1;"); }

// packed-pos -> local k within a 32-k tile
__device__ __forceinline__ int kOfPos(int pos) {
    int ks = pos >> 3, rem = pos & 7;
    return ks*8 + (rem >> 1) + 4*(rem & 1);
}

// smem: stage = A[128][32] (XOR 4*(row&7)) + B[128][32] (XOR 8*(n&3)); 3 stages
#define STAGE_W 8192
#define BS_OFF  4096
#define SMEM_MM (3*STAGE_W*4)   // 98304 B -> 2 CTA/SM

// ============ pipelined tf32 GEMM: 128x128 tile, Kt=32, cp.async 3-stage ============
// MODE: 0 plain, 1 +bias, 4 fused per-token GN(8ch) + x += gate*yn + tf32 shadow
template<int MODE>
__global__ __launch_bounds__(256, 2) void k_pgemm(
    const float* __restrict__ A, const float* __restrict__ Bp,
    const float* __restrict__ bias, const float* __restrict__ gate,
    float* __restrict__ C, float* __restrict__ xg, float* __restrict__ xs,
    int M, int N, int K) {
    extern __shared__ uint32_t dynsm[];
    uint32_t sbase = (uint32_t)__cvta_generic_to_shared(dynsm);
    int tid = threadIdx.x, lane = tid & 31, wid = tid >> 5;
    int g = lane >> 2, tig = lane & 3;
    int wm = wid >> 1, wn = wid & 1;
    int bn = blockIdx.x * 128, bm = blockIdx.y * 128;
    float acc[2][8][4] = {};
    int KT = K >> 5;

    auto copy = [&](int kt, int s) {
        int k0 = kt << 5;
        #pragma unroll
        for (int i = 0; i < 4; i++) {
            int idx = tid + i*256;
            int row = idx >> 3, c4 = idx & 7;
            cpa16(sbase + (s*STAGE_W + row*32 + ((c4*4) ^ ((row & 7)*4)))*4,
                  A + (size_t)(bm + row)*K + k0 + c4*4, 16);
            cpa16(sbase + (s*STAGE_W + BS_OFF + row*32 + ((c4*4) ^ ((row & 3)*8)))*4,
                  Bp + ((size_t)kt*N + bn + row)*32 + c4*4, 16);
        }
        cpa_commit();
    };

    copy(0, 0);
    if (KT > 1) copy(1, 1);
    for (int kt = 0; kt < KT; kt++) {
        if (kt + 1 < KT) cpa_wait1(); else cpa_wait0();
        __syncthreads();
        if (kt + 2 < KT) copy(kt + 2, (kt + 2) % 3);
        const uint32_t* As = dynsm + (kt % 3)*STAGE_W;
        const uint32_t* Bt = As + BS_OFF;
        #pragma unroll
        for (int ks = 0; ks < 4; ks++) {
            int k = ks * 8;
            uint32_t af[2][4], bf[8][2];
            int sw = g*4;
            #pragma unroll
            for (int mt = 0; mt < 2; mt++) {
                int r1 = wm*32 + mt*16 + g, r2 = r1 + 8;
                af[mt][0] = As[r1*32 + ((k + tig) ^ sw)];
                af[mt][1] = As[r2*32 + ((k + tig) ^ sw)];
                af[mt][2] = As[r1*32 + ((k + tig + 4) ^ sw)];
                af[mt][3] = As[r2*32 + ((k + tig + 4) ^ sw)];
            }
            #pragma unroll
            for (int nt = 0; nt < 8; nt++) {
                int c0 = wn*64 + nt*8 + g;
                uint2 bv = *(const uint2*)&Bt[c0*32 + ((k + tig*2) ^ ((c0 & 3)*8))];
                bf[nt][0] = bv.x; bf[nt][1] = bv.y;
            }
            #pragma unroll
            for (int mt = 0; mt < 2; mt++)
                #pragma unroll
                for (int nt = 0; nt < 8; nt++)
                    mma8(acc[mt][nt], af[mt], bf[nt]);
        }
    }

    if (MODE != 4) {
        #pragma unroll
        for (int mt = 0; mt < 2; mt++) {
            int row = bm + wm*32 + mt*16 + g;
            #pragma unroll
            for (int nt = 0; nt < 8; nt++) {
                int col = bn + wn*64 + nt*8 + tig*2;
                float2 v0 = make_float2(acc[mt][nt][0], acc[mt][nt][1]);
                float2 v1 = make_float2(acc[mt][nt][2], acc[mt][nt][3]);
                if (MODE == 1) {
                    float b0 = bias[col], b1v = bias[col + 1];
                    v0.x += b0; v0.y += b1v; v1.x += b0; v1.y += b1v;
                }
                *(float2*)(C + (size_t)row*N + col) = v0;
                *(float2*)(C + (size_t)(row + 8)*N + col) = v1;
            }
        }
    } else {
        float gg = gate[0];
        #pragma unroll
        for (int mt = 0; mt < 2; mt++) {
            int row = bm + wm*32 + mt*16 + g;
            #pragma unroll
            for (int nt = 0; nt < 8; nt++) {
                int col = bn + wn*64 + nt*8 + tig*2;
                float a0 = acc[mt][nt][0], a1 = acc[mt][nt][1];
                float b0 = acc[mt][nt][2], b1 = acc[mt][nt][3];
                float s0 = a0 + a1, s1 = b0 + b1;
                s0 += __shfl_xor_sync(0xffffffffu, s0, 1);
                s0 += __shfl_xor_sync(0xffffffffu, s0, 2);
                s1 += __shfl_xor_sync(0xffffffffu, s1, 1);
                s1 += __shfl_xor_sync(0xffffffffu, s1, 2);
                float m0 = s0 * 0.125f, m1 = s1 * 0.125f;
                float d00 = a0 - m0, d01 = a1 - m0, d10 = b0 - m1, d11 = b1 - m1;
                float q0 = d00*d00 + d01*d01, q1 = d10*d10 + d11*d11;
                q0 += __shfl_xor_sync(0xffffffffu, q0, 1);
                q0 += __shfl_xor_sync(0xffffffffu, q0, 2);
                q1 += __shfl_xor_sync(0xffffffffu, q1, 1);
                q1 += __shfl_xor_sync(0xffffffffu, q1, 2);
                float i0 = rsqrtf(q0*0.125f + 1e-5f), i1 = rsqrtf(q1*0.125f + 1e-5f);
                size_t o0 = (size_t)row*N + col, o1 = (size_t)(row + 8)*N + col;
                float2 x0 = *(float2*)(xg + o0), x1 = *(float2*)(xg + o1);
                x0.x += gg * d00 * i0; x0.y += gg * d01 * i0;
                x1.x += gg * d10 * i1; x1.y += gg * d11 * i1;
                *(float2*)(xg + o0) = x0;
                *(float2*)(xg + o1) = x1;
                *(float2*)(xs + o0) = make_float2(tf32r(x0.x), tf32r(x0.y));
                *(float2*)(xs + o1) = make_float2(tf32r(x1.x), tf32r(x1.y));
            }
        }
    }
}

// ============ pipelined conv3x3 implicit GEMM, 3-stage ============
template<int MODE>   // 0 plain, 1 bias+temb+silu
__global__ __launch_bounds__(256, 2) void k_pconv(
    const float* __restrict__ In, const float* __restrict__ Wp,
    const float* __restrict__ bias, const float* __restrict__ temb,
    const float* __restrict__ gate, float* __restrict__ Out) {
    extern __shared__ uint32_t dynsm[];
    uint32_t sbase = (uint32_t)__cvta_generic_to_shared(dynsm);
    int tid = threadIdx.x, lane = tid & 31, wid = tid >> 5;
    int g = lane >> 2, tig = lane & 3;
    int wm = wid >> 1, wn = wid & 1;
    int bn = blockIdx.x * 128, bm = blockIdx.y * 128;
    float acc[2][8][4] = {};

    int pb[4], pfy[4], pfx[4];
    #pragma unroll
    for (int i = 0; i < 4; i++) {
        int p = bm + ((tid + i*256) >> 3);
        pb[i] = p >> 14; pfy[i] = (p >> 8) & 63; pfx[i] = p & 255;
    }

    auto copy = [&](int kt, int s) {
        int k0 = kt << 5;
        int kyx = k0 >> 8, ci0 = k0 & 255;
        int ky = kyx / 3, kx = kyx - ky*3;
        #pragma unroll
        for (int i = 0; i < 4; i++) {
            int idx = tid + i*256;
            int row = idx >> 3, c4 = idx & 7;
            int fy2 = pfy[i] + ky - 1, fx2 = pfx[i] + kx - 1;
            bool v = ((unsigned)fy2 < 64u) && ((unsigned)fx2 < 256u);
            cpa16(sbase + (s*STAGE_W + row*32 + ((c4*4) ^ ((row & 7)*4)))*4,
                  In + (((size_t)(pb[i]*64 + (v?fy2:0)))*256 + (v?fx2:0))*256 + ci0 + c4*4,
                  v ? 16 : 0);
            cpa16(sbase + (s*STAGE_W + BS_OFF + row*32 + ((c4*4) ^ ((row & 3)*8)))*4,
                  Wp + ((size_t)kt*256 + bn + row)*32 + c4*4, 16);
        }
        cpa_commit();
    };

    copy(0, 0); copy(1, 1);
    for (int kt = 0; kt < 72; kt++) {
        if (kt + 1 < 72) cpa_wait1(); else cpa_wait0();
        __syncthreads();
        if (kt + 2 < 72) copy(kt + 2, (kt + 2) % 3);
        const uint32_t* As = dynsm + (kt % 3)*STAGE_W;
        const uint32_t* Bt = As + BS_OFF;
        #pragma unroll
        for (int ks = 0; ks < 4; ks++) {
            int k = ks * 8;
            uint32_t af[2][4], bf[8][2];
            int sw = g*4;
            #pragma unroll
            for (int mt = 0; mt < 2; mt++) {
                int r1 = wm*32 + mt*16 + g, r2 = r1 + 8;
                af[mt][0] = As[r1*32 + ((k + tig) ^ sw)];
                af[mt][1] = As[r2*32 + ((k + tig) ^ sw)];
                af[mt][2] = As[r1*32 + ((k + tig + 4) ^ sw)];
                af[mt][3] = As[r2*32 + ((k + tig + 4) ^ sw)];
            }
            #pragma unroll
            for (int nt = 0; nt < 8; nt++) {
                int c0 = wn*64 + nt*8 + g;
                uint2 bv = *(const uint2*)&Bt[c0*32 + ((k + tig*2) ^ ((c0 & 3)*8))];
                bf[nt][0] = bv.x; bf[nt][1] = bv.y;
            }
            #pragma unroll
            for (int mt = 0; mt < 2; mt++)
                #pragma unroll
                for (int nt = 0; nt < 8; nt++)
                    mma8(acc[mt][nt], af[mt], bf[nt]);
        }
    }
    float gd = (MODE == 1) ? gate[0] : 0.f;
    #pragma unroll
    for (int mt = 0; mt < 2; mt++) {
        int row = bm + wm*32 + mt*16 + g;
        int bidx = row >> 14;
        #pragma unroll
        for (int nt = 0; nt < 8; nt++) {
            int col = bn + wn*64 + nt*8 + tig*2;
            float v[4] = {acc[mt][nt][0], acc[mt][nt][1], acc[mt][nt][2], acc[mt][nt][3]};
            if (MODE == 1) {
                float a0 = bias[col]     + gd * temb[bidx*256 + col];
                float a1 = bias[col + 1] + gd * temb[bidx*256 + col + 1];
                v[0] += a0; v[1] += a1; v[2] += a0; v[3] += a1;
                #pragma unroll
                for (int j = 0; j < 4; j++) v[j] = v[j] / (1.f + __expf(-v[j]));
            }
            *(float2*)(Out + (size_t)row*256 + col) = make_float2(v[0], v[1]);
            *(float2*)(Out + (size_t)(row + 8)*256 + col) = make_float2(v[2], v[3]);
        }
    }
}

// ---------------- merged weight prepack ----------------
__device__ __forceinline__ void prep_gemm(const float* __restrict__ W, float* __restrict__ P,
                                          int NP, int coff, int srcN, int li) {
    int pos = li & 31;
    int rest = li >> 5;
    int n = rest % NP;
    int kt = rest / NP;
    int k = kt*32 + kOfPos(pos);
    P[li] = tf32r(W[(size_t)k * srcN + coff + n]);
}
__device__ __forceinline__ void prep_conv(const float* __restrict__ w, float* __restrict__ P, int li) {
    int pos = li & 31;
    int rest = li >> 5;
    int co = rest & 255;
    int kt = rest >> 8;
    int k = kt*32 + kOfPos(pos);
    int kyx = k >> 8, ci = k & 255;
    P[li] = tf32r(w[(size_t)co * 2304 + ci * 9 + kyx]);
}
__global__ void k_prep_all(
    const float* __restrict__ w1, const float* __restrict__ w2,
    const float* __restrict__ qkv2w, const float* __restrict__ out2w,
    const float* __restrict__ qkv3w, const float* __restrict__ out3w,
    const float* __restrict__ lsaqw, const float* __restrict__ lsaow,
    float* wt1, float* wt2, float* wq2, float* wo2, float* wq3kv, float* wq3q,
    float* wo3, float* wq4, float* wo4) {
    int idx = blockIdx.x * 256 + threadIdx.x;
    if      (idx < 589824)  prep_conv(w1, wt1, idx);
    else if (idx < 1179648) prep_conv(w2, wt2, idx - 589824);
    else if (idx < 1376256) prep_gemm(qkv2w, wq2, 768, 0, 768, idx - 1179648);
    else if (idx < 1441792) prep_gemm(out2w, wo2, 256, 0, 256, idx - 1376256);
    else if (idx < 1572864) prep_gemm(qkv3w, wq3kv, 512, 256, 768, idx - 1441792);
    else if (idx < 1638400) prep_gemm(qkv3w, wq3q, 256, 0, 768, idx - 1572864);
    else if (idx < 1703936) prep_gemm(out3w, wo3, 256, 0, 256, idx - 1638400);
    else if (idx < 1900544) prep_gemm(lsaqw, wq4, 768, 0, 768, idx - 1703936);
    else if (idx < 1966080) prep_gemm(lsaow, wo4, 256, 0, 256, idx - 1900544);
}

// ---------------- transposes ----------------
__global__ void k_nchw_to_nhwc(const float* __restrict__ in, float* __restrict__ out) {
    __shared__ float tile[32][33];
    int bfq = blockIdx.z, b = bfq >> 6, fq = bfq & 63;
    int t0 = blockIdx.x * 32, c0 = blockIdx.y * 32;
    for (int r = threadIdx.y; r < 32; r += 8)
        tile[r][threadIdx.x] = in[(((size_t)b*256 + c0 + r)*64 + fq)*256 + t0 + threadIdx.x];
    __syncthreads();
    for (int r = threadIdx.y; r < 32; r += 8)
        out[((size_t)bfq*256 + t0 + r)*256 + c0 + threadIdx.x] = tile[threadIdx.x][r];
}

__global__ void k_nhwc_to_nchw_add(const float* __restrict__ xa, const float* __restrict__ xb,
                                   float* __restrict__ out) {
    __shared__ float tile[32][33];
    int bfq = blockIdx.z, b = bfq >> 6, fq = bfq & 63;
    int t0 = blockIdx.x * 32, c0 = blockIdx.y * 32;
    for (int r = threadIdx.y; r < 32; r += 8) {
        size_t p = ((size_t)bfq*256 + t0 + r)*256 + c0 + threadIdx.x;
        tile[r][threadIdx.x] = xa[p] + xb[p];
    }
    __syncthreads();
    for (int r = threadIdx.y; r < 32; r += 8)
        out[(((size_t)b*256 + c0 + r)*64 + fq)*256 + t0 + threadIdx.x] = tile[threadIdx.x][r];
}

// ---------------- GroupNorm per (b, g) ----------------
template<bool ROUND>
__global__ void k_gn_bg(const float* __restrict__ in, float* __restrict__ out, float eps) {
    __shared__ float rs[64];
    int b = blockIdx.x >> 5, g = blockIdx.x & 31;
    const float* base = in  + (size_t)b*16384*256 + g*8;
    float*       ob   = out + (size_t)b*16384*256 + g*8;
    float s = 0.f, s2 = 0.f;
    for (int i = threadIdx.x; i < 16384; i += 256) {
        const float4* r = (const float4*)(base + (size_t)i*256);
        float4 a = r[0], c = r[1];
        s  += a.x+a.y+a.z+a.w + c.x+c.y+c.z+c.w;
        s2 += a.x*a.x+a.y*a.y+a.z*a.z+a.w*a.w + c.x*c.x+c.y*c.y+c.z*c.z+c.w*c.w;
    }
    int lane = threadIdx.x & 31, w = threadIdx.x >> 5;
    #pragma unroll
    for (int o = 16; o; o >>= 1) {
        s  += __shfl_down_sync(0xffffffffu, s,  o);
        s2 += __shfl_down_sync(0xffffffffu, s2, o);
    }
    if (lane == 0) { rs[w] = s; rs[32 + w] = s2; }
    __syncthreads();
    if (threadIdx.x == 0) {
        float S = 0.f, S2 = 0.f;
        for (int i = 0; i < 8; i++) { S += rs[i]; S2 += rs[32 + i]; }
        rs[0] = S; rs[32] = S2;
    }
    __syncthreads();
    float mean = rs[0] * (1.f/131072.f);
    float var  = rs[32] * (1.f/131072.f) - mean*mean;
    float inv  = rsqrtf(var + eps);
    for (int i = threadIdx.x; i < 16384; i += 256) {
        const float4* r = (const float4*)(base + (size_t)i*256);
        float4 a = r[0], c = r[1];
        a.x = (a.x-mean)*inv; a.y = (a.y-mean)*inv; a.z = (a.z-mean)*inv; a.w = (a.w-mean)*inv;
        c.x = (c.x-mean)*inv; c.y = (c.y-mean)*inv; c.z = (c.z-mean)*inv; c.w = (c.w-mean)*inv;
        if (ROUND) {
            a.x = tf32r(a.x); a.y = tf32r(a.y); a.z = tf32r(a.z); a.w = tf32r(a.w);
            c.x = tf32r(c.x); c.y = tf32r(c.y); c.z = tf32r(c.z); c.w = tf32r(c.w);
        }
        float4* o4 = (float4*)(ob + (size_t)i*256);
        o4[0] = a; o4[1] = c;
    }
}

// ---------------- fused GN(h2) + x += gres*hn; h2 <- tf32 shadow ----------------
__global__ void k_gn_axpy(float* __restrict__ h2, float* __restrict__ x,
                          const float* __restrict__ gate, float eps) {
    __shared__ float rs[64];
    int b = blockIdx.x >> 5, g = blockIdx.x & 31;
    float* hb = h2 + (size_t)b*16384*256 + g*8;
    float* xb = x  + (size_t)b*16384*256 + g*8;
    float s = 0.f, s2 = 0.f;
    for (int i = threadIdx.x; i < 16384; i += 256) {
        const float4* r = (const float4*)(hb + (size_t)i*256);
        float4 a = r[0], c = r[1];
        s  += a.x+a.y+a.z+a.w + c.x+c.y+c.z+c.w;
        s2 += a.x*a.x+a.y*a.y+a.z*a.z+a.w*a.w + c.x*c.x+c.y*c.y+c.z*c.z+c.w*c.w;
    }
    int lane = threadIdx.x & 31, w = threadIdx.x >> 5;
    #pragma unroll
    for (int o = 16; o; o >>= 1) {
        s  += __shfl_down_sync(0xffffffffu, s,  o);
        s2 += __shfl_down_sync(0xffffffffu, s2, o);
    }
    if (lane == 0) { rs[w] = s; rs[32 + w] = s2; }
    __syncthreads();
    if (threadIdx.x == 0) {
        float S = 0.f, S2 = 0.f;
        for (int i = 0; i < 8; i++) { S += rs[i]; S2 += rs[32 + i]; }
        rs[0] = S; rs[32] = S2;
    }
    __syncthreads();
    float mean = rs[0] * (1.f/131072.f);
    float var  = rs[32] * (1.f/131072.f) - mean*mean;
    float inv  = rsqrtf(var + eps);
    float gg = gate[0];
    for (int i = threadIdx.x; i < 16384; i += 256) {
        float4* hr = (float4*)(hb + (size_t)i*256);
        float4* xr = (float4*)(xb + (size_t)i*256);
        float4 a = hr[0], c = hr[1];
        float4 xa = xr[0], xc = xr[1];
        xa.x += gg*(a.x-mean)*inv; xa.y += gg*(a.y-mean)*inv;
        xa.z += gg*(a.z-mean)*inv; xa.w += gg*(a.w-mean)*inv;
        xc.x += gg*(c.x-mean)*inv; xc.y += gg*(c.y-mean)*inv;
        xc.z += gg*(c.z-mean)*inv; xc.w += gg*(c.w-mean)*inv;
        xr[0] = xa; xr[1] = xc;
        hr[0] = make_float4(tf32r(xa.x), tf32r(xa.y), tf32r(xa.z), tf32r(xa.w));
        hr[1] = make_float4(tf32r(xc.x), tf32r(xc.y), tf32r(xc.z), tf32r(xc.w));
    }
}

// ---------------- layer2 attention over Fq per (b,t,h) ----------------
__global__ void k_attn_freq(const float* __restrict__ qkv, float* __restrict__ y) {
    __shared__ float q[64][33], kk[64][33], v[64][33];
    __shared__ float S[64][65];
    int bt = blockIdx.x, h = blockIdx.y;
    int b = bt >> 8, t = bt & 255;
    int tid = threadIdx.x;
    for (int i = tid; i < 2048; i += 128) {
        int fq = i >> 5, d = i & 31;
        size_t base = ((size_t)((b*64 + fq)*256 + t))*768 + h*32 + d;
        q[fq][d]  = qkv[base];
        kk[fq][d] = qkv[base + 256];
        v[fq][d]  = qkv[base + 512];
    }
    __syncthreads();
    const float scale = 0.17677669529663687f;
    for (int i = tid; i < 4096; i += 128) {
        int L = i >> 6, l = i & 63;
        float s = 0.f;
        #pragma unroll
        for (int d = 0; d < 32; d++) s += q[L][d] * kk[l][d];
        S[L][l] = s * scale;
    }
    __syncthreads();
    if (tid < 64) {
        float m = -1e30f;
        for (int l = 0; l < 64; l++) m = fmaxf(m, S[tid][l]);
        float su = 0.f;
        for (int l = 0; l < 64; l++) { float e = __expf(S[tid][l] - m); S[tid][l] = e; su += e; }
        float r = 1.f / su;
        for (int l = 0; l < 64; l++) S[tid][l] *= r;
    }
    __syncthreads();
    for (int i = tid; i < 2048; i += 128) {
        int L = i >> 5, d = i & 31;
        float s = 0.f;
        #pragma unroll
        for (int l = 0; l < 64; l++) s += S[L][l] * v[l][d];
        y[((size_t)((b*64 + L)*256 + t))*256 + h*32 + d] = tf32r(s);
    }
}

// ---------------- layer3 attention: precomputed q, KV-only [NTOK,512] ----------
__global__ void k_attn_time2(const float* __restrict__ kv, const float* __restrict__ q3,
                             float* __restrict__ yout) {
    __shared__ float qs[32];
    __shared__ float part[8][32];
    __shared__ float prob[256];
    __shared__ float redm[8], reds[8];
    int bfq = blockIdx.x, h = blockIdx.y;
    int tid = threadIdx.x;
    size_t tokbase = (size_t)bfq * 256;
    int d = tid & 31, grp = tid >> 5;
    if (tid < 32) qs[tid] = q3[bfq*256 + h*32 + tid];
    __syncthreads();
    const float* kr = kv + (tokbase + tid)*512 + h*32;
    float sc = 0.f;
    #pragma unroll
    for (int dd = 0; dd < 32; dd++) sc += qs[dd] * kr[dd];
    sc *= 0.17677669529663687f;
    float m = sc;
    #pragma unroll
    for (int o = 16; o; o >>= 1) m = fmaxf(m, __shfl_xor_sync(0xffffffffu, m, o));
    if ((tid & 31) == 0) redm[grp] = m;
    __syncthreads();
    float M = redm[0];
    #pragma unroll
    for (int g = 1; g < 8; g++) M = fmaxf(M, redm[g]);
    float e = __expf(sc - M);
    float su = e;
    #pragma unroll
    for (int o = 16; o; o >>= 1) su += __shfl_xor_sync(0xffffffffu, su, o);
    if ((tid & 31) == 0) reds[grp] = su;
    __syncthreads();
    float Ssum = 0.f;
    #pragma unroll
    for (int g = 0; g < 8; g++) Ssum += reds[g];
    prob[tid] = e / Ssum;
    __syncthreads();
    float acc = 0.f;
    for (int t = grp; t < 256; t += 8)
        acc += prob[t] * kv[(tokbase + t)*512 + 256 + h*32 + d];
    part[grp][d] = acc;
    __syncthreads();
    if (tid < 32) {
        float ss = 0.f;
        #pragma unroll
        for (int g = 0; g < 8; g++) ss += part[g][tid];
        yout[(size_t)bfq*256 + h*32 + tid] = tf32r(ss);
    }
}

// ---------------- mean over T of tf32 shadow ----------------
__global__ void k_meanx(const float* __restrict__ xs, float* __restrict__ qm) {
    int bfq = blockIdx.x, c = threadIdx.x;
    const float* p = xs + (size_t)bfq * 65536 + c;
    float s = 0.f;
    for (int t = 0; t < 256; t++) s += p[(size_t)t * 256];
    qm[bfq*256 + c] = tf32r(s * (1.f/256.f));
}

// ---------------- layer3 epilogue ----------------
__global__ void k_gn_bcast_add(const float* __restrict__ yv, float* __restrict__ x,
                               const float* __restrict__ gate) {
    __shared__ float yn[256];
    int bfq = blockIdx.x, tid = threadIdx.x;
    if (tid < 32) {
        const float* r = yv + bfq*256 + tid*8;
        float vals[8];
        #pragma unroll
        for (int j = 0; j < 8; j++) vals[j] = r[j];
        float m = 0.f;
        #pragma unroll
        for (int j = 0; j < 8; j++) m += vals[j];
        m *= 0.125f;
        float var = 0.f;
        #pragma unroll
        for (int j = 0; j < 8; j++) { float dd = vals[j] - m; var += dd * dd; }
        var *= 0.125f;
        float inv = rsqrtf(var + 1e-5f);
        #pragma unroll
        for (int j = 0; j < 8; j++) yn[tid*8 + j] = (vals[j] - m) * inv;
    }
    __syncthreads();
    float add = gate[0] * yn[tid];
    float* xp = x + (size_t)bfq * 65536 + tid;
    for (int t = 0; t < 256; t++) xp[(size_t)t * 256] += add;
}

// ---------------- layer4 LSA ----------------
__global__ void k_attn_lsa(const float* __restrict__ qkv, float* __restrict__ y) {
    __shared__ float q[16][33], kk[16][33], v[16][33];
    __shared__ float S[16][17];
    int blk = blockIdx.x;
    size_t p0 = (size_t)(blk >> 4) * 256 + (blk & 15) * 16;
    int tid = threadIdx.x;
    int qi = tid >> 4, kj = tid & 15;
    const float scale = 0.17677669529663687f;
    for (int h = 0; h < 8; h++) {
        for (int i = tid; i < 512; i += 256) {
            int r = i >> 5, d = i & 31;
            size_t a = (p0 + r)*768 + h*32 + d;
            q[r][d] = qkv[a]; kk[r][d] = qkv[a + 256]; v[r][d] = qkv[a + 512];
        }
        __syncthreads();
        float s = 0.f;
        #pragma unroll
        for (int d = 0; d < 32; d++) s += q[qi][d] * kk[kj][d];
        S[qi][kj] = s * scale;
        __syncthreads();
        if (tid < 16) {
            float m = -1e30f;
            for (int j = 0; j < 16; j++) m = fmaxf(m, S[tid][j]);
            float su = 0.f;
            for (int j = 0; j < 16; j++) { float e = __expf(S[tid][j] - m); S[tid][j] = e; su += e; }
            float r = 1.f / su;
            for (int j = 0; j < 16; j++) S[tid][j] *= r;
        }
        __syncthreads();
        for (int i = tid; i < 512; i += 256) {
            int r = i >> 5, d = i & 31;
            float s2 = 0.f;
            #pragma unroll
            for (int j = 0; j < 16; j++) s2 += S[r][j] * v[j][d];
            y[(p0 + r)*256 + h*32 + d] = tf32r(s2);
        }
        __syncthreads();
    }
}

// =====================================================================================
extern "C" void kernel_launch(void* const* d_in, const int* in_sizes, int n_in,
                              void* d_out, int out_size) {
    const float* x     = (const float*)d_in[0];
    const float* temb  = (const float*)d_in[1];
    const float* w1    = (const float*)d_in[2];
    const float* b1    = (const float*)d_in[3];
    const float* w2    = (const float*)d_in[4];
    const float* gdiff = (const float*)d_in[5];
    const float* gres  = (const float*)d_in[6];
    const float* g2    = (const float*)d_in[7];
    const float* g3    = (const float*)d_in[8];
    const float* qkv2w = (const float*)d_in[9];
    const float* qkv2b = (const float*)d_in[10];
    const float* out2w = (const float*)d_in[11];
    const float* qkv3w = (const float*)d_in[12];
    const float* qkv3b = (const float*)d_in[13];
    const float* out3w = (const float*)d_in[14];
    const float* lsaqw = (const float*)d_in[15];
    const float* lsaow = (const float*)d_in[16];
    float* out = (float*)d_out;

    float *px, *ph, *ph2, *py, *pqkv, *pa3, *pa3b, *pqm, *pq3;
    float *pwt, *pwt2, *pwq2, *pwo2, *pwq3, *pwq3q, *pwo3, *pwq4, *pwo4;
    cudaGetSymbolAddress((void**)&px,    g_x);
    cudaGetSymbolAddress((void**)&ph,    g_h);
    cudaGetSymbolAddress((void**)&ph2,   g_h2);
    cudaGetSymbolAddress((void**)&py,    g_y);
    cudaGetSymbolAddress((void**)&pqkv,  g_qkv);
    cudaGetSymbolAddress((void**)&pa3,   g_a3);
    cudaGetSymbolAddress((void**)&pa3b,  g_a3b);
    cudaGetSymbolAddress((void**)&pqm,   g_qm);
    cudaGetSymbolAddress((void**)&pq3,   g_q3);
    cudaGetSymbolAddress((void**)&pwt,   g_wt);
    cudaGetSymbolAddress((void**)&pwt2,  g_wt2);
    cudaGetSymbolAddress((void**)&pwq2,  g_wq2);
    cudaGetSymbolAddress((void**)&pwo2,  g_wo2);
    cudaGetSymbolAddress((void**)&pwq3,  g_wq3);
    cudaGetSymbolAddress((void**)&pwq3q, g_wq3q);
    cudaGetSymbolAddress((void**)&pwo3,  g_wo3);
    cudaGetSymbolAddress((void**)&pwq4,  g_wq4);
    cudaGetSymbolAddress((void**)&pwo4,  g_wo4);

    cudaFuncSetAttribute(k_pgemm<0>, cudaFuncAttributeMaxDynamicSharedMemorySize, SMEM_MM);
    cudaFuncSetAttribute(k_pgemm<1>, cudaFuncAttributeMaxDynamicSharedMemorySize, SMEM_MM);
    cudaFuncSetAttribute(k_pgemm<4>, cudaFuncAttributeMaxDynamicSharedMemorySize, SMEM_MM);
    cudaFuncSetAttribute(k_pconv<0>, cudaFuncAttributeMaxDynamicSharedMemorySize, SMEM_MM);
    cudaFuncSetAttribute(k_pconv<1>, cudaFuncAttributeMaxDynamicSharedMemorySize, SMEM_MM);

    dim3 tb32(32, 8);

    k_prep_all<<<7680, 256>>>(w1, w2, qkv2w, out2w, qkv3w, out3w, lsaqw, lsaow,
                              pwt, pwt2, pwq2, pwo2, pwq3, pwq3q, pwo3, pwq4, pwo4);
    k_nchw_to_nhwc<<<dim3(8, 8, 256), tb32>>>(x, px);

    // ---- Residual block ----
    k_gn_bg<true><<<128, 256>>>(px, ph, 1e-6f);
    k_pconv<1><<<dim3(2, 512), 256, SMEM_MM>>>(ph, pwt, b1, temb, gdiff, ph2);
    k_gn_bg<true><<<128, 256>>>(ph2, ph, 1e-6f);
    k_pconv<0><<<dim3(2, 512), 256, SMEM_MM>>>(ph, pwt2, nullptr, nullptr, nullptr, ph2);
    k_gn_axpy<<<128, 256>>>(ph2, px, gres, 1e-6f);

    // ---- layer2 ----
    k_pgemm<1><<<dim3(6, 512), 256, SMEM_MM>>>(ph2, pwq2, qkv2b, nullptr, pqkv,
                                               nullptr, nullptr, NTOK, 768, 256);
    k_attn_freq<<<dim3(1024, 8), 128>>>(pqkv, py);
    k_pgemm<4><<<dim3(2, 512), 256, SMEM_MM>>>(py, pwo2, nullptr, g2, ph,
                                               px, ph2, NTOK, 256, 256);

    // ---- layer3 (q via mean-then-project) ----
    k_pgemm<1><<<dim3(4, 512), 256, SMEM_MM>>>(ph2, pwq3, qkv3b + 256, nullptr, pqkv,
                                               nullptr, nullptr, NTOK, 512, 256);
    k_meanx<<<256, 256>>>(ph2, pqm);
    k_pgemm<1><<<dim3(2, 2), 256, SMEM_MM>>>(pqm, pwq3q, qkv3b, nullptr, pq3,
                                             nullptr, nullptr, 256, 256, 256);
    k_attn_time2<<<dim3(256, 8), 256>>>(pqkv, pq3, pa3);
    k_pgemm<0><<<dim3(2, 2), 256, SMEM_MM>>>(pa3, pwo3, nullptr, nullptr, pa3b,
                                             nullptr, nullptr, 256, 256, 256);
    k_gn_bcast_add<<<256, 256>>>(pa3b, px, g3);

    // ---- layer4 ----
    k_gn_bg<true><<<128, 256>>>(px, ph, 1e-5f);
    k_pgemm<0><<<dim3(6, 512), 256, SMEM_MM>>>(ph, pwq4, nullptr, nullptr, pqkv,
                                               nullptr, nullptr, NTOK, 768, 256);
    k_attn_lsa<<<4096, 256>>>(pqkv, py);
    k_pgemm<0><<<dim3(2, 512), 256, SMEM_MM>>>(py, pwo4, nullptr, nullptr, ph,
                                               nullptr, nullptr, NTOK, 256, 256);

    k_nhwc_to_nchw_add<<<dim3(8, 8, 256), tb32>>>(px, ph, out);
}

// round 13
// speedup vs baseline: 1.2038x; 1.0831x over previous
#include <cuda_runtime.h>
#include <cstdint>
#include <math.h>

// B=4, C=256, Fq=64, T=256, HEADS=8, Dh=32, GROUPS=32, WIN=16
#define NTOK   65536
#define ELEMS  16777216

// ---------------- scratch ----------------
__device__ float g_x[ELEMS];
__device__ float g_h[ELEMS];
__device__ float g_h2[ELEMS];       // tf32 shadow of g_x
__device__ float g_y[ELEMS];
__device__ float g_qkv[3*ELEMS];
__device__ float g_a3[65536];
__device__ float g_a3b[65536];
__device__ float g_qm[65536];
__device__ float g_q3[65536];
__device__ float g_wt[589824];
__device__ float g_wt2[589824];
__device__ float g_wq2[196608];
__device__ float g_wo2[65536];
__device__ float g_wq3[131072];     // KV-only (N=512)
__device__ float g_wq3q[65536];     // q-only (N=256)
__device__ float g_wo3[65536];
__device__ float g_wq4[196608];
__device__ float g_wo4[65536];
__device__ float g_stat[4*128*2];         // [inst][b*32+g][mean,inv]
__device__ float g_part[4*128*256*2];     // [inst][b*32+g][chunk][sum,sumsq]

// ---------------- tf32 helpers ----------------
__device__ __forceinline__ uint32_t f2tf(float x) {
    uint32_t r; asm("cvt.rna.tf32.f32 %0, %1;" : "=r"(r) : "f"(x)); return r;
}
__device__ __forceinline__ float tf32r(float x) { return __uint_as_float(f2tf(x)); }
__device__ __forceinline__ void mma8(float* d, const uint32_t* a, const uint32_t* b) {
    asm volatile("mma.sync.aligned.m16n8k8.row.col.f32.tf32.tf32.f32 "
        "{%0,%1,%2,%3}, {%4,%5,%6,%7}, {%8,%9}, {%0,%1,%2,%3};"
        : "+f"(d[0]), "+f"(d[1]), "+f"(d[2]), "+f"(d[3])
        : "r"(a[0]), "r"(a[1]), "r"(a[2]), "r"(a[3]), "r"(b[0]), "r"(b[1]));
}
__device__ __forceinline__ void cpa16(uint32_t dst, const void* src, int sz) {
    asm volatile("cp.async.cg.shared.global [%0], [%1], 16, %2;" :: "r"(dst), "l"(src), "r"(sz));
}
__device__ __forceinline__ void cpa_commit() { asm volatile("cp.async.commit_group;"); }
__device__ __forceinline__ void cpa_wait0()  { asm volatile("cp.async.wait_group 0;"); }
__device__ __forceinline__ void cpa_wait1()  { asm volatile("cp.async.wait_group 1;"); }

// packed-pos -> local k within a 32-k tile
__device__ __forceinline__ int kOfPos(int pos) {
    int ks = pos >> 3, rem = pos & 7;
    return ks*8 + (rem >> 1) + 4*(rem & 1);
}

// smem: stage = A[128][32] (XOR 4*(row&7)) + B[128][32] (XOR 8*(n&3)); 3 stages
#define STAGE_W 8192
#define BS_OFF  4096
#define SMEM_MM (3*STAGE_W*4)   // 98304 B -> 2 CTA/SM

// ============ pipelined tf32 GEMM: 128x128 tile, Kt=32, cp.async 3-stage ============
// MODE: 0 plain, 1 +bias, 4 fused per-token GN(8ch) + x += gate*yn + tf32 shadow
template<int MODE>
__global__ __launch_bounds__(256, 2) void k_pgemm(
    const float* __restrict__ A, const float* __restrict__ Bp,
    const float* __restrict__ bias, const float* __restrict__ gate,
    float* __restrict__ C, float* __restrict__ xg, float* __restrict__ xs,
    int M, int N, int K) {
    extern __shared__ uint32_t dynsm[];
    uint32_t sbase = (uint32_t)__cvta_generic_to_shared(dynsm);
    int tid = threadIdx.x, lane = tid & 31, wid = tid >> 5;
    int g = lane >> 2, tig = lane & 3;
    int wm = wid >> 1, wn = wid & 1;
    int bn = blockIdx.x * 128, bm = blockIdx.y * 128;
    float acc[2][8][4] = {};
    int KT = K >> 5;

    auto copy = [&](int kt, int s) {
        int k0 = kt << 5;
        #pragma unroll
        for (int i = 0; i < 4; i++) {
            int idx = tid + i*256;
            int row = idx >> 3, c4 = idx & 7;
            cpa16(sbase + (s*STAGE_W + row*32 + ((c4*4) ^ ((row & 7)*4)))*4,
                  A + (size_t)(bm + row)*K + k0 + c4*4, 16);
            cpa16(sbase + (s*STAGE_W + BS_OFF + row*32 + ((c4*4) ^ ((row & 3)*8)))*4,
                  Bp + ((size_t)kt*N + bn + row)*32 + c4*4, 16);
        }
        cpa_commit();
    };

    copy(0, 0);
    if (KT > 1) copy(1, 1);
    for (int kt = 0; kt < KT; kt++) {
        if (kt + 1 < KT) cpa_wait1(); else cpa_wait0();
        __syncthreads();
        if (kt + 2 < KT) copy(kt + 2, (kt + 2) % 3);
        const uint32_t* As = dynsm + (kt % 3)*STAGE_W;
        const uint32_t* Bt = As + BS_OFF;
        #pragma unroll
        for (int ks = 0; ks < 4; ks++) {
            int k = ks * 8;
            uint32_t af[2][4], bf[8][2];
            int sw = g*4;
            #pragma unroll
            for (int mt = 0; mt < 2; mt++) {
                int r1 = wm*32 + mt*16 + g, r2 = r1 + 8;
                af[mt][0] = As[r1*32 + ((k + tig) ^ sw)];
                af[mt][1] = As[r2*32 + ((k + tig) ^ sw)];
                af[mt][2] = As[r1*32 + ((k + tig + 4) ^ sw)];
                af[mt][3] = As[r2*32 + ((k + tig + 4) ^ sw)];
            }
            #pragma unroll
            for (int nt = 0; nt < 8; nt++) {
                int c0 = wn*64 + nt*8 + g;
                uint2 bv = *(const uint2*)&Bt[c0*32 + ((k + tig*2) ^ ((c0 & 3)*8))];
                bf[nt][0] = bv.x; bf[nt][1] = bv.y;
            }
            #pragma unroll
            for (int mt = 0; mt < 2; mt++)
                #pragma unroll
                for (int nt = 0; nt < 8; nt++)
                    mma8(acc[mt][nt], af[mt], bf[nt]);
        }
    }

    if (MODE != 4) {
        #pragma unroll
        for (int mt = 0; mt < 2; mt++) {
            int row = bm + wm*32 + mt*16 + g;
            #pragma unroll
            for (int nt = 0; nt < 8; nt++) {
                int col = bn + wn*64 + nt*8 + tig*2;
                float2 v0 = make_float2(acc[mt][nt][0], acc[mt][nt][1]);
                float2 v1 = make_float2(acc[mt][nt][2], acc[mt][nt][3]);
                if (MODE == 1) {
                    float b0 = bias[col], b1v = bias[col + 1];
                    v0.x += b0; v0.y += b1v; v1.x += b0; v1.y += b1v;
                }
                *(float2*)(C + (size_t)row*N + col) = v0;
                *(float2*)(C + (size_t)(row + 8)*N + col) = v1;
            }
        }
    } else {
        float gg = gate[0];
        #pragma unroll
        for (int mt = 0; mt < 2; mt++) {
            int row = bm + wm*32 + mt*16 + g;
            #pragma unroll
            for (int nt = 0; nt < 8; nt++) {
                int col = bn + wn*64 + nt*8 + tig*2;
                float a0 = acc[mt][nt][0], a1 = acc[mt][nt][1];
                float b0 = acc[mt][nt][2], b1 = acc[mt][nt][3];
                float s0 = a0 + a1, s1 = b0 + b1;
                s0 += __shfl_xor_sync(0xffffffffu, s0, 1);
                s0 += __shfl_xor_sync(0xffffffffu, s0, 2);
                s1 += __shfl_xor_sync(0xffffffffu, s1, 1);
                s1 += __shfl_xor_sync(0xffffffffu, s1, 2);
                float m0 = s0 * 0.125f, m1 = s1 * 0.125f;
                float d00 = a0 - m0, d01 = a1 - m0, d10 = b0 - m1, d11 = b1 - m1;
                float q0 = d00*d00 + d01*d01, q1 = d10*d10 + d11*d11;
                q0 += __shfl_xor_sync(0xffffffffu, q0, 1);
                q0 += __shfl_xor_sync(0xffffffffu, q0, 2);
                q1 += __shfl_xor_sync(0xffffffffu, q1, 1);
                q1 += __shfl_xor_sync(0xffffffffu, q1, 2);
                float i0 = rsqrtf(q0*0.125f + 1e-5f), i1 = rsqrtf(q1*0.125f + 1e-5f);
                size_t o0 = (size_t)row*N + col, o1 = (size_t)(row + 8)*N + col;
                float2 x0 = *(float2*)(xg + o0), x1 = *(float2*)(xg + o1);
                x0.x += gg * d00 * i0; x0.y += gg * d01 * i0;
                x1.x += gg * d10 * i1; x1.y += gg * d11 * i1;
                *(float2*)(xg + o0) = x0;
                *(float2*)(xg + o1) = x1;
                *(float2*)(xs + o0) = make_float2(tf32r(x0.x), tf32r(x0.y));
                *(float2*)(xs + o1) = make_float2(tf32r(x1.x), tf32r(x1.y));
            }
        }
    }
}

// ============ pipelined conv3x3 implicit GEMM, 3-stage ============
template<int MODE>   // 0 plain, 1 bias+temb+silu
__global__ __launch_bounds__(256, 2) void k_pconv(
    const float* __restrict__ In, const float* __restrict__ Wp,
    const float* __restrict__ bias, const float* __restrict__ temb,
    const float* __restrict__ gate, float* __restrict__ Out) {
    extern __shared__ uint32_t dynsm[];
    uint32_t sbase = (uint32_t)__cvta_generic_to_shared(dynsm);
    int tid = threadIdx.x, lane = tid & 31, wid = tid >> 5;
    int g = lane >> 2, tig = lane & 3;
    int wm = wid >> 1, wn = wid & 1;
    int bn = blockIdx.x * 128, bm = blockIdx.y * 128;
    float acc[2][8][4] = {};

    int pb[4], pfy[4], pfx[4];
    #pragma unroll
    for (int i = 0; i < 4; i++) {
        int p = bm + ((tid + i*256) >> 3);
        pb[i] = p >> 14; pfy[i] = (p >> 8) & 63; pfx[i] = p & 255;
    }

    auto copy = [&](int kt, int s) {
        int k0 = kt << 5;
        int kyx = k0 >> 8, ci0 = k0 & 255;
        int ky = kyx / 3, kx = kyx - ky*3;
        #pragma unroll
        for (int i = 0; i < 4; i++) {
            int idx = tid + i*256;
            int row = idx >> 3, c4 = idx & 7;
            int fy2 = pfy[i] + ky - 1, fx2 = pfx[i] + kx - 1;
            bool v = ((unsigned)fy2 < 64u) && ((unsigned)fx2 < 256u);
            cpa16(sbase + (s*STAGE_W + row*32 + ((c4*4) ^ ((row & 7)*4)))*4,
                  In + (((size_t)(pb[i]*64 + (v?fy2:0)))*256 + (v?fx2:0))*256 + ci0 + c4*4,
                  v ? 16 : 0);
            cpa16(sbase + (s*STAGE_W + BS_OFF + row*32 + ((c4*4) ^ ((row & 3)*8)))*4,
                  Wp + ((size_t)kt*256 + bn + row)*32 + c4*4, 16);
        }
        cpa_commit();
    };

    copy(0, 0); copy(1, 1);
    for (int kt = 0; kt < 72; kt++) {
        if (kt + 1 < 72) cpa_wait1(); else cpa_wait0();
        __syncthreads();
        if (kt + 2 < 72) copy(kt + 2, (kt + 2) % 3);
        const uint32_t* As = dynsm + (kt % 3)*STAGE_W;
        const uint32_t* Bt = As + BS_OFF;
        #pragma unroll
        for (int ks = 0; ks < 4; ks++) {
            int k = ks * 8;
            uint32_t af[2][4], bf[8][2];
            int sw = g*4;
            #pragma unroll
            for (int mt = 0; mt < 2; mt++) {
                int r1 = wm*32 + mt*16 + g, r2 = r1 + 8;
                af[mt][0] = As[r1*32 + ((k + tig) ^ sw)];
                af[mt][1] = As[r2*32 + ((k + tig) ^ sw)];
                af[mt][2] = As[r1*32 + ((k + tig + 4) ^ sw)];
                af[mt][3] = As[r2*32 + ((k + tig + 4) ^ sw)];
            }
            #pragma unroll
            for (int nt = 0; nt < 8; nt++) {
                int c0 = wn*64 + nt*8 + g;
                uint2 bv = *(const uint2*)&Bt[c0*32 + ((k + tig*2) ^ ((c0 & 3)*8))];
                bf[nt][0] = bv.x; bf[nt][1] = bv.y;
            }
            #pragma unroll
            for (int mt = 0; mt < 2; mt++)
                #pragma unroll
                for (int nt = 0; nt < 8; nt++)
                    mma8(acc[mt][nt], af[mt], bf[nt]);
        }
    }
    float gd = (MODE == 1) ? gate[0] : 0.f;
    #pragma unroll
    for (int mt = 0; mt < 2; mt++) {
        int row = bm + wm*32 + mt*16 + g;
        int bidx = row >> 14;
        #pragma unroll
        for (int nt = 0; nt < 8; nt++) {
            int col = bn + wn*64 + nt*8 + tig*2;
            float v[4] = {acc[mt][nt][0], acc[mt][nt][1], acc[mt][nt][2], acc[mt][nt][3]};
            if (MODE == 1) {
                float a0 = bias[col]     + gd * temb[bidx*256 + col];
                float a1 = bias[col + 1] + gd * temb[bidx*256 + col + 1];
                v[0] += a0; v[1] += a1; v[2] += a0; v[3] += a1;
                #pragma unroll
                for (int j = 0; j < 4; j++) v[j] = v[j] / (1.f + __expf(-v[j]));
            }
            *(float2*)(Out + (size_t)row*256 + col) = make_float2(v[0], v[1]);
            *(float2*)(Out + (size_t)(row + 8)*256 + col) = make_float2(v[2], v[3]);
        }
    }
}

// ---------------- merged weight prepack ----------------
__device__ __forceinline__ void prep_gemm(const float* __restrict__ W, float* __restrict__ P,
                                          int NP, int coff, int srcN, int li) {
    int pos = li & 31;
    int rest = li >> 5;
    int n = rest % NP;
    int kt = rest / NP;
    int k = kt*32 + kOfPos(pos);
    P[li] = tf32r(W[(size_t)k * srcN + coff + n]);
}
__device__ __forceinline__ void prep_conv(const float* __restrict__ w, float* __restrict__ P, int li) {
    int pos = li & 31;
    int rest = li >> 5;
    int co = rest & 255;
    int kt = rest >> 8;
    int k = kt*32 + kOfPos(pos);
    int kyx = k >> 8, ci = k & 255;
    P[li] = tf32r(w[(size_t)co * 2304 + ci * 9 + kyx]);
}
__global__ void k_prep_all(
    const float* __restrict__ w1, const float* __restrict__ w2,
    const float* __restrict__ qkv2w, const float* __restrict__ out2w,
    const float* __restrict__ qkv3w, const float* __restrict__ out3w,
    const float* __restrict__ lsaqw, const float* __restrict__ lsaow,
    float* wt1, float* wt2, float* wq2, float* wo2, float* wq3kv, float* wq3q,
    float* wo3, float* wq4, float* wo4) {
    int idx = blockIdx.x * 256 + threadIdx.x;
    if      (idx < 589824)  prep_conv(w1, wt1, idx);
    else if (idx < 1179648) prep_conv(w2, wt2, idx - 589824);
    else if (idx < 1376256) prep_gemm(qkv2w, wq2, 768, 0, 768, idx - 1179648);
    else if (idx < 1441792) prep_gemm(out2w, wo2, 256, 0, 256, idx - 1376256);
    else if (idx < 1572864) prep_gemm(qkv3w, wq3kv, 512, 256, 768, idx - 1441792);
    else if (idx < 1638400) prep_gemm(qkv3w, wq3q, 256, 0, 768, idx - 1572864);
    else if (idx < 1703936) prep_gemm(out3w, wo3, 256, 0, 256, idx - 1638400);
    else if (idx < 1900544) prep_gemm(lsaqw, wq4, 768, 0, 768, idx - 1703936);
    else if (idx < 1966080) prep_gemm(lsaow, wo4, 256, 0, 256, idx - 1900544);
}

// ---------------- transposes ----------------
__global__ void k_nchw_to_nhwc(const float* __restrict__ in, float* __restrict__ out) {
    __shared__ float tile[32][33];
    int bfq = blockIdx.z, b = bfq >> 6, fq = bfq & 63;
    int t0 = blockIdx.x * 32, c0 = blockIdx.y * 32;
    for (int r = threadIdx.y; r < 32; r += 8)
        tile[r][threadIdx.x] = in[(((size_t)b*256 + c0 + r)*64 + fq)*256 + t0 + threadIdx.x];
    __syncthreads();
    for (int r = threadIdx.y; r < 32; r += 8)
        out[((size_t)bfq*256 + t0 + r)*256 + c0 + threadIdx.x] = tile[threadIdx.x][r];
}

__global__ void k_nhwc_to_nchw_add(const float* __restrict__ xa, const float* __restrict__ xb,
                                   float* __restrict__ out) {
    __shared__ float tile[32][33];
    int bfq = blockIdx.z, b = bfq >> 6, fq = bfq & 63;
    int t0 = blockIdx.x * 32, c0 = blockIdx.y * 32;
    for (int r = threadIdx.y; r < 32; r += 8) {
        size_t p = ((size_t)bfq*256 + t0 + r)*256 + c0 + threadIdx.x;
        tile[r][threadIdx.x] = xa[p] + xb[p];
    }
    __syncthreads();
    for (int r = threadIdx.y; r < 32; r += 8)
        out[(((size_t)b*256 + c0 + r)*64 + fq)*256 + t0 + threadIdx.x] = tile[threadIdx.x][r];
}

// ================= GroupNorm, 3-phase coalesced =================
// phase 1: per-chunk (64 tokens) per-group partial sums; fully coalesced
__global__ void k_gnstat1(const float* __restrict__ in, int inst) {
    __shared__ float sc[256], sq[256];
    int blk = blockIdx.x;           // 1024 = 4 batches x 256 chunks
    int b = blk >> 8, chunk = blk & 255;
    const float* base = in + ((size_t)b*16384 + chunk*64) * 256;
    int c = threadIdx.x;
    float s = 0.f, s2 = 0.f;
    for (int t = 0; t < 64; t++) {
        float v = base[(size_t)t*256 + c];
        s += v; s2 += v*v;
    }
    sc[c] = s; sq[c] = s2;
    __syncthreads();
    if (c < 32) {
        float S = 0.f, S2 = 0.f;
        #pragma unroll
        for (int j = 0; j < 8; j++) { S += sc[c*8 + j]; S2 += sq[c*8 + j]; }
        float* p = g_part + ((size_t)(inst*128 + b*32 + c)*256 + chunk)*2;
        p[0] = S; p[1] = S2;
    }
}
// phase 2: reduce 256 chunks -> mean/inv per (b,g)
__global__ void k_gnstat2(int inst, float eps) {
    __shared__ float rs[64];
    int bg = blockIdx.x;            // 128
    int tid = threadIdx.x;          // 256
    const float* p = g_part + ((size_t)(inst*128 + bg)*256 + tid)*2;
    float s = p[0], s2 = p[1];
    int lane = tid & 31, w = tid >> 5;
    #pragma unroll
    for (int o = 16; o; o >>= 1) {
        s  += __shfl_down_sync(0xffffffffu, s,  o);
        s2 += __shfl_down_sync(0xffffffffu, s2, o);
    }
    if (lane == 0) { rs[w] = s; rs[32 + w] = s2; }
    __syncthreads();
    if (tid == 0) {
        float S = 0.f, S2 = 0.f;
        for (int i = 0; i < 8; i++) { S += rs[i]; S2 += rs[32 + i]; }
        float mean = S * (1.f/131072.f);
        float var  = S2 * (1.f/131072.f) - mean*mean;
        g_stat[(inst*128 + bg)*2]     = mean;
        g_stat[(inst*128 + bg)*2 + 1] = rsqrtf(var + eps);
    }
}
// phase 3: normalize, fully coalesced (16 tokens per block)
template<bool ROUND>
__global__ void k_gnapply(const float* __restrict__ in, float* __restrict__ out, int inst) {
    __shared__ float ms[32], is[32];
    int p0 = blockIdx.x * 16;       // 4096 blocks
    int b = p0 >> 14;
    if (threadIdx.x < 32) {
        ms[threadIdx.x] = g_stat[(inst*128 + b*32 + threadIdx.x)*2];
        is[threadIdx.x] = g_stat[(inst*128 + b*32 + threadIdx.x)*2 + 1];
    }
    __syncthreads();
    for (int i = threadIdx.x; i < 1024; i += 256) {
        int c4 = i & 63, g = c4 >> 1;
        size_t off = (size_t)p0*256 + (size_t)i*4;
        float4 v = *(const float4*)(in + off);
        float m = ms[g], iv = is[g];
        v.x = (v.x-m)*iv; v.y = (v.y-m)*iv; v.z = (v.z-m)*iv; v.w = (v.w-m)*iv;
        if (ROUND) { v.x = tf32r(v.x); v.y = tf32r(v.y); v.z = tf32r(v.z); v.w = tf32r(v.w); }
        *(float4*)(out + off) = v;
    }
}
// phase 3 variant: x += gate * hn; h2 <- tf32 shadow of new x
__global__ void k_gnaxapply(float* __restrict__ h2, float* __restrict__ x,
                            const float* __restrict__ gate, int inst) {
    __shared__ float ms[32], is[32];
    int p0 = blockIdx.x * 16;
    int b = p0 >> 14;
    if (threadIdx.x < 32) {
        ms[threadIdx.x] = g_stat[(inst*128 + b*32 + threadIdx.x)*2];
        is[threadIdx.x] = g_stat[(inst*128 + b*32 + threadIdx.x)*2 + 1];
    }
    __syncthreads();
    float gg = gate[0];
    for (int i = threadIdx.x; i < 1024; i += 256) {
        int c4 = i & 63, g = c4 >> 1;
        size_t off = (size_t)p0*256 + (size_t)i*4;
        float4 h = *(const float4*)(h2 + off);
        float4 xv = *(float4*)(x + off);
        float m = ms[g], iv = is[g];
        xv.x += gg*(h.x-m)*iv; xv.y += gg*(h.y-m)*iv;
        xv.z += gg*(h.z-m)*iv; xv.w += gg*(h.w-m)*iv;
        *(float4*)(x + off) = xv;
        *(float4*)(h2 + off) = make_float4(tf32r(xv.x), tf32r(xv.y), tf32r(xv.z), tf32r(xv.w));
    }
}

// ---------------- layer2 attention over Fq per (b,t,h) ----------------
__global__ void k_attn_freq(const float* __restrict__ qkv, float* __restrict__ y) {
    __shared__ float q[64][33], kk[64][33], v[64][33];
    __shared__ float S[64][65];
    int bt = blockIdx.x, h = blockIdx.y;
    int b = bt >> 8, t = bt & 255;
    int tid = threadIdx.x;
    for (int i = tid; i < 2048; i += 128) {
        int fq = i >> 5, d = i & 31;
        size_t base = ((size_t)((b*64 + fq)*256 + t))*768 + h*32 + d;
        q[fq][d]  = qkv[base];
        kk[fq][d] = qkv[base + 256];
        v[fq][d]  = qkv[base + 512];
    }
    __syncthreads();
    const float scale = 0.17677669529663687f;
    for (int i = tid; i < 4096; i += 128) {
        int L = i >> 6, l = i & 63;
        float s = 0.f;
        #pragma unroll
        for (int d = 0; d < 32; d++) s += q[L][d] * kk[l][d];
        S[L][l] = s * scale;
    }
    __syncthreads();
    if (tid < 64) {
        float m = -1e30f;
        for (int l = 0; l < 64; l++) m = fmaxf(m, S[tid][l]);
        float su = 0.f;
        for (int l = 0; l < 64; l++) { float e = __expf(S[tid][l] - m); S[tid][l] = e; su += e; }
        float r = 1.f / su;
        for (int l = 0; l < 64; l++) S[tid][l] *= r;
    }
    __syncthreads();
    for (int i = tid; i < 2048; i += 128) {
        int L = i >> 5, d = i & 31;
        float s = 0.f;
        #pragma unroll
        for (int l = 0; l < 64; l++) s += S[L][l] * v[l][d];
        y[((size_t)((b*64 + L)*256 + t))*256 + h*32 + d] = tf32r(s);
    }
}

// ---------------- layer3 attention: precomputed q, KV-only [NTOK,512] ----------
__global__ void k_attn_time2(const float* __restrict__ kv, const float* __restrict__ q3,
                             float* __restrict__ yout) {
    __shared__ float qs[32];
    __shared__ float part[8][32];
    __shared__ float prob[256];
    __shared__ float redm[8], reds[8];
    int bfq = blockIdx.x, h = blockIdx.y;
    int tid = threadIdx.x;
    size_t tokbase = (size_t)bfq * 256;
    int d = tid & 31, grp = tid >> 5;
    if (tid < 32) qs[tid] = q3[bfq*256 + h*32 + tid];
    __syncthreads();
    const float* kr = kv + (tokbase + tid)*512 + h*32;
    float sc = 0.f;
    #pragma unroll
    for (int dd = 0; dd < 32; dd++) sc += qs[dd] * kr[dd];
    sc *= 0.17677669529663687f;
    float m = sc;
    #pragma unroll
    for (int o = 16; o; o >>= 1) m = fmaxf(m, __shfl_xor_sync(0xffffffffu, m, o));
    if ((tid & 31) == 0) redm[grp] = m;
    __syncthreads();
    float M = redm[0];
    #pragma unroll
    for (int g = 1; g < 8; g++) M = fmaxf(M, redm[g]);
    float e = __expf(sc - M);
    float su = e;
    #pragma unroll
    for (int o = 16; o; o >>= 1) su += __shfl_xor_sync(0xffffffffu, su, o);
    if ((tid & 31) == 0) reds[grp] = su;
    __syncthreads();
    float Ssum = 0.f;
    #pragma unroll
    for (int g = 0; g < 8; g++) Ssum += reds[g];
    prob[tid] = e / Ssum;
    __syncthreads();
    float acc = 0.f;
    for (int t = grp; t < 256; t += 8)
        acc += prob[t] * kv[(tokbase + t)*512 + 256 + h*32 + d];
    part[grp][d] = acc;
    __syncthreads();
    if (tid < 32) {
        float ss = 0.f;
        #pragma unroll
        for (int g = 0; g < 8; g++) ss += part[g][tid];
        yout[(size_t)bfq*256 + h*32 + tid] = tf32r(ss);
    }
}

// ---------------- mean over T of tf32 shadow ----------------
__global__ void k_meanx(const float* __restrict__ xs, float* __restrict__ qm) {
    int bfq = blockIdx.x, c = threadIdx.x;
    const float* p = xs + (size_t)bfq * 65536 + c;
    float s = 0.f;
    for (int t = 0; t < 256; t++) s += p[(size_t)t * 256];
    qm[bfq*256 + c] = tf32r(s * (1.f/256.f));
}

// ---------------- layer3 epilogue ----------------
__global__ void k_gn_bcast_add(const float* __restrict__ yv, float* __restrict__ x,
                               const float* __restrict__ gate) {
    __shared__ float yn[256];
    int bfq = blockIdx.x, tid = threadIdx.x;
    if (tid < 32) {
        const float* r = yv + bfq*256 + tid*8;
        float vals[8];
        #pragma unroll
        for (int j = 0; j < 8; j++) vals[j] = r[j];
        float m = 0.f;
        #pragma unroll
        for (int j = 0; j < 8; j++) m += vals[j];
        m *= 0.125f;
        float var = 0.f;
        #pragma unroll
        for (int j = 0; j < 8; j++) { float dd = vals[j] - m; var += dd * dd; }
        var *= 0.125f;
        float inv = rsqrtf(var + 1e-5f);
        #pragma unroll
        for (int j = 0; j < 8; j++) yn[tid*8 + j] = (vals[j] - m) * inv;
    }
    __syncthreads();
    float add = gate[0] * yn[tid];
    float* xp = x + (size_t)bfq * 65536 + tid;
    for (int t = 0; t < 256; t++) xp[(size_t)t * 256] += add;
}

// ---------------- layer4 LSA ----------------
__global__ void k_attn_lsa(const float* __restrict__ qkv, float* __restrict__ y) {
    __shared__ float q[16][33], kk[16][33], v[16][33];
    __shared__ float S[16][17];
    int blk = blockIdx.x;
    size_t p0 = (size_t)(blk >> 4) * 256 + (blk & 15) * 16;
    int tid = threadIdx.x;
    int qi = tid >> 4, kj = tid & 15;
    const float scale = 0.17677669529663687f;
    for (int h = 0; h < 8; h++) {
        for (int i = tid; i < 512; i += 256) {
            int r = i >> 5, d = i & 31;
            size_t a = (p0 + r)*768 + h*32 + d;
            q[r][d] = qkv[a]; kk[r][d] = qkv[a + 256]; v[r][d] = qkv[a + 512];
        }
        __syncthreads();
        float s = 0.f;
        #pragma unroll
        for (int d = 0; d < 32; d++) s += q[qi][d] * kk[kj][d];
        S[qi][kj] = s * scale;
        __syncthreads();
        if (tid < 16) {
            float m = -1e30f;
            for (int j = 0; j < 16; j++) m = fmaxf(m, S[tid][j]);
            float su = 0.f;
            for (int j = 0; j < 16; j++) { float e = __expf(S[tid][j] - m); S[tid][j] = e; su += e; }
            float r = 1.f / su;
            for (int j = 0; j < 16; j++) S[tid][j] *= r;
        }
        __syncthreads();
        for (int i = tid; i < 512; i += 256) {
            int r = i >> 5, d = i & 31;
            float s2 = 0.f;
            #pragma unroll
            for (int j = 0; j < 16; j++) s2 += S[r][j] * v[j][d];
            y[(p0 + r)*256 + h*32 + d] = tf32r(s2);
        }
        __syncthreads();
    }
}

// =====================================================================================
extern "C" void kernel_launch(void* const* d_in, const int* in_sizes, int n_in,
                              void* d_out, int out_size) {
    const float* x     = (const float*)d_in[0];
    const float* temb  = (const float*)d_in[1];
    const float* w1    = (const float*)d_in[2];
    const float* b1    = (const float*)d_in[3];
    const float* w2    = (const float*)d_in[4];
    const float* gdiff = (const float*)d_in[5];
    const float* gres  = (const float*)d_in[6];
    const float* g2    = (const float*)d_in[7];
    const float* g3    = (const float*)d_in[8];
    const float* qkv2w = (const float*)d_in[9];
    const float* qkv2b = (const float*)d_in[10];
    const float* out2w = (const float*)d_in[11];
    const float* qkv3w = (const float*)d_in[12];
    const float* qkv3b = (const float*)d_in[13];
    const float* out3w = (const float*)d_in[14];
    const float* lsaqw = (const float*)d_in[15];
    const float* lsaow = (const float*)d_in[16];
    float* out = (float*)d_out;

    float *px, *ph, *ph2, *py, *pqkv, *pa3, *pa3b, *pqm, *pq3;
    float *pwt, *pwt2, *pwq2, *pwo2, *pwq3, *pwq3q, *pwo3, *pwq4, *pwo4;
    cudaGetSymbolAddress((void**)&px,    g_x);
    cudaGetSymbolAddress((void**)&ph,    g_h);
    cudaGetSymbolAddress((void**)&ph2,   g_h2);
    cudaGetSymbolAddress((void**)&py,    g_y);
    cudaGetSymbolAddress((void**)&pqkv,  g_qkv);
    cudaGetSymbolAddress((void**)&pa3,   g_a3);
    cudaGetSymbolAddress((void**)&pa3b,  g_a3b);
    cudaGetSymbolAddress((void**)&pqm,   g_qm);
    cudaGetSymbolAddress((void**)&pq3,   g_q3);
    cudaGetSymbolAddress((void**)&pwt,   g_wt);
    cudaGetSymbolAddress((void**)&pwt2,  g_wt2);
    cudaGetSymbolAddress((void**)&pwq2,  g_wq2);
    cudaGetSymbolAddress((void**)&pwo2,  g_wo2);
    cudaGetSymbolAddress((void**)&pwq3,  g_wq3);
    cudaGetSymbolAddress((void**)&pwq3q, g_wq3q);
    cudaGetSymbolAddress((void**)&pwo3,  g_wo3);
    cudaGetSymbolAddress((void**)&pwq4,  g_wq4);
    cudaGetSymbolAddress((void**)&pwo4,  g_wo4);

    cudaFuncSetAttribute(k_pgemm<0>, cudaFuncAttributeMaxDynamicSharedMemorySize, SMEM_MM);
    cudaFuncSetAttribute(k_pgemm<1>, cudaFuncAttributeMaxDynamicSharedMemorySize, SMEM_MM);
    cudaFuncSetAttribute(k_pgemm<4>, cudaFuncAttributeMaxDynamicSharedMemorySize, SMEM_MM);
    cudaFuncSetAttribute(k_pconv<0>, cudaFuncAttributeMaxDynamicSharedMemorySize, SMEM_MM);
    cudaFuncSetAttribute(k_pconv<1>, cudaFuncAttributeMaxDynamicSharedMemorySize, SMEM_MM);

    dim3 tb32(32, 8);

    k_prep_all<<<7680, 256>>>(w1, w2, qkv2w, out2w, qkv3w, out3w, lsaqw, lsaow,
                              pwt, pwt2, pwq2, pwo2, pwq3, pwq3q, pwo3, pwq4, pwo4);
    k_nchw_to_nhwc<<<dim3(8, 8, 256), tb32>>>(x, px);

    // ---- Residual block ----
    k_gnstat1<<<1024, 256>>>(px, 0);
    k_gnstat2<<<128, 256>>>(0, 1e-6f);
    k_gnapply<true><<<4096, 256>>>(px, ph, 0);
    k_pconv<1><<<dim3(2, 512), 256, SMEM_MM>>>(ph, pwt, b1, temb, gdiff, ph2);
    k_gnstat1<<<1024, 256>>>(ph2, 1);
    k_gnstat2<<<128, 256>>>(1, 1e-6f);
    k_gnapply<true><<<4096, 256>>>(ph2, ph, 1);
    k_pconv<0><<<dim3(2, 512), 256, SMEM_MM>>>(ph, pwt2, nullptr, nullptr, nullptr, ph2);
    k_gnstat1<<<1024, 256>>>(ph2, 2);
    k_gnstat2<<<128, 256>>>(2, 1e-6f);
    k_gnaxapply<<<4096, 256>>>(ph2, px, gres, 2);     // px updated, ph2 = tf32 shadow

    // ---- layer2 ----
    k_pgemm<1><<<dim3(6, 512), 256, SMEM_MM>>>(ph2, pwq2, qkv2b, nullptr, pqkv,
                                               nullptr, nullptr, NTOK, 768, 256);
    k_attn_freq<<<dim3(1024, 8), 128>>>(pqkv, py);
    k_pgemm<4><<<dim3(2, 512), 256, SMEM_MM>>>(py, pwo2, nullptr, g2, ph,
                                               px, ph2, NTOK, 256, 256);

    // ---- layer3 (q via mean-then-project) ----
    k_pgemm<1><<<dim3(4, 512), 256, SMEM_MM>>>(ph2, pwq3, qkv3b + 256, nullptr, pqkv,
                                               nullptr, nullptr, NTOK, 512, 256);
    k_meanx<<<256, 256>>>(ph2, pqm);
    k_pgemm<1><<<dim3(2, 2), 256, SMEM_MM>>>(pqm, pwq3q, qkv3b, nullptr, pq3,
                                             nullptr, nullptr, 256, 256, 256);
    k_attn_time2<<<dim3(256, 8), 256>>>(pqkv, pq3, pa3);
    k_pgemm<0><<<dim3(2, 2), 256, SMEM_MM>>>(pa3, pwo3, nullptr, nullptr, pa3b,
                                             nullptr, nullptr, 256, 256, 256);
    k_gn_bcast_add<<<256, 256>>>(pa3b, px, g3);

    // ---- layer4 ----
    k_gnstat1<<<1024, 256>>>(px, 3);
    k_gnstat2<<<128, 256>>>(3, 1e-5f);
    k_gnapply<true><<<4096, 256>>>(px, ph, 3);
    k_pgemm<0><<<dim3(6, 512), 256, SMEM_MM>>>(ph, pwq4, nullptr, nullptr, pqkv,
                                               nullptr, nullptr, NTOK, 768, 256);
    k_attn_lsa<<<4096, 256>>>(pqkv, py);
    k_pgemm<0><<<dim3(2, 512), 256, SMEM_MM>>>(py, pwo4, nullptr, nullptr, ph,
                                               nullptr, nullptr, NTOK, 256, 256);

    k_nhwc_to_nchw_add<<<dim3(8, 8, 256), tb32>>>(px, ph, out);
}

// round 14
// speedup vs baseline: 1.5767x; 1.3098x over previous
#include <cuda_runtime.h>
#include <cuda_fp16.h>
#include <cstdint>
#include <math.h>

// B=4, C=256, Fq=64, T=256, HEADS=8, Dh=32, GROUPS=32, WIN=16
#define NTOK   65536
#define ELEMS  16777216

// ---------------- scratch ----------------
__device__ float  g_x[ELEMS];        // fp32 master
__device__ float  g_hf[ELEMS];       // fp32: conv outs / out-proj outs
__device__ __half g_ha[ELEMS];       // half: GN outputs (matmul A)
__device__ __half g_hs[ELEMS];       // half: shadow of g_x (matmul A)
__device__ __half g_ya[ELEMS];       // half: attention outputs (matmul A)
__device__ float  g_qkv[3*ELEMS];
__device__ __half g_a3[65536];
__device__ float  g_a3b[65536];
__device__ __half g_qm[65536];
__device__ float  g_q3[65536];
__device__ __half g_wt[589824];
__device__ __half g_wt2[589824];
__device__ __half g_wq2[196608];
__device__ __half g_wo2[65536];
__device__ __half g_wq3[131072];     // KV-only (N=512)
__device__ __half g_wq3q[65536];
__device__ __half g_wo3[65536];
__device__ __half g_wq4[196608];
__device__ __half g_wo4[65536];
__device__ float  g_stat[4*128*2];
__device__ float  g_part[4*128*256*2];

// ---------------- helpers ----------------
__device__ __forceinline__ __half h2f(float x) { return __float2half_rn(x); }
__device__ __forceinline__ void mma16(float* d, const uint32_t* a, const uint32_t* b) {
    asm volatile("mma.sync.aligned.m16n8k16.row.col.f32.f16.f16.f32 "
        "{%0,%1,%2,%3}, {%4,%5,%6,%7}, {%8,%9}, {%0,%1,%2,%3};"
        : "+f"(d[0]), "+f"(d[1]), "+f"(d[2]), "+f"(d[3])
        : "r"(a[0]), "r"(a[1]), "r"(a[2]), "r"(a[3]), "r"(b[0]), "r"(b[1]));
}
__device__ __forceinline__ void cpa16(uint32_t dst, const void* src, int sz) {
    asm volatile("cp.async.cg.shared.global [%0], [%1], 16, %2;" :: "r"(dst), "l"(src), "r"(sz));
}
__device__ __forceinline__ void cpa_commit() { asm volatile("cp.async.commit_group;"); }
__device__ __forceinline__ void cpa_wait0()  { asm volatile("cp.async.wait_group 0;"); }
__device__ __forceinline__ void cpa_wait1()  { asm volatile("cp.async.wait_group 1;"); }

// packed half pos (0..31) -> local k within 32-k tile (word-level interleave, half pairs)
__device__ __forceinline__ int kHalfOfPos(int pos) {
    int pw = pos >> 1, b = pos & 1;
    int group = pw >> 3, rem = pw & 7;
    int ow = group*8 + (rem >> 1) + 4*(rem & 1);
    return ow*2 + b;
}

// smem words: A rows 16 (XOR ((row>>1)&3)*4), B rows 24 (16 data + 8 pad)
#define A_W     16
#define B_W     24
#define BA_OFF  2048                // 128*16
#define STAGE_W 5120                // 2048 + 128*24
#define SMEM_MM (3*STAGE_W*4)       // 61440 B -> 2 CTA/SM

// ============ fp16 GEMM: 128x128 tile, Kt=32, cp.async 3-stage ============
// MODE: 0 plain->fp32 C, 1 +bias->fp32 C, 4 fused per-token GN + x+=gate*yn + half shadow
template<int MODE>
__global__ __launch_bounds__(256, 2) void k_pgemm(
    const __half* __restrict__ A, const __half* __restrict__ Bp,
    const float* __restrict__ bias, const float* __restrict__ gate,
    float* __restrict__ C, float* __restrict__ xg, __half* __restrict__ xs,
    int M, int N, int K) {
    extern __shared__ uint32_t dynsm[];
    uint32_t sbase = (uint32_t)__cvta_generic_to_shared(dynsm);
    int tid = threadIdx.x, lane = tid & 31, wid = tid >> 5;
    int g = lane >> 2, tig = lane & 3;
    int wm = wid >> 1, wn = wid & 1;
    int bn = blockIdx.x * 128, bm = blockIdx.y * 128;
    float acc[2][8][4] = {};
    int KT = K >> 5;

    auto copy = [&](int kt, int s) {
        int k0 = kt << 5;
        #pragma unroll
        for (int i = 0; i < 2; i++) {
            int idx = tid + i*256;
            int row = idx >> 2, c4 = idx & 3;
            cpa16(sbase + (s*STAGE_W + row*A_W + ((c4*4) ^ (((row >> 1) & 3)*4)))*4,
                  A + (size_t)(bm + row)*K + k0 + c4*8, 16);
            cpa16(sbase + (s*STAGE_W + BA_OFF + row*B_W + c4*4)*4,
                  Bp + ((size_t)kt*N + bn + row)*32 + c4*8, 16);
        }
        cpa_commit();
    };

    copy(0, 0);
    if (KT > 1) copy(1, 1);
    for (int kt = 0; kt < KT; kt++) {
        if (kt + 1 < KT) cpa_wait1(); else cpa_wait0();
        __syncthreads();
        if (kt + 2 < KT) copy(kt + 2, (kt + 2) % 3);
        const uint32_t* As = dynsm + (kt % 3)*STAGE_W;
        const uint32_t* Bt = As + BA_OFF;
        #pragma unroll
        for (int kk = 0; kk < 2; kk++) {
            uint32_t af[2][4], bf[8][2];
            #pragma unroll
            for (int mt = 0; mt < 2; mt++) {
                int r1 = wm*32 + mt*16 + g, r2 = r1 + 8;
                int xa = ((r1 >> 1) & 3)*4;
                af[mt][0] = As[r1*A_W + ((8*kk + tig) ^ xa)];
                af[mt][1] = As[r2*A_W + ((8*kk + tig) ^ xa)];
                af[mt][2] = As[r1*A_W + ((8*kk + tig + 4) ^ xa)];
                af[mt][3] = As[r2*A_W + ((8*kk + tig + 4) ^ xa)];
            }
            #pragma unroll
            for (int nt = 0; nt < 8; nt++) {
                int c0 = wn*64 + nt*8 + g;
                uint2 bv = *(const uint2*)&Bt[c0*B_W + 8*kk + 2*tig];
                bf[nt][0] = bv.x; bf[nt][1] = bv.y;
            }
            #pragma unroll
            for (int mt = 0; mt < 2; mt++)
                #pragma unroll
                for (int nt = 0; nt < 8; nt++)
                    mma16(acc[mt][nt], af[mt], bf[nt]);
        }
    }

    if (MODE != 4) {
        #pragma unroll
        for (int mt = 0; mt < 2; mt++) {
            int row = bm + wm*32 + mt*16 + g;
            #pragma unroll
            for (int nt = 0; nt < 8; nt++) {
                int col = bn + wn*64 + nt*8 + tig*2;
                float2 v0 = make_float2(acc[mt][nt][0], acc[mt][nt][1]);
                float2 v1 = make_float2(acc[mt][nt][2], acc[mt][nt][3]);
                if (MODE == 1) {
                    float b0 = bias[col], b1v = bias[col + 1];
                    v0.x += b0; v0.y += b1v; v1.x += b0; v1.y += b1v;
                }
                *(float2*)(C + (size_t)row*N + col) = v0;
                *(float2*)(C + (size_t)(row + 8)*N + col) = v1;
            }
        }
    } else {
        float gg = gate[0];
        #pragma unroll
        for (int mt = 0; mt < 2; mt++) {
            int row = bm + wm*32 + mt*16 + g;
            #pragma unroll
            for (int nt = 0; nt < 8; nt++) {
                int col = bn + wn*64 + nt*8 + tig*2;
                float a0 = acc[mt][nt][0], a1 = acc[mt][nt][1];
                float b0 = acc[mt][nt][2], b1 = acc[mt][nt][3];
                float s0 = a0 + a1, s1 = b0 + b1;
                s0 += __shfl_xor_sync(0xffffffffu, s0, 1);
                s0 += __shfl_xor_sync(0xffffffffu, s0, 2);
                s1 += __shfl_xor_sync(0xffffffffu, s1, 1);
                s1 += __shfl_xor_sync(0xffffffffu, s1, 2);
                float m0 = s0 * 0.125f, m1 = s1 * 0.125f;
                float d00 = a0 - m0, d01 = a1 - m0, d10 = b0 - m1, d11 = b1 - m1;
                float q0 = d00*d00 + d01*d01, q1 = d10*d10 + d11*d11;
                q0 += __shfl_xor_sync(0xffffffffu, q0, 1);
                q0 += __shfl_xor_sync(0xffffffffu, q0, 2);
                q1 += __shfl_xor_sync(0xffffffffu, q1, 1);
                q1 += __shfl_xor_sync(0xffffffffu, q1, 2);
                float i0 = rsqrtf(q0*0.125f + 1e-5f), i1 = rsqrtf(q1*0.125f + 1e-5f);
                size_t o0 = (size_t)row*N + col, o1 = (size_t)(row + 8)*N + col;
                float2 x0 = *(float2*)(xg + o0), x1 = *(float2*)(xg + o1);
                x0.x += gg * d00 * i0; x0.y += gg * d01 * i0;
                x1.x += gg * d10 * i1; x1.y += gg * d11 * i1;
                *(float2*)(xg + o0) = x0;
                *(float2*)(xg + o1) = x1;
                *(__half2*)(xs + o0) = __floats2half2_rn(x0.x, x0.y);
                *(__half2*)(xs + o1) = __floats2half2_rn(x1.x, x1.y);
            }
        }
    }
}

// ============ fp16 conv3x3 implicit GEMM, 3-stage ============
template<int MODE>   // 0 plain, 1 bias+temb+silu
__global__ __launch_bounds__(256, 2) void k_pconv(
    const __half* __restrict__ In, const __half* __restrict__ Wp,
    const float* __restrict__ bias, const float* __restrict__ temb,
    const float* __restrict__ gate, float* __restrict__ Out) {
    extern __shared__ uint32_t dynsm[];
    uint32_t sbase = (uint32_t)__cvta_generic_to_shared(dynsm);
    int tid = threadIdx.x, lane = tid & 31, wid = tid >> 5;
    int g = lane >> 2, tig = lane & 3;
    int wm = wid >> 1, wn = wid & 1;
    int bn = blockIdx.x * 128, bm = blockIdx.y * 128;
    float acc[2][8][4] = {};

    int pb[2], pfy[2], pfx[2];
    #pragma unroll
    for (int i = 0; i < 2; i++) {
        int p = bm + ((tid + i*256) >> 2);
        pb[i] = p >> 14; pfy[i] = (p >> 8) & 63; pfx[i] = p & 255;
    }

    auto copy = [&](int kt, int s) {
        int k0 = kt << 5;
        int kyx = k0 >> 8, ci0 = k0 & 255;
        int ky = kyx / 3, kx = kyx - ky*3;
        #pragma unroll
        for (int i = 0; i < 2; i++) {
            int idx = tid + i*256;
            int row = idx >> 2, c4 = idx & 3;
            int fy2 = pfy[i] + ky - 1, fx2 = pfx[i] + kx - 1;
            bool v = ((unsigned)fy2 < 64u) && ((unsigned)fx2 < 256u);
            cpa16(sbase + (s*STAGE_W + row*A_W + ((c4*4) ^ (((row >> 1) & 3)*4)))*4,
                  In + (((size_t)(pb[i]*64 + (v?fy2:0)))*256 + (v?fx2:0))*256 + ci0 + c4*8,
                  v ? 16 : 0);
            cpa16(sbase + (s*STAGE_W + BA_OFF + row*B_W + c4*4)*4,
                  Wp + ((size_t)kt*256 + bn + row)*32 + c4*8, 16);
        }
        cpa_commit();
    };

    copy(0, 0); copy(1, 1);
    for (int kt = 0; kt < 72; kt++) {
        if (kt + 1 < 72) cpa_wait1(); else cpa_wait0();
        __syncthreads();
        if (kt + 2 < 72) copy(kt + 2, (kt + 2) % 3);
        const uint32_t* As = dynsm + (kt % 3)*STAGE_W;
        const uint32_t* Bt = As + BA_OFF;
        #pragma unroll
        for (int kk = 0; kk < 2; kk++) {
            uint32_t af[2][4], bf[8][2];
            #pragma unroll
            for (int mt = 0; mt < 2; mt++) {
                int r1 = wm*32 + mt*16 + g, r2 = r1 + 8;
                int xa = ((r1 >> 1) & 3)*4;
                af[mt][0] = As[r1*A_W + ((8*kk + tig) ^ xa)];
                af[mt][1] = As[r2*A_W + ((8*kk + tig) ^ xa)];
                af[mt][2] = As[r1*A_W + ((8*kk + tig + 4) ^ xa)];
                af[mt][3] = As[r2*A_W + ((8*kk + tig + 4) ^ xa)];
            }
            #pragma unroll
            for (int nt = 0; nt < 8; nt++) {
                int c0 = wn*64 + nt*8 + g;
                uint2 bv = *(const uint2*)&Bt[c0*B_W + 8*kk + 2*tig];
                bf[nt][0] = bv.x; bf[nt][1] = bv.y;
            }
            #pragma unroll
            for (int mt = 0; mt < 2; mt++)
                #pragma unroll
                for (int nt = 0; nt < 8; nt++)
                    mma16(acc[mt][nt], af[mt], bf[nt]);
        }
    }
    float gd = (MODE == 1) ? gate[0] : 0.f;
    #pragma unroll
    for (int mt = 0; mt < 2; mt++) {
        int row = bm + wm*32 + mt*16 + g;
        int bidx = row >> 14;
        #pragma unroll
        for (int nt = 0; nt < 8; nt++) {
            int col = bn + wn*64 + nt*8 + tig*2;
            float v[4] = {acc[mt][nt][0], acc[mt][nt][1], acc[mt][nt][2], acc[mt][nt][3]};
            if (MODE == 1) {
                float a0 = bias[col]     + gd * temb[bidx*256 + col];
                float a1 = bias[col + 1] + gd * temb[bidx*256 + col + 1];
                v[0] += a0; v[1] += a1; v[2] += a0; v[3] += a1;
                #pragma unroll
                for (int j = 0; j < 4; j++) v[j] = v[j] / (1.f + __expf(-v[j]));
            }
            *(float2*)(Out + (size_t)row*256 + col) = make_float2(v[0], v[1]);
            *(float2*)(Out + (size_t)(row + 8)*256 + col) = make_float2(v[2], v[3]);
        }
    }
}

// ---------------- merged weight prepack (half, interleaved tile order) ----------------
__device__ __forceinline__ void prep_gemm(const float* __restrict__ W, __half* __restrict__ P,
                                          int NP, int coff, int srcN, int li) {
    int pos = li & 31;
    int rest = li >> 5;
    int n = rest % NP;
    int kt = rest / NP;
    int k = kt*32 + kHalfOfPos(pos);
    P[li] = h2f(W[(size_t)k * srcN + coff + n]);
}
__device__ __forceinline__ void prep_conv(const float* __restrict__ w, __half* __restrict__ P, int li) {
    int pos = li & 31;
    int rest = li >> 5;
    int co = rest & 255;
    int kt = rest >> 8;
    int k = kt*32 + kHalfOfPos(pos);
    int kyx = k >> 8, ci = k & 255;
    P[li] = h2f(w[(size_t)co * 2304 + ci * 9 + kyx]);
}
__global__ void k_prep_all(
    const float* __restrict__ w1, const float* __restrict__ w2,
    const float* __restrict__ qkv2w, const float* __restrict__ out2w,
    const float* __restrict__ qkv3w, const float* __restrict__ out3w,
    const float* __restrict__ lsaqw, const float* __restrict__ lsaow,
    __half* wt1, __half* wt2, __half* wq2, __half* wo2, __half* wq3kv, __half* wq3q,
    __half* wo3, __half* wq4, __half* wo4) {
    int idx = blockIdx.x * 256 + threadIdx.x;
    if      (idx < 589824)  prep_conv(w1, wt1, idx);
    else if (idx < 1179648) prep_conv(w2, wt2, idx - 589824);
    else if (idx < 1376256) prep_gemm(qkv2w, wq2, 768, 0, 768, idx - 1179648);
    else if (idx < 1441792) prep_gemm(out2w, wo2, 256, 0, 256, idx - 1376256);
    else if (idx < 1572864) prep_gemm(qkv3w, wq3kv, 512, 256, 768, idx - 1441792);
    else if (idx < 1638400) prep_gemm(qkv3w, wq3q, 256, 0, 768, idx - 1572864);
    else if (idx < 1703936) prep_gemm(out3w, wo3, 256, 0, 256, idx - 1638400);
    else if (idx < 1900544) prep_gemm(lsaqw, wq4, 768, 0, 768, idx - 1703936);
    else if (idx < 1966080) prep_gemm(lsaow, wo4, 256, 0, 256, idx - 1900544);
}

// ---------------- transposes ----------------
__global__ void k_nchw_to_nhwc(const float* __restrict__ in, float* __restrict__ out) {
    __shared__ float tile[32][33];
    int bfq = blockIdx.z, b = bfq >> 6, fq = bfq & 63;
    int t0 = blockIdx.x * 32, c0 = blockIdx.y * 32;
    for (int r = threadIdx.y; r < 32; r += 8)
        tile[r][threadIdx.x] = in[(((size_t)b*256 + c0 + r)*64 + fq)*256 + t0 + threadIdx.x];
    __syncthreads();
    for (int r = threadIdx.y; r < 32; r += 8)
        out[((size_t)bfq*256 + t0 + r)*256 + c0 + threadIdx.x] = tile[threadIdx.x][r];
}

__global__ void k_nhwc_to_nchw_add(const float* __restrict__ xa, const float* __restrict__ xb,
                                   float* __restrict__ out) {
    __shared__ float tile[32][33];
    int bfq = blockIdx.z, b = bfq >> 6, fq = bfq & 63;
    int t0 = blockIdx.x * 32, c0 = blockIdx.y * 32;
    for (int r = threadIdx.y; r < 32; r += 8) {
        size_t p = ((size_t)bfq*256 + t0 + r)*256 + c0 + threadIdx.x;
        tile[r][threadIdx.x] = xa[p] + xb[p];
    }
    __syncthreads();
    for (int r = threadIdx.y; r < 32; r += 8)
        out[(((size_t)b*256 + c0 + r)*64 + fq)*256 + t0 + threadIdx.x] = tile[threadIdx.x][r];
}

// ================= GroupNorm, 3-phase coalesced =================
__global__ void k_gnstat1(const float* __restrict__ in, int inst) {
    __shared__ float sc[256], sq[256];
    int blk = blockIdx.x;
    int b = blk >> 8, chunk = blk & 255;
    const float* base = in + ((size_t)b*16384 + chunk*64) * 256;
    int c = threadIdx.x;
    float s = 0.f, s2 = 0.f;
    for (int t = 0; t < 64; t++) {
        float v = base[(size_t)t*256 + c];
        s += v; s2 += v*v;
    }
    sc[c] = s; sq[c] = s2;
    __syncthreads();
    if (c < 32) {
        float S = 0.f, S2 = 0.f;
        #pragma unroll
        for (int j = 0; j < 8; j++) { S += sc[c*8 + j]; S2 += sq[c*8 + j]; }
        float* p = g_part + ((size_t)(inst*128 + b*32 + c)*256 + chunk)*2;
        p[0] = S; p[1] = S2;
    }
}
__global__ void k_gnstat2(int inst, float eps) {
    __shared__ float rs[64];
    int bg = blockIdx.x;
    int tid = threadIdx.x;
    const float* p = g_part + ((size_t)(inst*128 + bg)*256 + tid)*2;
    float s = p[0], s2 = p[1];
    int lane = tid & 31, w = tid >> 5;
    #pragma unroll
    for (int o = 16; o; o >>= 1) {
        s  += __shfl_down_sync(0xffffffffu, s,  o);
        s2 += __shfl_down_sync(0xffffffffu, s2, o);
    }
    if (lane == 0) { rs[w] = s; rs[32 + w] = s2; }
    __syncthreads();
    if (tid == 0) {
        float S = 0.f, S2 = 0.f;
        for (int i = 0; i < 8; i++) { S += rs[i]; S2 += rs[32 + i]; }
        float mean = S * (1.f/131072.f);
        float var  = S2 * (1.f/131072.f) - mean*mean;
        g_stat[(inst*128 + bg)*2]     = mean;
        g_stat[(inst*128 + bg)*2 + 1] = rsqrtf(var + eps);
    }
}
// normalize -> half out (matmul A operand)
__global__ void k_gnapply(const float* __restrict__ in, __half* __restrict__ out, int inst) {
    __shared__ float ms[32], is[32];
    int p0 = blockIdx.x * 16;
    int b = p0 >> 14;
    if (threadIdx.x < 32) {
        ms[threadIdx.x] = g_stat[(inst*128 + b*32 + threadIdx.x)*2];
        is[threadIdx.x] = g_stat[(inst*128 + b*32 + threadIdx.x)*2 + 1];
    }
    __syncthreads();
    for (int i = threadIdx.x; i < 1024; i += 256) {
        int c4 = i & 63, g = c4 >> 1;
        size_t off = (size_t)p0*256 + (size_t)i*4;
        float4 v = *(const float4*)(in + off);
        float m = ms[g], iv = is[g];
        __half2 h0 = __floats2half2_rn((v.x-m)*iv, (v.y-m)*iv);
        __half2 h1 = __floats2half2_rn((v.z-m)*iv, (v.w-m)*iv);
        *(__half2*)(out + off)     = h0;
        *(__half2*)(out + off + 2) = h1;
    }
}
// x += gate * hn; write half shadow
__global__ void k_gnaxapply(const float* __restrict__ hf, float* __restrict__ x,
                            __half* __restrict__ hs, const float* __restrict__ gate, int inst) {
    __shared__ float ms[32], is[32];
    int p0 = blockIdx.x * 16;
    int b = p0 >> 14;
    if (threadIdx.x < 32) {
        ms[threadIdx.x] = g_stat[(inst*128 + b*32 + threadIdx.x)*2];
        is[threadIdx.x] = g_stat[(inst*128 + b*32 + threadIdx.x)*2 + 1];
    }
    __syncthreads();
    float gg = gate[0];
    for (int i = threadIdx.x; i < 1024; i += 256) {
        int c4 = i & 63, g = c4 >> 1;
        size_t off = (size_t)p0*256 + (size_t)i*4;
        float4 h = *(const float4*)(hf + off);
        float4 xv = *(float4*)(x + off);
        float m = ms[g], iv = is[g];
        xv.x += gg*(h.x-m)*iv; xv.y += gg*(h.y-m)*iv;
        xv.z += gg*(h.z-m)*iv; xv.w += gg*(h.w-m)*iv;
        *(float4*)(x + off) = xv;
        *(__half2*)(hs + off)     = __floats2half2_rn(xv.x, xv.y);
        *(__half2*)(hs + off + 2) = __floats2half2_rn(xv.z, xv.w);
    }
}

// ---------------- layer2 attention over Fq per (b,t,h); half out ----------------
__global__ void k_attn_freq(const float* __restrict__ qkv, __half* __restrict__ y) {
    __shared__ float q[64][33], kk[64][33], v[64][33];
    __shared__ float S[64][65];
    int bt = blockIdx.x, h = blockIdx.y;
    int b = bt >> 8, t = bt & 255;
    int tid = threadIdx.x;
    for (int i = tid; i < 2048; i += 128) {
        int fq = i >> 5, d = i & 31;
        size_t base = ((size_t)((b*64 + fq)*256 + t))*768 + h*32 + d;
        q[fq][d]  = qkv[base];
        kk[fq][d] = qkv[base + 256];
        v[fq][d]  = qkv[base + 512];
    }
    __syncthreads();
    const float scale = 0.17677669529663687f;
    for (int i = tid; i < 4096; i += 128) {
        int L = i >> 6, l = i & 63;
        float s = 0.f;
        #pragma unroll
        for (int d = 0; d < 32; d++) s += q[L][d] * kk[l][d];
        S[L][l] = s * scale;
    }
    __syncthreads();
    if (tid < 64) {
        float m = -1e30f;
        for (int l = 0; l < 64; l++) m = fmaxf(m, S[tid][l]);
        float su = 0.f;
        for (int l = 0; l < 64; l++) { float e = __expf(S[tid][l] - m); S[tid][l] = e; su += e; }
        float r = 1.f / su;
        for (int l = 0; l < 64; l++) S[tid][l] *= r;
    }
    __syncthreads();
    for (int i = tid; i < 2048; i += 128) {
        int L = i >> 5, d = i & 31;
        float s = 0.f;
        #pragma unroll
        for (int l = 0; l < 64; l++) s += S[L][l] * v[l][d];
        y[((size_t)((b*64 + L)*256 + t))*256 + h*32 + d] = h2f(s);
    }
}

// ---------------- layer3 attention: precomputed q, KV-only [NTOK,512]; half out -----
__global__ void k_attn_time2(const float* __restrict__ kv, const float* __restrict__ q3,
                             __half* __restrict__ yout) {
    __shared__ float qs[32];
    __shared__ float part[8][32];
    __shared__ float prob[256];
    __shared__ float redm[8], reds[8];
    int bfq = blockIdx.x, h = blockIdx.y;
    int tid = threadIdx.x;
    size_t tokbase = (size_t)bfq * 256;
    int d = tid & 31, grp = tid >> 5;
    if (tid < 32) qs[tid] = q3[bfq*256 + h*32 + tid];
    __syncthreads();
    const float* kr = kv + (tokbase + tid)*512 + h*32;
    float sc = 0.f;
    #pragma unroll
    for (int dd = 0; dd < 32; dd++) sc += qs[dd] * kr[dd];
    sc *= 0.17677669529663687f;
    float m = sc;
    #pragma unroll
    for (int o = 16; o; o >>= 1) m = fmaxf(m, __shfl_xor_sync(0xffffffffu, m, o));
    if ((tid & 31) == 0) redm[grp] = m;
    __syncthreads();
    float M = redm[0];
    #pragma unroll
    for (int g = 1; g < 8; g++) M = fmaxf(M, redm[g]);
    float e = __expf(sc - M);
    float su = e;
    #pragma unroll
    for (int o = 16; o; o >>= 1) su += __shfl_xor_sync(0xffffffffu, su, o);
    if ((tid & 31) == 0) reds[grp] = su;
    __syncthreads();
    float Ssum = 0.f;
    #pragma unroll
    for (int g = 0; g < 8; g++) Ssum += reds[g];
    prob[tid] = e / Ssum;
    __syncthreads();
    float acc = 0.f;
    for (int t = grp; t < 256; t += 8)
        acc += prob[t] * kv[(tokbase + t)*512 + 256 + h*32 + d];
    part[grp][d] = acc;
    __syncthreads();
    if (tid < 32) {
        float ss = 0.f;
        #pragma unroll
        for (int g = 0; g < 8; g++) ss += part[g][tid];
        yout[(size_t)bfq*256 + h*32 + tid] = h2f(ss);
    }
}

// ---------------- mean over T of half shadow -> half ----------------
__global__ void k_meanx(const __half* __restrict__ xs, __half* __restrict__ qm) {
    int bfq = blockIdx.x, c = threadIdx.x;
    const __half* p = xs + (size_t)bfq * 65536 + c;
    float s = 0.f;
    for (int t = 0; t < 256; t++) s += __half2float(p[(size_t)t * 256]);
    qm[bfq*256 + c] = h2f(s * (1.f/256.f));
}

// ---------------- layer3 epilogue ----------------
__global__ void k_gn_bcast_add(const float* __restrict__ yv, float* __restrict__ x,
                               const float* __restrict__ gate) {
    __shared__ float yn[256];
    int bfq = blockIdx.x, tid = threadIdx.x;
    if (tid < 32) {
        const float* r = yv + bfq*256 + tid*8;
        float vals[8];
        #pragma unroll
        for (int j = 0; j < 8; j++) vals[j] = r[j];
        float m = 0.f;
        #pragma unroll
        for (int j = 0; j < 8; j++) m += vals[j];
        m *= 0.125f;
        float var = 0.f;
        #pragma unroll
        for (int j = 0; j < 8; j++) { float dd = vals[j] - m; var += dd * dd; }
        var *= 0.125f;
        float inv = rsqrtf(var + 1e-5f);
        #pragma unroll
        for (int j = 0; j < 8; j++) yn[tid*8 + j] = (vals[j] - m) * inv;
    }
    __syncthreads();
    float add = gate[0] * yn[tid];
    float* xp = x + (size_t)bfq * 65536 + tid;
    for (int t = 0; t < 256; t++) xp[(size_t)t * 256] += add;
}

// ---------------- layer4 LSA; half out ----------------
__global__ void k_attn_lsa(const float* __restrict__ qkv, __half* __restrict__ y) {
    __shared__ float q[16][33], kk[16][33], v[16][33];
    __shared__ float S[16][17];
    int blk = blockIdx.x;
    size_t p0 = (size_t)(blk >> 4) * 256 + (blk & 15) * 16;
    int tid = threadIdx.x;
    int qi = tid >> 4, kj = tid & 15;
    const float scale = 0.17677669529663687f;
    for (int h = 0; h < 8; h++) {
        for (int i = tid; i < 512; i += 256) {
            int r = i >> 5, d = i & 31;
            size_t a = (p0 + r)*768 + h*32 + d;
            q[r][d] = qkv[a]; kk[r][d] = qkv[a + 256]; v[r][d] = qkv[a + 512];
        }
        __syncthreads();
        float s = 0.f;
        #pragma unroll
        for (int d = 0; d < 32; d++) s += q[qi][d] * kk[kj][d];
        S[qi][kj] = s * scale;
        __syncthreads();
        if (tid < 16) {
            float m = -1e30f;
            for (int j = 0; j < 16; j++) m = fmaxf(m, S[tid][j]);
            float su = 0.f;
            for (int j = 0; j < 16; j++) { float e = __expf(S[tid][j] - m); S[tid][j] = e; su += e; }
            float r = 1.f / su;
            for (int j = 0; j < 16; j++) S[tid][j] *= r;
        }
        __syncthreads();
        for (int i = tid; i < 512; i += 256) {
            int r = i >> 5, d = i & 31;
            float s2 = 0.f;
            #pragma unroll
            for (int j = 0; j < 16; j++) s2 += S[r][j] * v[j][d];
            y[(p0 + r)*256 + h*32 + d] = h2f(s2);
        }
        __syncthreads();
    }
}

// =====================================================================================
extern "C" void kernel_launch(void* const* d_in, const int* in_sizes, int n_in,
                              void* d_out, int out_size) {
    const float* x     = (const float*)d_in[0];
    const float* temb  = (const float*)d_in[1];
    const float* w1    = (const float*)d_in[2];
    const float* b1    = (const float*)d_in[3];
    const float* w2    = (const float*)d_in[4];
    const float* gdiff = (const float*)d_in[5];
    const float* gres  = (const float*)d_in[6];
    const float* g2    = (const float*)d_in[7];
    const float* g3    = (const float*)d_in[8];
    const float* qkv2w = (const float*)d_in[9];
    const float* qkv2b = (const float*)d_in[10];
    const float* out2w = (const float*)d_in[11];
    const float* qkv3w = (const float*)d_in[12];
    const float* qkv3b = (const float*)d_in[13];
    const float* out3w = (const float*)d_in[14];
    const float* lsaqw = (const float*)d_in[15];
    const float* lsaow = (const float*)d_in[16];
    float* out = (float*)d_out;

    float *px, *phf, *pqkv, *pa3b, *pq3;
    __half *pha, *phs, *pya, *pa3, *pqm;
    __half *pwt, *pwt2, *pwq2, *pwo2, *pwq3, *pwq3q, *pwo3, *pwq4, *pwo4;
    cudaGetSymbolAddress((void**)&px,    g_x);
    cudaGetSymbolAddress((void**)&phf,   g_hf);
    cudaGetSymbolAddress((void**)&pha,   g_ha);
    cudaGetSymbolAddress((void**)&phs,   g_hs);
    cudaGetSymbolAddress((void**)&pya,   g_ya);
    cudaGetSymbolAddress((void**)&pqkv,  g_qkv);
    cudaGetSymbolAddress((void**)&pa3,   g_a3);
    cudaGetSymbolAddress((void**)&pa3b,  g_a3b);
    cudaGetSymbolAddress((void**)&pqm,   g_qm);
    cudaGetSymbolAddress((void**)&pq3,   g_q3);
    cudaGetSymbolAddress((void**)&pwt,   g_wt);
    cudaGetSymbolAddress((void**)&pwt2,  g_wt2);
    cudaGetSymbolAddress((void**)&pwq2,  g_wq2);
    cudaGetSymbolAddress((void**)&pwo2,  g_wo2);
    cudaGetSymbolAddress((void**)&pwq3,  g_wq3);
    cudaGetSymbolAddress((void**)&pwq3q, g_wq3q);
    cudaGetSymbolAddress((void**)&pwo3,  g_wo3);
    cudaGetSymbolAddress((void**)&pwq4,  g_wq4);
    cudaGetSymbolAddress((void**)&pwo4,  g_wo4);

    cudaFuncSetAttribute(k_pgemm<0>, cudaFuncAttributeMaxDynamicSharedMemorySize, SMEM_MM);
    cudaFuncSetAttribute(k_pgemm<1>, cudaFuncAttributeMaxDynamicSharedMemorySize, SMEM_MM);
    cudaFuncSetAttribute(k_pgemm<4>, cudaFuncAttributeMaxDynamicSharedMemorySize, SMEM_MM);
    cudaFuncSetAttribute(k_pconv<0>, cudaFuncAttributeMaxDynamicSharedMemorySize, SMEM_MM);
    cudaFuncSetAttribute(k_pconv<1>, cudaFuncAttributeMaxDynamicSharedMemorySize, SMEM_MM);

    dim3 tb32(32, 8);

    k_prep_all<<<7680, 256>>>(w1, w2, qkv2w, out2w, qkv3w, out3w, lsaqw, lsaow,
                              pwt, pwt2, pwq2, pwo2, pwq3, pwq3q, pwo3, pwq4, pwo4);
    k_nchw_to_nhwc<<<dim3(8, 8, 256), tb32>>>(x, px);

    // ---- Residual block ----
    k_gnstat1<<<1024, 256>>>(px, 0);
    k_gnstat2<<<128, 256>>>(0, 1e-6f);
    k_gnapply<<<4096, 256>>>(px, pha, 0);
    k_pconv<1><<<dim3(2, 512), 256, SMEM_MM>>>(pha, pwt, b1, temb, gdiff, phf);
    k_gnstat1<<<1024, 256>>>(phf, 1);
    k_gnstat2<<<128, 256>>>(1, 1e-6f);
    k_gnapply<<<4096, 256>>>(phf, pha, 1);
    k_pconv<0><<<dim3(2, 512), 256, SMEM_MM>>>(pha, pwt2, nullptr, nullptr, nullptr, phf);
    k_gnstat1<<<1024, 256>>>(phf, 2);
    k_gnstat2<<<128, 256>>>(2, 1e-6f);
    k_gnaxapply<<<4096, 256>>>(phf, px, phs, gres, 2);   // px updated, phs = half shadow

    // ---- layer2 ----
    k_pgemm<1><<<dim3(6, 512), 256, SMEM_MM>>>(phs, pwq2, qkv2b, nullptr, pqkv,
                                               nullptr, nullptr, NTOK, 768, 256);
    k_attn_freq<<<dim3(1024, 8), 128>>>(pqkv, pya);
    k_pgemm<4><<<dim3(2, 512), 256, SMEM_MM>>>(pya, pwo2, nullptr, g2, nullptr,
                                               px, phs, NTOK, 256, 256);

    // ---- layer3 (q via mean-then-project) ----
    k_pgemm<1><<<dim3(4, 512), 256, SMEM_MM>>>(phs, pwq3, qkv3b + 256, nullptr, pqkv,
                                               nullptr, nullptr, NTOK, 512, 256);
    k_meanx<<<256, 256>>>(phs, pqm);
    k_pgemm<1><<<dim3(2, 2), 256, SMEM_MM>>>(pqm, pwq3q, qkv3b, nullptr, pq3,
                                             nullptr, nullptr, 256, 256, 256);
    k_attn_time2<<<dim3(256, 8), 256>>>(pqkv, pq3, pa3);
    k_pgemm<0><<<dim3(2, 2), 256, SMEM_MM>>>(pa3, pwo3, nullptr, nullptr, pa3b,
                                             nullptr, nullptr, 256, 256, 256);
    k_gn_bcast_add<<<256, 256>>>(pa3b, px, g3);

    // ---- layer4 ----
    k_gnstat1<<<1024, 256>>>(px, 3);
    k_gnstat2<<<128, 256>>>(3, 1e-5f);
    k_gnapply<<<4096, 256>>>(px, pha, 3);
    k_pgemm<0><<<dim3(6, 512), 256, SMEM_MM>>>(pha, pwq4, nullptr, nullptr, pqkv,
                                               nullptr, nullptr, NTOK, 768, 256);
    k_attn_lsa<<<4096, 256>>>(pqkv, pya);
    k_pgemm<0><<<dim3(2, 512), 256, SMEM_MM>>>(pya, pwo4, nullptr, nullptr, phf,
                                               nullptr, nullptr, NTOK, 256, 256);

    k_nhwc_to_nchw_add<<<dim3(8, 8, 256), tb32>>>(px, phf, out);
}

// round 16
// speedup vs baseline: 1.6010x; 1.0154x over previous
#include <cuda_runtime.h>
#include <cuda_fp16.h>
#include <cstdint>
#include <math.h>

// B=4, C=256, Fq=64, T=256, HEADS=8, Dh=32, GROUPS=32, WIN=16
#define NTOK   65536
#define ELEMS  16777216

// ---------------- scratch ----------------
__device__ float  g_x[ELEMS];        // fp32 master
__device__ float  g_hf[ELEMS];       // fp32: conv outs / out-proj outs
__device__ __half g_ha[ELEMS];       // half: GN outputs (matmul A)
__device__ __half g_hs[ELEMS];       // half: shadow of g_x (matmul A)
__device__ __half g_ya[ELEMS];       // half: attention outputs (matmul A)
__device__ __half g_qkv[3*ELEMS];    // half qkv / kv buffer
__device__ __half g_a3[65536];
__device__ float  g_a3b[65536];
__device__ __half g_qm[65536];
__device__ float  g_q3[65536];
__device__ __half g_wt[589824];
__device__ __half g_wt2[589824];
__device__ __half g_wq2[196608];
__device__ __half g_wo2[65536];
__device__ __half g_wq3[131072];     // KV-only (N=512)
__device__ __half g_wq3q[65536];
__device__ __half g_wo3[65536];
__device__ __half g_wq4[196608];
__device__ __half g_wo4[65536];
__device__ float  g_stat[4*128*2];
__device__ float  g_part[4*128*256*2];

// ---------------- helpers ----------------
__device__ __forceinline__ __half h2f(float x) { return __float2half_rn(x); }
__device__ __forceinline__ void mma16(float* d, const uint32_t* a, const uint32_t* b) {
    asm volatile("mma.sync.aligned.m16n8k16.row.col.f32.f16.f16.f32 "
        "{%0,%1,%2,%3}, {%4,%5,%6,%7}, {%8,%9}, {%0,%1,%2,%3};"
        : "+f"(d[0]), "+f"(d[1]), "+f"(d[2]), "+f"(d[3])
        : "r"(a[0]), "r"(a[1]), "r"(a[2]), "r"(a[3]), "r"(b[0]), "r"(b[1]));
}
__device__ __forceinline__ void cpa16(uint32_t dst, const void* src, int sz) {
    asm volatile("cp.async.cg.shared.global [%0], [%1], 16, %2;" :: "r"(dst), "l"(src), "r"(sz));
}
__device__ __forceinline__ void cpa_commit() { asm volatile("cp.async.commit_group;"); }
__device__ __forceinline__ void cpa_wait0()  { asm volatile("cp.async.wait_group 0;"); }
__device__ __forceinline__ void cpa_wait1()  { asm volatile("cp.async.wait_group 1;"); }

// packed half pos (0..31) -> local k within 32-k tile
__device__ __forceinline__ int kHalfOfPos(int pos) {
    int pw = pos >> 1, b = pos & 1;
    int group = pw >> 3, rem = pw & 7;
    int ow = group*8 + (rem >> 1) + 4*(rem & 1);
    return ow*2 + b;
}

// smem words: A rows 16 (XOR ((row>>1)&3)*4), B rows 24 (16 data + 8 pad)
#define A_W     16
#define B_W     24
#define BA_OFF  2048
#define STAGE_W 5120
#define SMEM_MM (3*STAGE_W*4)       // 61440 B -> 2 CTA/SM

// ============ fp16 GEMM: 128x128 tile, Kt=32, cp.async 3-stage ============
// MODE: 0 plain->fp32, 1 bias->fp32, 2 plain->half, 3 bias->half,
//       4 fused per-token GN + x+=gate*yn + half shadow
template<int MODE>
__global__ __launch_bounds__(256, 2) void k_pgemm(
    const __half* __restrict__ A, const __half* __restrict__ Bp,
    const float* __restrict__ bias, const float* __restrict__ gate,
    float* __restrict__ C, __half* __restrict__ Ch,
    float* __restrict__ xg, __half* __restrict__ xs,
    int M, int N, int K) {
    extern __shared__ uint32_t dynsm[];
    uint32_t sbase = (uint32_t)__cvta_generic_to_shared(dynsm);
    int tid = threadIdx.x, lane = tid & 31, wid = tid >> 5;
    int g = lane >> 2, tig = lane & 3;
    int wm = wid >> 1, wn = wid & 1;
    int bn = blockIdx.x * 128, bm = blockIdx.y * 128;
    float acc[2][8][4] = {};
    int KT = K >> 5;

    auto copy = [&](int kt, int s) {
        int k0 = kt << 5;
        #pragma unroll
        for (int i = 0; i < 2; i++) {
            int idx = tid + i*256;
            int row = idx >> 2, c4 = idx & 3;
            cpa16(sbase + (s*STAGE_W + row*A_W + ((c4*4) ^ (((row >> 1) & 3)*4)))*4,
                  A + (size_t)(bm + row)*K + k0 + c4*8, 16);
            cpa16(sbase + (s*STAGE_W + BA_OFF + row*B_W + c4*4)*4,
                  Bp + ((size_t)kt*N + bn + row)*32 + c4*8, 16);
        }
        cpa_commit();
    };

    copy(0, 0);
    if (KT > 1) copy(1, 1);
    for (int kt = 0; kt < KT; kt++) {
        if (kt + 1 < KT) cpa_wait1(); else cpa_wait0();
        __syncthreads();
        if (kt + 2 < KT) copy(kt + 2, (kt + 2) % 3);
        const uint32_t* As = dynsm + (kt % 3)*STAGE_W;
        const uint32_t* Bt = As + BA_OFF;
        #pragma unroll
        for (int kk = 0; kk < 2; kk++) {
            uint32_t af[2][4], bf[8][2];
            #pragma unroll
            for (int mt = 0; mt < 2; mt++) {
                int r1 = wm*32 + mt*16 + g, r2 = r1 + 8;
                int xa = ((r1 >> 1) & 3)*4;
                af[mt][0] = As[r1*A_W + ((8*kk + tig) ^ xa)];
                af[mt][1] = As[r2*A_W + ((8*kk + tig) ^ xa)];
                af[mt][2] = As[r1*A_W + ((8*kk + tig + 4) ^ xa)];
                af[mt][3] = As[r2*A_W + ((8*kk + tig + 4) ^ xa)];
            }
            #pragma unroll
            for (int nt = 0; nt < 8; nt++) {
                int c0 = wn*64 + nt*8 + g;
                uint2 bv = *(const uint2*)&Bt[c0*B_W + 8*kk + 2*tig];
                bf[nt][0] = bv.x; bf[nt][1] = bv.y;
            }
            #pragma unroll
            for (int mt = 0; mt < 2; mt++)
                #pragma unroll
                for (int nt = 0; nt < 8; nt++)
                    mma16(acc[mt][nt], af[mt], bf[nt]);
        }
    }

    if (MODE <= 3) {
        #pragma unroll
        for (int mt = 0; mt < 2; mt++) {
            int row = bm + wm*32 + mt*16 + g;
            #pragma unroll
            for (int nt = 0; nt < 8; nt++) {
                int col = bn + wn*64 + nt*8 + tig*2;
                float2 v0 = make_float2(acc[mt][nt][0], acc[mt][nt][1]);
                float2 v1 = make_float2(acc[mt][nt][2], acc[mt][nt][3]);
                if (MODE == 1 || MODE == 3) {
                    float b0 = bias[col], b1v = bias[col + 1];
                    v0.x += b0; v0.y += b1v; v1.x += b0; v1.y += b1v;
                }
                if (MODE <= 1) {
                    *(float2*)(C + (size_t)row*N + col) = v0;
                    *(float2*)(C + (size_t)(row + 8)*N + col) = v1;
                } else {
                    *(__half2*)(Ch + (size_t)row*N + col) = __floats2half2_rn(v0.x, v0.y);
                    *(__half2*)(Ch + (size_t)(row + 8)*N + col) = __floats2half2_rn(v1.x, v1.y);
                }
            }
        }
    } else {
        float gg = gate[0];
        #pragma unroll
        for (int mt = 0; mt < 2; mt++) {
            int row = bm + wm*32 + mt*16 + g;
            #pragma unroll
            for (int nt = 0; nt < 8; nt++) {
                int col = bn + wn*64 + nt*8 + tig*2;
                float a0 = acc[mt][nt][0], a1 = acc[mt][nt][1];
                float b0 = acc[mt][nt][2], b1 = acc[mt][nt][3];
                float s0 = a0 + a1, s1 = b0 + b1;
                s0 += __shfl_xor_sync(0xffffffffu, s0, 1);
                s0 += __shfl_xor_sync(0xffffffffu, s0, 2);
                s1 += __shfl_xor_sync(0xffffffffu, s1, 1);
                s1 += __shfl_xor_sync(0xffffffffu, s1, 2);
                float m0 = s0 * 0.125f, m1 = s1 * 0.125f;
                float d00 = a0 - m0, d01 = a1 - m0, d10 = b0 - m1, d11 = b1 - m1;
                float q0 = d00*d00 + d01*d01, q1 = d10*d10 + d11*d11;
                q0 += __shfl_xor_sync(0xffffffffu, q0, 1);
                q0 += __shfl_xor_sync(0xffffffffu, q0, 2);
                q1 += __shfl_xor_sync(0xffffffffu, q1, 1);
                q1 += __shfl_xor_sync(0xffffffffu, q1, 2);
                float i0 = rsqrtf(q0*0.125f + 1e-5f), i1 = rsqrtf(q1*0.125f + 1e-5f);
                size_t o0 = (size_t)row*N + col, o1 = (size_t)(row + 8)*N + col;
                float2 x0 = *(float2*)(xg + o0), x1 = *(float2*)(xg + o1);
                x0.x += gg * d00 * i0; x0.y += gg * d01 * i0;
                x1.x += gg * d10 * i1; x1.y += gg * d11 * i1;
                *(float2*)(xg + o0) = x0;
                *(float2*)(xg + o1) = x1;
                *(__half2*)(xs + o0) = __floats2half2_rn(x0.x, x0.y);
                *(__half2*)(xs + o1) = __floats2half2_rn(x1.x, x1.y);
            }
        }
    }
}

// ============ fp16 conv3x3 implicit GEMM, 3-stage ============
template<int MODE>   // 0 plain, 1 bias+temb+silu
__global__ __launch_bounds__(256, 2) void k_pconv(
    const __half* __restrict__ In, const __half* __restrict__ Wp,
    const float* __restrict__ bias, const float* __restrict__ temb,
    const float* __restrict__ gate, float* __restrict__ Out) {
    extern __shared__ uint32_t dynsm[];
    uint32_t sbase = (uint32_t)__cvta_generic_to_shared(dynsm);
    int tid = threadIdx.x, lane = tid & 31, wid = tid >> 5;
    int g = lane >> 2, tig = lane & 3;
    int wm = wid >> 1, wn = wid & 1;
    int bn = blockIdx.x * 128, bm = blockIdx.y * 128;
    float acc[2][8][4] = {};

    int pb[2], pfy[2], pfx[2];
    #pragma unroll
    for (int i = 0; i < 2; i++) {
        int p = bm + ((tid + i*256) >> 2);
        pb[i] = p >> 14; pfy[i] = (p >> 8) & 63; pfx[i] = p & 255;
    }

    auto copy = [&](int kt, int s) {
        int k0 = kt << 5;
        int kyx = k0 >> 8, ci0 = k0 & 255;
        int ky = kyx / 3, kx = kyx - ky*3;
        #pragma unroll
        for (int i = 0; i < 2; i++) {
            int idx = tid + i*256;
            int row = idx >> 2, c4 = idx & 3;
            int fy2 = pfy[i] + ky - 1, fx2 = pfx[i] + kx - 1;
            bool v = ((unsigned)fy2 < 64u) && ((unsigned)fx2 < 256u);
            cpa16(sbase + (s*STAGE_W + row*A_W + ((c4*4) ^ (((row >> 1) & 3)*4)))*4,
                  In + (((size_t)(pb[i]*64 + (v?fy2:0)))*256 + (v?fx2:0))*256 + ci0 + c4*8,
                  v ? 16 : 0);
            cpa16(sbase + (s*STAGE_W + BA_OFF + row*B_W + c4*4)*4,
                  Wp + ((size_t)kt*256 + bn + row)*32 + c4*8, 16);
        }
        cpa_commit();
    };

    copy(0, 0); copy(1, 1);
    for (int kt = 0; kt < 72; kt++) {
        if (kt + 1 < 72) cpa_wait1(); else cpa_wait0();
        __syncthreads();
        if (kt + 2 < 72) copy(kt + 2, (kt + 2) % 3);
        const uint32_t* As = dynsm + (kt % 3)*STAGE_W;
        const uint32_t* Bt = As + BA_OFF;
        #pragma unroll
        for (int kk = 0; kk < 2; kk++) {
            uint32_t af[2][4], bf[8][2];
            #pragma unroll
            for (int mt = 0; mt < 2; mt++) {
                int r1 = wm*32 + mt*16 + g, r2 = r1 + 8;
                int xa = ((r1 >> 1) & 3)*4;
                af[mt][0] = As[r1*A_W + ((8*kk + tig) ^ xa)];
                af[mt][1] = As[r2*A_W + ((8*kk + tig) ^ xa)];
                af[mt][2] = As[r1*A_W + ((8*kk + tig + 4) ^ xa)];
                af[mt][3] = As[r2*A_W + ((8*kk + tig + 4) ^ xa)];
            }
            #pragma unroll
            for (int nt = 0; nt < 8; nt++) {
                int c0 = wn*64 + nt*8 + g;
                uint2 bv = *(const uint2*)&Bt[c0*B_W + 8*kk + 2*tig];
                bf[nt][0] = bv.x; bf[nt][1] = bv.y;
            }
            #pragma unroll
            for (int mt = 0; mt < 2; mt++)
                #pragma unroll
                for (int nt = 0; nt < 8; nt++)
                    mma16(acc[mt][nt], af[mt], bf[nt]);
        }
    }
    float gd = (MODE == 1) ? gate[0] : 0.f;
    #pragma unroll
    for (int mt = 0; mt < 2; mt++) {
        int row = bm + wm*32 + mt*16 + g;
        int bidx = row >> 14;
        #pragma unroll
        for (int nt = 0; nt < 8; nt++) {
            int col = bn + wn*64 + nt*8 + tig*2;
            float v[4] = {acc[mt][nt][0], acc[mt][nt][1], acc[mt][nt][2], acc[mt][nt][3]};
            if (MODE == 1) {
                float a0 = bias[col]     + gd * temb[bidx*256 + col];
                float a1 = bias[col + 1] + gd * temb[bidx*256 + col + 1];
                v[0] += a0; v[1] += a1; v[2] += a0; v[3] += a1;
                #pragma unroll
                for (int j = 0; j < 4; j++) v[j] = v[j] / (1.f + __expf(-v[j]));
            }
            *(float2*)(Out + (size_t)row*256 + col) = make_float2(v[0], v[1]);
            *(float2*)(Out + (size_t)(row + 8)*256 + col) = make_float2(v[2], v[3]);
        }
    }
}

// ---------------- merged weight prepack ----------------
__device__ __forceinline__ void prep_gemm(const float* __restrict__ W, __half* __restrict__ P,
                                          int NP, int coff, int srcN, int li) {
    int pos = li & 31;
    int rest = li >> 5;
    int n = rest % NP;
    int kt = rest / NP;
    int k = kt*32 + kHalfOfPos(pos);
    P[li] = h2f(W[(size_t)k * srcN + coff + n]);
}
__device__ __forceinline__ void prep_conv(const float* __restrict__ w, __half* __restrict__ P, int li) {
    int pos = li & 31;
    int rest = li >> 5;
    int co = rest & 255;
    int kt = rest >> 8;
    int k = kt*32 + kHalfOfPos(pos);
    int kyx = k >> 8, ci = k & 255;
    P[li] = h2f(w[(size_t)co * 2304 + ci * 9 + kyx]);
}
__global__ void k_prep_all(
    const float* __restrict__ w1, const float* __restrict__ w2,
    const float* __restrict__ qkv2w, const float* __restrict__ out2w,
    const float* __restrict__ qkv3w, const float* __restrict__ out3w,
    const float* __restrict__ lsaqw, const float* __restrict__ lsaow,
    __half* wt1, __half* wt2, __half* wq2, __half* wo2, __half* wq3kv, __half* wq3q,
    __half* wo3, __half* wq4, __half* wo4) {
    int idx = blockIdx.x * 256 + threadIdx.x;
    if      (idx < 589824)  prep_conv(w1, wt1, idx);
    else if (idx < 1179648) prep_conv(w2, wt2, idx - 589824);
    else if (idx < 1376256) prep_gemm(qkv2w, wq2, 768, 0, 768, idx - 1179648);
    else if (idx < 1441792) prep_gemm(out2w, wo2, 256, 0, 256, idx - 1376256);
    else if (idx < 1572864) prep_gemm(qkv3w, wq3kv, 512, 256, 768, idx - 1441792);
    else if (idx < 1638400) prep_gemm(qkv3w, wq3q, 256, 0, 768, idx - 1572864);
    else if (idx < 1703936) prep_gemm(out3w, wo3, 256, 0, 256, idx - 1638400);
    else if (idx < 1900544) prep_gemm(lsaqw, wq4, 768, 0, 768, idx - 1703936);
    else if (idx < 1966080) prep_gemm(lsaow, wo4, 256, 0, 256, idx - 1900544);
}

// ---------------- transposes ----------------
__global__ void k_nchw_to_nhwc(const float* __restrict__ in, float* __restrict__ out) {
    __shared__ float tile[32][33];
    int bfq = blockIdx.z, b = bfq >> 6, fq = bfq & 63;
    int t0 = blockIdx.x * 32, c0 = blockIdx.y * 32;
    for (int r = threadIdx.y; r < 32; r += 8)
        tile[r][threadIdx.x] = in[(((size_t)b*256 + c0 + r)*64 + fq)*256 + t0 + threadIdx.x];
    __syncthreads();
    for (int r = threadIdx.y; r < 32; r += 8)
        out[((size_t)bfq*256 + t0 + r)*256 + c0 + threadIdx.x] = tile[threadIdx.x][r];
}

__global__ void k_nhwc_to_nchw_add(const float* __restrict__ xa, const float* __restrict__ xb,
                                   float* __restrict__ out) {
    __shared__ float tile[32][33];
    int bfq = blockIdx.z, b = bfq >> 6, fq = bfq & 63;
    int t0 = blockIdx.x * 32, c0 = blockIdx.y * 32;
    for (int r = threadIdx.y; r < 32; r += 8) {
        size_t p = ((size_t)bfq*256 + t0 + r)*256 + c0 + threadIdx.x;
        tile[r][threadIdx.x] = xa[p] + xb[p];
    }
    __syncthreads();
    for (int r = threadIdx.y; r < 32; r += 8)
        out[(((size_t)b*256 + c0 + r)*64 + fq)*256 + t0 + threadIdx.x] = tile[threadIdx.x][r];
}

// ================= GroupNorm, 3-phase coalesced =================
__global__ void k_gnstat1(const float* __restrict__ in, int inst) {
    __shared__ float sc[256], sq[256];
    int blk = blockIdx.x;
    int b = blk >> 8, chunk = blk & 255;
    const float* base = in + ((size_t)b*16384 + chunk*64) * 256;
    int c = threadIdx.x;
    float s = 0.f, s2 = 0.f;
    for (int t = 0; t < 64; t++) {
        float v = base[(size_t)t*256 + c];
        s += v; s2 += v*v;
    }
    sc[c] = s; sq[c] = s2;
    __syncthreads();
    if (c < 32) {
        float S = 0.f, S2 = 0.f;
        #pragma unroll
        for (int j = 0; j < 8; j++) { S += sc[c*8 + j]; S2 += sq[c*8 + j]; }
        float* p = g_part + ((size_t)(inst*128 + b*32 + c)*256 + chunk)*2;
        p[0] = S; p[1] = S2;
    }
}
__global__ void k_gnstat2(int inst, float eps) {
    __shared__ float rs[64];
    int bg = blockIdx.x;
    int tid = threadIdx.x;
    const float* p = g_part + ((size_t)(inst*128 + bg)*256 + tid)*2;
    float s = p[0], s2 = p[1];
    int lane = tid & 31, w = tid >> 5;
    #pragma unroll
    for (int o = 16; o; o >>= 1) {
        s  += __shfl_down_sync(0xffffffffu, s,  o);
        s2 += __shfl_down_sync(0xffffffffu, s2, o);
    }
    if (lane == 0) { rs[w] = s; rs[32 + w] = s2; }
    __syncthreads();
    if (tid == 0) {
        float S = 0.f, S2 = 0.f;
        for (int i = 0; i < 8; i++) { S += rs[i]; S2 += rs[32 + i]; }
        float mean = S * (1.f/131072.f);
        float var  = S2 * (1.f/131072.f) - mean*mean;
        g_stat[(inst*128 + bg)*2]     = mean;
        g_stat[(inst*128 + bg)*2 + 1] = rsqrtf(var + eps);
    }
}
__global__ void k_gnapply(const float* __restrict__ in, __half* __restrict__ out, int inst) {
    __shared__ float ms[32], is[32];
    int p0 = blockIdx.x * 16;
    int b = p0 >> 14;
    if (threadIdx.x < 32) {
        ms[threadIdx.x] = g_stat[(inst*128 + b*32 + threadIdx.x)*2];
        is[threadIdx.x] = g_stat[(inst*128 + b*32 + threadIdx.x)*2 + 1];
    }
    __syncthreads();
    for (int i = threadIdx.x; i < 1024; i += 256) {
        int c4 = i & 63, g = c4 >> 1;
        size_t off = (size_t)p0*256 + (size_t)i*4;
        float4 v = *(const float4*)(in + off);
        float m = ms[g], iv = is[g];
        *(__half2*)(out + off)     = __floats2half2_rn((v.x-m)*iv, (v.y-m)*iv);
        *(__half2*)(out + off + 2) = __floats2half2_rn((v.z-m)*iv, (v.w-m)*iv);
    }
}
__global__ void k_gnaxapply(const float* __restrict__ hf, float* __restrict__ x,
                            __half* __restrict__ hs, const float* __restrict__ gate, int inst) {
    __shared__ float ms[32], is[32];
    int p0 = blockIdx.x * 16;
    int b = p0 >> 14;
    if (threadIdx.x < 32) {
        ms[threadIdx.x] = g_stat[(inst*128 + b*32 + threadIdx.x)*2];
        is[threadIdx.x] = g_stat[(inst*128 + b*32 + threadIdx.x)*2 + 1];
    }
    __syncthreads();
    float gg = gate[0];
    for (int i = threadIdx.x; i < 1024; i += 256) {
        int c4 = i & 63, g = c4 >> 1;
        size_t off = (size_t)p0*256 + (size_t)i*4;
        float4 h = *(const float4*)(hf + off);
        float4 xv = *(float4*)(x + off);
        float m = ms[g], iv = is[g];
        xv.x += gg*(h.x-m)*iv; xv.y += gg*(h.y-m)*iv;
        xv.z += gg*(h.z-m)*iv; xv.w += gg*(h.w-m)*iv;
        *(float4*)(x + off) = xv;
        *(__half2*)(hs + off)     = __floats2half2_rn(xv.x, xv.y);
        *(__half2*)(hs + off + 2) = __floats2half2_rn(xv.z, xv.w);
    }
}

// ---------------- layer2 attention over Fq per (b,t,h); half in/out ----------------
__global__ void k_attn_freq(const __half* __restrict__ qkv, __half* __restrict__ y) {
    __shared__ float q[64][33], kk[64][33], v[64][33];
    __shared__ float S[64][65];
    int bt = blockIdx.x, h = blockIdx.y;
    int b = bt >> 8, t = bt & 255;
    int tid = threadIdx.x;
    for (int i = tid; i < 2048; i += 128) {
        int fq = i >> 5, d = i & 31;
        size_t base = ((size_t)((b*64 + fq)*256 + t))*768 + h*32 + d;
        q[fq][d]  = __half2float(qkv[base]);
        kk[fq][d] = __half2float(qkv[base + 256]);
        v[fq][d]  = __half2float(qkv[base + 512]);
    }
    __syncthreads();
    const float scale = 0.17677669529663687f;
    for (int i = tid; i < 4096; i += 128) {
        int L = i >> 6, l = i & 63;
        float s = 0.f;
        #pragma unroll
        for (int d = 0; d < 32; d++) s += q[L][d] * kk[l][d];
        S[L][l] = s * scale;
    }
    __syncthreads();
    if (tid < 64) {
        float m = -1e30f;
        for (int l = 0; l < 64; l++) m = fmaxf(m, S[tid][l]);
        float su = 0.f;
        for (int l = 0; l < 64; l++) { float e = __expf(S[tid][l] - m); S[tid][l] = e; su += e; }
        float r = 1.f / su;
        for (int l = 0; l < 64; l++) S[tid][l] *= r;
    }
    __syncthreads();
    for (int i = tid; i < 2048; i += 128) {
        int L = i >> 5, d = i & 31;
        float s = 0.f;
        #pragma unroll
        for (int l = 0; l < 64; l++) s += S[L][l] * v[l][d];
        y[((size_t)((b*64 + L)*256 + t))*256 + h*32 + d] = h2f(s);
    }
}

// ---------------- layer3 attention: precomputed q, half KV [NTOK,512] ----------
__global__ void k_attn_time2(const __half* __restrict__ kv, const float* __restrict__ q3,
                             __half* __restrict__ yout) {
    __shared__ float qs[32];
    __shared__ float part[8][32];
    __shared__ float prob[256];
    __shared__ float redm[8], reds[8];
    int bfq = blockIdx.x, h = blockIdx.y;
    int tid = threadIdx.x;
    size_t tokbase = (size_t)bfq * 256;
    int d = tid & 31, grp = tid >> 5;
    if (tid < 32) qs[tid] = q3[bfq*256 + h*32 + tid];
    __syncthreads();
    const __half* kr = kv + (tokbase + tid)*512 + h*32;
    float sc = 0.f;
    #pragma unroll
    for (int dd = 0; dd < 32; dd++) sc += qs[dd] * __half2float(kr[dd]);
    sc *= 0.17677669529663687f;
    float m = sc;
    #pragma unroll
    for (int o = 16; o; o >>= 1) m = fmaxf(m, __shfl_xor_sync(0xffffffffu, m, o));
    if ((tid & 31) == 0) redm[grp] = m;
    __syncthreads();
    float M = redm[0];
    #pragma unroll
    for (int g = 1; g < 8; g++) M = fmaxf(M, redm[g]);
    float e = __expf(sc - M);
    float su = e;
    #pragma unroll
    for (int o = 16; o; o >>= 1) su += __shfl_xor_sync(0xffffffffu, su, o);
    if ((tid & 31) == 0) reds[grp] = su;
    __syncthreads();
    float Ssum = 0.f;
    #pragma unroll
    for (int g = 0; g < 8; g++) Ssum += reds[g];
    prob[tid] = e / Ssum;
    __syncthreads();
    float acc = 0.f;
    for (int t = grp; t < 256; t += 8)
        acc += prob[t] * __half2float(kv[(tokbase + t)*512 + 256 + h*32 + d]);
    part[grp][d] = acc;
    __syncthreads();
    if (tid < 32) {
        float ss = 0.f;
        #pragma unroll
        for (int g = 0; g < 8; g++) ss += part[g][tid];
        yout[(size_t)bfq*256 + h*32 + tid] = h2f(ss);
    }
}

// ---------------- mean over T of half shadow -> half ----------------
__global__ void k_meanx(const __half* __restrict__ xs, __half* __restrict__ qm) {
    int bfq = blockIdx.x, c = threadIdx.x;
    const __half* p = xs + (size_t)bfq * 65536 + c;
    float s = 0.f;
    for (int t = 0; t < 256; t++) s += __half2float(p[(size_t)t * 256]);
    qm[bfq*256 + c] = h2f(s * (1.f/256.f));
}

// ---------------- layer3 epilogue ----------------
__global__ void k_gn_bcast_add(const float* __restrict__ yv, float* __restrict__ x,
                               const float* __restrict__ gate) {
    __shared__ float yn[256];
    int bfq = blockIdx.x, tid = threadIdx.x;
    if (tid < 32) {
        const float* r = yv + bfq*256 + tid*8;
        float vals[8];
        #pragma unroll
        for (int j = 0; j < 8; j++) vals[j] = r[j];
        float m = 0.f;
        #pragma unroll
        for (int j = 0; j < 8; j++) m += vals[j];
        m *= 0.125f;
        float var = 0.f;
        #pragma unroll
        for (int j = 0; j < 8; j++) { float dd = vals[j] - m; var += dd * dd; }
        var *= 0.125f;
        float inv = rsqrtf(var + 1e-5f);
        #pragma unroll
        for (int j = 0; j < 8; j++) yn[tid*8 + j] = (vals[j] - m) * inv;
    }
    __syncthreads();
    float add = gate[0] * yn[tid];
    float* xp = x + (size_t)bfq * 65536 + tid;
    for (int t = 0; t < 256; t++) xp[(size_t)t * 256] += add;
}

// ---------------- layer4 LSA; half in/out ----------------
__global__ void k_attn_lsa(const __half* __restrict__ qkv, __half* __restrict__ y) {
    __shared__ float q[16][33], kk[16][33], v[16][33];
    __shared__ float S[16][17];
    int blk = blockIdx.x;
    size_t p0 = (size_t)(blk >> 4) * 256 + (blk & 15) * 16;
    int tid = threadIdx.x;
    int qi = tid >> 4, kj = tid & 15;
    const float scale = 0.17677669529663687f;
    for (int h = 0; h < 8; h++) {
        for (int i = tid; i < 512; i += 256) {
            int r = i >> 5, d = i & 31;
            size_t a = (p0 + r)*768 + h*32 + d;
            q[r][d] = __half2float(qkv[a]);
            kk[r][d] = __half2float(qkv[a + 256]);
            v[r][d] = __half2float(qkv[a + 512]);
        }
        __syncthreads();
        float s = 0.f;
        #pragma unroll
        for (int d = 0; d < 32; d++) s += q[qi][d] * kk[kj][d];
        S[qi][kj] = s * scale;
        __syncthreads();
        if (tid < 16) {
            float m = -1e30f;
            for (int j = 0; j < 16; j++) m = fmaxf(m, S[tid][j]);
            float su = 0.f;
            for (int j = 0; j < 16; j++) { float e = __expf(S[tid][j] - m); S[tid][j] = e; su += e; }
            float r = 1.f / su;
            for (int j = 0; j < 16; j++) S[tid][j] *= r;
        }
        __syncthreads();
        for (int i = tid; i < 512; i += 256) {
            int r = i >> 5, d = i & 31;
            float s2 = 0.f;
            #pragma unroll
            for (int j = 0; j < 16; j++) s2 += S[r][j] * v[j][d];
            y[(p0 + r)*256 + h*32 + d] = h2f(s2);
        }
        __syncthreads();
    }
}

// =====================================================================================
extern "C" void kernel_launch(void* const* d_in, const int* in_sizes, int n_in,
                              void* d_out, int out_size) {
    const float* x     = (const float*)d_in[0];
    const float* temb  = (const float*)d_in[1];
    const float* w1    = (const float*)d_in[2];
    const float* b1    = (const float*)d_in[3];
    const float* w2    = (const float*)d_in[4];
    const float* gdiff = (const float*)d_in[5];
    const float* gres  = (const float*)d_in[6];
    const float* g2    = (const float*)d_in[7];
    const float* g3    = (const float*)d_in[8];
    const float* qkv2w = (const float*)d_in[9];
    const float* qkv2b = (const float*)d_in[10];
    const float* out2w = (const float*)d_in[11];
    const float* qkv3w = (const float*)d_in[12];
    const float* qkv3b = (const float*)d_in[13];
    const float* out3w = (const float*)d_in[14];
    const float* lsaqw = (const float*)d_in[15];
    const float* lsaow = (const float*)d_in[16];
    float* out = (float*)d_out;

    float *px, *phf, *pa3b, *pq3;
    __half *pha, *phs, *pya, *pqkv, *pa3, *pqm;
    __half *pwt, *pwt2, *pwq2, *pwo2, *pwq3, *pwq3q, *pwo3, *pwq4, *pwo4;
    cudaGetSymbolAddress((void**)&px,    g_x);
    cudaGetSymbolAddress((void**)&phf,   g_hf);
    cudaGetSymbolAddress((void**)&pha,   g_ha);
    cudaGetSymbolAddress((void**)&phs,   g_hs);
    cudaGetSymbolAddress((void**)&pya,   g_ya);
    cudaGetSymbolAddress((void**)&pqkv,  g_qkv);
    cudaGetSymbolAddress((void**)&pa3,   g_a3);
    cudaGetSymbolAddress((void**)&pa3b,  g_a3b);
    cudaGetSymbolAddress((void**)&pqm,   g_qm);
    cudaGetSymbolAddress((void**)&pq3,   g_q3);
    cudaGetSymbolAddress((void**)&pwt,   g_wt);
    cudaGetSymbolAddress((void**)&pwt2,  g_wt2);
    cudaGetSymbolAddress((void**)&pwq2,  g_wq2);
    cudaGetSymbolAddress((void**)&pwo2,  g_wo2);
    cudaGetSymbolAddress((void**)&pwq3,  g_wq3);
    cudaGetSymbolAddress((void**)&pwq3q, g_wq3q);
    cudaGetSymbolAddress((void**)&pwo3,  g_wo3);
    cudaGetSymbolAddress((void**)&pwq4,  g_wq4);
    cudaGetSymbolAddress((void**)&pwo4,  g_wo4);

    cudaFuncSetAttribute(k_pgemm<0>, cudaFuncAttributeMaxDynamicSharedMemorySize, SMEM_MM);
    cudaFuncSetAttribute(k_pgemm<1>, cudaFuncAttributeMaxDynamicSharedMemorySize, SMEM_MM);
    cudaFuncSetAttribute(k_pgemm<2>, cudaFuncAttributeMaxDynamicSharedMemorySize, SMEM_MM);
    cudaFuncSetAttribute(k_pgemm<3>, cudaFuncAttributeMaxDynamicSharedMemorySize, SMEM_MM);
    cudaFuncSetAttribute(k_pgemm<4>, cudaFuncAttributeMaxDynamicSharedMemorySize, SMEM_MM);
    cudaFuncSetAttribute(k_pconv<0>, cudaFuncAttributeMaxDynamicSharedMemorySize, SMEM_MM);
    cudaFuncSetAttribute(k_pconv<1>, cudaFuncAttributeMaxDynamicSharedMemorySize, SMEM_MM);

    dim3 tb32(32, 8);

    k_prep_all<<<7680, 256>>>(w1, w2, qkv2w, out2w, qkv3w, out3w, lsaqw, lsaow,
                              pwt, pwt2, pwq2, pwo2, pwq3, pwq3q, pwo3, pwq4, pwo4);
    k_nchw_to_nhwc<<<dim3(8, 8, 256), tb32>>>(x, px);

    // ---- Residual block ----
    k_gnstat1<<<1024, 256>>>(px, 0);
    k_gnstat2<<<128, 256>>>(0, 1e-6f);
    k_gnapply<<<4096, 256>>>(px, pha, 0);
    k_pconv<1><<<dim3(2, 512), 256, SMEM_MM>>>(pha, pwt, b1, temb, gdiff, phf);
    k_gnstat1<<<1024, 256>>>(phf, 1);
    k_gnstat2<<<128, 256>>>(1, 1e-6f);
    k_gnapply<<<4096, 256>>>(phf, pha, 1);
    k_pconv<0><<<dim3(2, 512), 256, SMEM_MM>>>(pha, pwt2, nullptr, nullptr, nullptr, phf);
    k_gnstat1<<<1024, 256>>>(phf, 2);
    k_gnstat2<<<128, 256>>>(2, 1e-6f);
    k_gnaxapply<<<4096, 256>>>(phf, px, phs, gres, 2);   // px updated, phs = half shadow

    // ---- layer2 ----
    k_pgemm<3><<<dim3(6, 512), 256, SMEM_MM>>>(phs, pwq2, qkv2b, nullptr, nullptr, pqkv,
                                               nullptr, nullptr, NTOK, 768, 256);
    k_attn_freq<<<dim3(1024, 8), 128>>>(pqkv, pya);
    k_pgemm<4><<<dim3(2, 512), 256, SMEM_MM>>>(pya, pwo2, nullptr, g2, nullptr, nullptr,
                                               px, phs, NTOK, 256, 256);

    // ---- layer3 (q via mean-then-project) ----
    k_pgemm<3><<<dim3(4, 512), 256, SMEM_MM>>>(phs, pwq3, qkv3b + 256, nullptr, nullptr, pqkv,
                                               nullptr, nullptr, NTOK, 512, 256);
    k_meanx<<<256, 256>>>(phs, pqm);
    k_pgemm<1><<<dim3(2, 2), 256, SMEM_MM>>>(pqm, pwq3q, qkv3b, nullptr, pq3, nullptr,
                                             nullptr, nullptr, 256, 256, 256);
    k_attn_time2<<<dim3(256, 8), 256>>>(pqkv, pq3, pa3);
    k_pgemm<0><<<dim3(2, 2), 256, SMEM_MM>>>(pa3, pwo3, nullptr, nullptr, pa3b, nullptr,
                                             nullptr, nullptr, 256, 256, 256);
    k_gn_bcast_add<<<256, 256>>>(pa3b, px, g3);

    // ---- layer4 ----
    k_gnstat1<<<1024, 256>>>(px, 3);
    k_gnstat2<<<128, 256>>>(3, 1e-5f);
    k_gnapply<<<4096, 256>>>(px, pha, 3);
    k_pgemm<2><<<dim3(6, 512), 256, SMEM_MM>>>(pha, pwq4, nullptr, nullptr, nullptr, pqkv,
                                               nullptr, nullptr, NTOK, 768, 256);
    k_attn_lsa<<<4096, 256>>>(pqkv, pya);
    k_pgemm<0><<<dim3(2, 512), 256, SMEM_MM>>>(pya, pwo4, nullptr, nullptr, phf, nullptr,
                                               nullptr, nullptr, NTOK, 256, 256);

    k_nhwc_to_nchw_add<<<dim3(8, 8, 256), tb32>>>(px, phf, out);
}